// round 1
// baseline (speedup 1.0000x reference)
#include <cuda_runtime.h>
#include <cuda_bf16.h>

// ---------------- problem constants ----------------
#define BB 64
#define NN 8192
#define PP 8
#define SS 1024
#define MM 8
#define KK 7
#define NPATCH (BB*PP)   // 512

// ---------------- device scratch (no allocations allowed) ----------------
__device__ float g_seed[NPATCH * 3];            // seed coords per (b,p)
__device__ float g_patch[NPATCH * 3 * SS];      // normalized patch coords, SoA [bp][c][s]
__device__ float g_mean[NPATCH * 3];
__device__ float g_norm[NPATCH];
__device__ float g_feat[NPATCH * 128];
__device__ float g_gen[NPATCH * 24];

// =========================================================================
// Kernel 1: farthest point sampling (matches jax loop semantics exactly:
// seed[i] = far_before_update; first seed is index 0; argmax first-index tie)
// =========================================================================
__global__ void fps_kernel(const float* __restrict__ xyz) {
    int b = blockIdx.x;
    const float* X = xyz + (size_t)b * 3 * NN;
    __shared__ float s_v[1024];
    __shared__ int   s_i[1024];
    __shared__ float s_c[3];
    int tid = threadIdx.x;

    float dist[8];
#pragma unroll
    for (int k = 0; k < 8; k++) dist[k] = 1e10f;
    int far = 0;

    for (int it = 0; it < PP; it++) {
        if (tid == 0) {
            float fx = X[far], fy = X[NN + far], fz = X[2 * NN + far];
            s_c[0] = fx; s_c[1] = fy; s_c[2] = fz;
            g_seed[(b * PP + it) * 3 + 0] = fx;
            g_seed[(b * PP + it) * 3 + 1] = fy;
            g_seed[(b * PP + it) * 3 + 2] = fz;
        }
        __syncthreads();
        float cx = s_c[0], cy = s_c[1], cz = s_c[2];
        float bv = -1.0f; int bi = 0;
#pragma unroll
        for (int k = 0; k < 8; k++) {
            int i = tid + k * 1024;
            float dx = X[i] - cx, dy = X[NN + i] - cy, dz = X[2 * NN + i] - cz;
            float d = dx * dx + dy * dy + dz * dz;
            float nd = fminf(dist[k], d);
            dist[k] = nd;
            if (nd > bv || (nd == bv && i < bi)) { bv = nd; bi = i; }
        }
        s_v[tid] = bv; s_i[tid] = bi;
        __syncthreads();
        for (int s = 512; s > 0; s >>= 1) {
            if (tid < s) {
                float ov = s_v[tid + s]; int oi = s_i[tid + s];
                if (ov > s_v[tid] || (ov == s_v[tid] && oi < s_i[tid])) {
                    s_v[tid] = ov; s_i[tid] = oi;
                }
            }
            __syncthreads();
        }
        far = s_i[0];
        __syncthreads();
    }
}

// =========================================================================
// Kernel 2: per-(b,p) KNN via exact radix select (1024 smallest of 8192),
// then patch mean / max-norm / normalization.  Set-based (order-free).
// =========================================================================
__global__ void knn_kernel(const float* __restrict__ xyz) {
    int bp = blockIdx.x;
    int b = bp >> 3;
    const float* X = xyz + (size_t)b * 3 * NN;
    __shared__ unsigned s_key[NN];          // 32 KB
    __shared__ int s_sel[SS];               // 4 KB
    __shared__ int s_hist[256];
    __shared__ unsigned s_pref;
    __shared__ int s_kk;
    __shared__ int s_cnt[2];
    __shared__ float s_red[256];
    int tid = threadIdx.x;

    float sx = g_seed[bp * 3 + 0], sy = g_seed[bp * 3 + 1], sz = g_seed[bp * 3 + 2];
    float s2 = sx * sx + sy * sy + sz * sz;

    for (int i = tid; i < NN; i += 256) {
        float px = X[i], py = X[NN + i], pz = X[2 * NN + i];
        float p2 = px * px + py * py + pz * pz;
        float dot = sx * px + sy * py + sz * pz;
        float d = (s2 - 2.0f * dot) + p2;          // same expansion as reference _sqdist
        unsigned u = __float_as_uint(d);
        u = (u & 0x80000000u) ? ~u : (u | 0x80000000u);   // total order
        s_key[i] = u;
    }
    __syncthreads();

    // radix select: value of the 1024-th smallest key
    unsigned prefix = 0, maskHi = 0;
    int kk = SS;
    for (int pass = 0; pass < 4; pass++) {
        int shift = 24 - 8 * pass;
        if (tid < 256) s_hist[tid] = 0;
        __syncthreads();
        for (int i = tid; i < NN; i += 256) {
            unsigned u = s_key[i];
            if ((u & maskHi) == prefix) atomicAdd(&s_hist[(u >> shift) & 255], 1);
        }
        __syncthreads();
        if (tid == 0) {
            int cum = 0, bsel = 0;
            for (bsel = 0; bsel < 256; bsel++) {
                int c = s_hist[bsel];
                if (cum + c >= kk) break;
                cum += c;
            }
            s_pref = prefix | ((unsigned)bsel << shift);
            s_kk = kk - cum;
        }
        __syncthreads();
        prefix = s_pref; kk = s_kk;
        maskHi |= (0xFFu << shift);
        __syncthreads();
    }
    unsigned T = prefix;

    if (tid == 0) { s_cnt[0] = 0; s_cnt[1] = 0; }
    __syncthreads();
    for (int i = tid; i < NN; i += 256) {
        if (s_key[i] < T) { int pos = atomicAdd(&s_cnt[0], 1); s_sel[pos] = i; }
    }
    __syncthreads();
    int nLess = s_cnt[0];
    for (int i = tid; i < NN; i += 256) {
        if (s_key[i] == T) {
            int pos = atomicAdd(&s_cnt[1], 1);
            if (nLess + pos < SS) s_sel[nLess + pos] = i;
        }
    }
    __syncthreads();

    // gather selected coords (reuse key memory), partial sums for mean
    float* cxs = (float*)s_key;
    float* cys = cxs + SS;
    float* czs = cxs + 2 * SS;
    float ax = 0.f, ay = 0.f, az = 0.f;
    for (int j = tid; j < SS; j += 256) {
        int i = s_sel[j];
        float px = X[i], py = X[NN + i], pz = X[2 * NN + i];
        cxs[j] = px; cys[j] = py; czs[j] = pz;
        ax += px; ay += py; az += pz;
    }
    // reduce sums (x)
    s_red[tid] = ax; __syncthreads();
    for (int s = 128; s > 0; s >>= 1) { if (tid < s) s_red[tid] += s_red[tid + s]; __syncthreads(); }
    float mx = s_red[0] * (1.0f / SS); __syncthreads();
    s_red[tid] = ay; __syncthreads();
    for (int s = 128; s > 0; s >>= 1) { if (tid < s) s_red[tid] += s_red[tid + s]; __syncthreads(); }
    float my = s_red[0] * (1.0f / SS); __syncthreads();
    s_red[tid] = az; __syncthreads();
    for (int s = 128; s > 0; s >>= 1) { if (tid < s) s_red[tid] += s_red[tid + s]; __syncthreads(); }
    float mz = s_red[0] * (1.0f / SS); __syncthreads();

    // max L2 norm of centered
    float mnorm = 0.f;
    for (int j = tid; j < SS; j += 256) {
        float dx = cxs[j] - mx, dy = cys[j] - my, dz = czs[j] - mz;
        float l = sqrtf(dx * dx + dy * dy + dz * dz);
        mnorm = fmaxf(mnorm, l);
    }
    s_red[tid] = mnorm; __syncthreads();
    for (int s = 128; s > 0; s >>= 1) { if (tid < s) s_red[tid] = fmaxf(s_red[tid], s_red[tid + s]); __syncthreads(); }
    float nrm = s_red[0]; __syncthreads();

    // write normalized patch (SoA) + stats
    for (int j = tid; j < SS; j += 256) {
        g_patch[(bp * 3 + 0) * SS + j] = (cxs[j] - mx) / nrm;
        g_patch[(bp * 3 + 1) * SS + j] = (cys[j] - my) / nrm;
        g_patch[(bp * 3 + 2) * SS + j] = (czs[j] - mz) / nrm;
    }
    if (tid == 0) {
        g_mean[bp * 3 + 0] = mx; g_mean[bp * 3 + 1] = my; g_mean[bp * 3 + 2] = mz;
        g_norm[bp] = nrm;
    }
}

// =========================================================================
// Kernel 3: fused per-point MLP (3->64->64->64->128->128, relu) + maxpool.
// All weights in dynamic shared (133 KB), activations in registers.
// One block per patch (1024 points, 256 threads x 4 point-iters).
// =========================================================================
#define SW_W0 0
#define SW_B0 192
#define SW_W1 256
#define SW_B1 4352
#define SW_W2 4416
#define SW_B2 8512
#define SW_W3T 8576      // transposed [out=128][in=64]
#define SW_B3 16768
#define SW_W4 16896
#define SW_B4 33280
#define SW_TOTAL 33408

__global__ void __launch_bounds__(256, 1) mlp_kernel(
    const float* __restrict__ mw0, const float* __restrict__ mb0,
    const float* __restrict__ mw1, const float* __restrict__ mb1,
    const float* __restrict__ mw2, const float* __restrict__ mb2,
    const float* __restrict__ mw3, const float* __restrict__ mb3,
    const float* __restrict__ mw4, const float* __restrict__ mb4) {
    extern __shared__ float sw[];
    __shared__ int smax[128];
    int bp = blockIdx.x;
    int tid = threadIdx.x;

    for (int i = tid; i < 192; i += 256) sw[SW_W0 + i] = mw0[i];
    for (int i = tid; i < 64; i += 256) sw[SW_B0 + i] = mb0[i];
    for (int i = tid; i < 4096; i += 256) sw[SW_W1 + i] = mw1[i];
    for (int i = tid; i < 64; i += 256) sw[SW_B1 + i] = mb1[i];
    for (int i = tid; i < 4096; i += 256) sw[SW_W2 + i] = mw2[i];
    for (int i = tid; i < 64; i += 256) sw[SW_B2 + i] = mb2[i];
    for (int i = tid; i < 8192; i += 256) {
        int r = i >> 7, c = i & 127;            // mw3 is [64][128]
        sw[SW_W3T + c * 64 + r] = mw3[i];
    }
    for (int i = tid; i < 128; i += 256) sw[SW_B3 + i] = mb3[i];
    for (int i = tid; i < 16384; i += 256) sw[SW_W4 + i] = mw4[i];
    for (int i = tid; i < 128; i += 256) sw[SW_B4 + i] = mb4[i];
    if (tid < 128) smax[tid] = 0;
    __syncthreads();

    const float* s_w0 = sw + SW_W0; const float* s_b0 = sw + SW_B0;
    const float* s_w1 = sw + SW_W1; const float* s_b1 = sw + SW_B1;
    const float* s_w2 = sw + SW_W2; const float* s_b2 = sw + SW_B2;
    const float* s_w3t = sw + SW_W3T; const float* s_b3 = sw + SW_B3;
    const float* s_w4 = sw + SW_W4; const float* s_b4 = sw + SW_B4;

    for (int pt = 0; pt < 4; pt++) {
        int i = pt * 256 + tid;
        float x = g_patch[(bp * 3 + 0) * SS + i];
        float y = g_patch[(bp * 3 + 1) * SS + i];
        float z = g_patch[(bp * 3 + 2) * SS + i];

        float h1[64];
#pragma unroll
        for (int j = 0; j < 64; j++) {
            float a = s_b0[j];
            a = fmaf(x, s_w0[j], a);
            a = fmaf(y, s_w0[64 + j], a);
            a = fmaf(z, s_w0[128 + j], a);
            h1[j] = fmaxf(a, 0.f);
        }
        float h2[64];
#pragma unroll
        for (int j = 0; j < 64; j += 4) {
            float a0 = s_b1[j], a1 = s_b1[j + 1], a2 = s_b1[j + 2], a3 = s_b1[j + 3];
#pragma unroll
            for (int k = 0; k < 64; k++) {
                float4 w = *reinterpret_cast<const float4*>(&s_w1[k * 64 + j]);
                float h = h1[k];
                a0 = fmaf(h, w.x, a0); a1 = fmaf(h, w.y, a1);
                a2 = fmaf(h, w.z, a2); a3 = fmaf(h, w.w, a3);
            }
            h2[j] = fmaxf(a0, 0.f); h2[j + 1] = fmaxf(a1, 0.f);
            h2[j + 2] = fmaxf(a2, 0.f); h2[j + 3] = fmaxf(a3, 0.f);
        }
        float h3[64];
#pragma unroll
        for (int j = 0; j < 64; j += 4) {
            float a0 = s_b2[j], a1 = s_b2[j + 1], a2 = s_b2[j + 2], a3 = s_b2[j + 3];
#pragma unroll
            for (int k = 0; k < 64; k++) {
                float4 w = *reinterpret_cast<const float4*>(&s_w2[k * 64 + j]);
                float h = h2[k];
                a0 = fmaf(h, w.x, a0); a1 = fmaf(h, w.y, a1);
                a2 = fmaf(h, w.z, a2); a3 = fmaf(h, w.w, a3);
            }
            h3[j] = fmaxf(a0, 0.f); h3[j + 1] = fmaxf(a1, 0.f);
            h3[j + 2] = fmaxf(a2, 0.f); h3[j + 3] = fmaxf(a3, 0.f);
        }
        // fused L4 (64->128) + L5 (128->128): h4 computed 2-at-a-time on the fly
        float acc[128];
#pragma unroll
        for (int j = 0; j < 128; j++) acc[j] = s_b4[j];
        for (int i4 = 0; i4 < 128; i4 += 2) {
            float ha = s_b3[i4], hb = s_b3[i4 + 1];
#pragma unroll
            for (int k = 0; k < 64; k += 4) {
                float4 wa = *reinterpret_cast<const float4*>(&s_w3t[i4 * 64 + k]);
                float4 wb = *reinterpret_cast<const float4*>(&s_w3t[(i4 + 1) * 64 + k]);
                ha = fmaf(h3[k], wa.x, ha); ha = fmaf(h3[k + 1], wa.y, ha);
                ha = fmaf(h3[k + 2], wa.z, ha); ha = fmaf(h3[k + 3], wa.w, ha);
                hb = fmaf(h3[k], wb.x, hb); hb = fmaf(h3[k + 1], wb.y, hb);
                hb = fmaf(h3[k + 2], wb.z, hb); hb = fmaf(h3[k + 3], wb.w, hb);
            }
            ha = fmaxf(ha, 0.f); hb = fmaxf(hb, 0.f);
#pragma unroll
            for (int j = 0; j < 128; j += 4) {
                float4 wa = *reinterpret_cast<const float4*>(&s_w4[i4 * 128 + j]);
                float4 wb = *reinterpret_cast<const float4*>(&s_w4[(i4 + 1) * 128 + j]);
                acc[j]     = fmaf(ha, wa.x, fmaf(hb, wb.x, acc[j]));
                acc[j + 1] = fmaf(ha, wa.y, fmaf(hb, wb.y, acc[j + 1]));
                acc[j + 2] = fmaf(ha, wa.z, fmaf(hb, wb.z, acc[j + 2]));
                acc[j + 3] = fmaf(ha, wa.w, fmaf(hb, wb.w, acc[j + 3]));
            }
        }
        // relu + maxpool over points (warp shuffle, then shared atomicMax on bits)
#pragma unroll
        for (int j = 0; j < 128; j++) {
            float v = fmaxf(acc[j], 0.f);
#pragma unroll
            for (int o = 16; o > 0; o >>= 1)
                v = fmaxf(v, __shfl_xor_sync(0xffffffffu, v, o));
            if ((tid & 31) == 0) atomicMax(&smax[j], __float_as_int(v));
        }
    }
    __syncthreads();
    if (tid < 128) g_feat[bp * 128 + tid] = __int_as_float(smax[tid]);
}

// =========================================================================
// Kernel 4: per-patch FC decoder 128->256->256->256->24 (last layer no relu)
// =========================================================================
__global__ void dec_kernel(
    const float* __restrict__ fw0, const float* __restrict__ fb0,
    const float* __restrict__ fw1, const float* __restrict__ fb1,
    const float* __restrict__ fw2, const float* __restrict__ fb2,
    const float* __restrict__ fw3, const float* __restrict__ fb3) {
    int bp = blockIdx.x;
    int tid = threadIdx.x;
    __shared__ float a0[256], a1[256];
    if (tid < 128) a0[tid] = g_feat[bp * 128 + tid];
    __syncthreads();
    {
        float acc = fb0[tid];
#pragma unroll 8
        for (int i = 0; i < 128; i++) acc = fmaf(a0[i], fw0[i * 256 + tid], acc);
        a1[tid] = fmaxf(acc, 0.f);
    }
    __syncthreads();
    {
        float acc = fb1[tid];
#pragma unroll 8
        for (int i = 0; i < 256; i++) acc = fmaf(a1[i], fw1[i * 256 + tid], acc);
        a0[tid] = fmaxf(acc, 0.f);
    }
    __syncthreads();
    {
        float acc = fb2[tid];
#pragma unroll 8
        for (int i = 0; i < 256; i++) acc = fmaf(a0[i], fw2[i * 256 + tid], acc);
        a1[tid] = fmaxf(acc, 0.f);
    }
    __syncthreads();
    if (tid < 24) {
        float acc = fb3[tid];
#pragma unroll 8
        for (int i = 0; i < 256; i++) acc = fmaf(a1[i], fw3[i * 24 + tid], acc);
        g_gen[bp * 24 + tid] = acc;
    }
}

// =========================================================================
// Kernel 5: SoftProjection (top-7 of 1024 per query, softmax, weighted sum)
// + denormalize.  One warp per (patch, m).
// =========================================================================
__global__ void proj_kernel(const float* __restrict__ temperature,
                            float* __restrict__ out) {
    int bp = blockIdx.x;
    int tid = threadIdx.x;
    int m = tid >> 5;
    int lane = tid & 31;
    float t = temperature[0];
    float sigma = fmaxf(t * t, 1e-4f);

    const float* PX = &g_patch[(bp * 3 + 0) * SS];
    const float* PY = &g_patch[(bp * 3 + 1) * SS];
    const float* PZ = &g_patch[(bp * 3 + 2) * SS];

    float qx = g_gen[bp * 24 + m * 3 + 0];
    float qy = g_gen[bp * 24 + m * 3 + 1];
    float qz = g_gen[bp * 24 + m * 3 + 2];
    float q2 = qx * qx + qy * qy + qz * qz;

    float bd[7]; int bi[7];
#pragma unroll
    for (int k = 0; k < 7; k++) { bd[k] = 3.4e38f; bi[k] = 0; }

    for (int i = lane; i < SS; i += 32) {
        float px = PX[i], py = PY[i], pz = PZ[i];
        float p2 = px * px + py * py + pz * pz;
        float dot = qx * px + qy * py + qz * pz;
        float d = (q2 - 2.0f * dot) + p2;
        if (d < bd[6]) {
            bd[6] = d; bi[6] = i;
#pragma unroll
            for (int k = 6; k > 0; k--) {
                if (bd[k] < bd[k - 1]) {
                    float td = bd[k]; bd[k] = bd[k - 1]; bd[k - 1] = td;
                    int ti = bi[k]; bi[k] = bi[k - 1]; bi[k - 1] = ti;
                }
            }
        }
    }
    // merge 7 smallest across the warp
    float selD[7]; int selI[7];
#pragma unroll
    for (int k = 0; k < 7; k++) {
        float mv = bd[0]; int ml = lane;
#pragma unroll
        for (int o = 16; o > 0; o >>= 1) {
            float ov = __shfl_xor_sync(0xffffffffu, mv, o);
            int ol = __shfl_xor_sync(0xffffffffu, ml, o);
            if (ov < mv || (ov == mv && ol < ml)) { mv = ov; ml = ol; }
        }
        selD[k] = mv;
        selI[k] = __shfl_sync(0xffffffffu, bi[0], ml);
        if (lane == ml) {
#pragma unroll
            for (int q = 0; q < 6; q++) { bd[q] = bd[q + 1]; bi[q] = bi[q + 1]; }
            bd[6] = 3.4e38f;
        }
    }
    if (lane == 0) {
        // softmax over neg_d/sigma: exp((selD[0]-selD[k])/sigma)
        float wsum = 0.f, sx = 0.f, sy = 0.f, sz = 0.f;
#pragma unroll
        for (int k = 0; k < 7; k++) {
            float w = expf((selD[0] - selD[k]) / sigma);
            int i = selI[k];
            wsum += w;
            sx = fmaf(w, PX[i], sx);
            sy = fmaf(w, PY[i], sy);
            sz = fmaf(w, PZ[i], sz);
        }
        float inv = 1.0f / wsum;
        float nrm = g_norm[bp];
        float mex = g_mean[bp * 3 + 0], mey = g_mean[bp * 3 + 1], mez = g_mean[bp * 3 + 2];
        int o = (bp * MM + m) * 3;
        out[o + 0] = fmaf(sx * inv, nrm, mex);
        out[o + 1] = fmaf(sy * inv, nrm, mey);
        out[o + 2] = fmaf(sz * inv, nrm, mez);
    }
}

// =========================================================================
extern "C" void kernel_launch(void* const* d_in, const int* in_sizes, int n_in,
                              void* d_out, int out_size) {
    const float* xyz = (const float*)d_in[0];
    const float* mw0 = (const float*)d_in[1];  const float* mb0 = (const float*)d_in[2];
    const float* mw1 = (const float*)d_in[3];  const float* mb1 = (const float*)d_in[4];
    const float* mw2 = (const float*)d_in[5];  const float* mb2 = (const float*)d_in[6];
    const float* mw3 = (const float*)d_in[7];  const float* mb3 = (const float*)d_in[8];
    const float* mw4 = (const float*)d_in[9];  const float* mb4 = (const float*)d_in[10];
    const float* fw0 = (const float*)d_in[11]; const float* fb0 = (const float*)d_in[12];
    const float* fw1 = (const float*)d_in[13]; const float* fb1 = (const float*)d_in[14];
    const float* fw2 = (const float*)d_in[15]; const float* fb2 = (const float*)d_in[16];
    const float* fw3 = (const float*)d_in[17]; const float* fb3 = (const float*)d_in[18];
    const float* temp = (const float*)d_in[19];
    float* out = (float*)d_out;

    cudaFuncSetAttribute(mlp_kernel, cudaFuncAttributeMaxDynamicSharedMemorySize,
                         SW_TOTAL * sizeof(float));

    fps_kernel<<<BB, 1024>>>(xyz);
    knn_kernel<<<NPATCH, 256>>>(xyz);
    mlp_kernel<<<NPATCH, 256, SW_TOTAL * sizeof(float)>>>(
        mw0, mb0, mw1, mb1, mw2, mb2, mw3, mb3, mw4, mb4);
    dec_kernel<<<NPATCH, 256>>>(fw0, fb0, fw1, fb1, fw2, fb2, fw3, fb3);
    proj_kernel<<<NPATCH, 256>>>(temp, out);
}

// round 2
// speedup vs baseline: 1.0000x; 1.0000x over previous
#include <cuda_runtime.h>
#include <cuda_bf16.h>

// ---------------- problem constants ----------------
#define BB 64
#define NN 8192
#define PP 8
#define SS 1024
#define MM 8
#define KK 7
#define NPATCH (BB*PP)   // 512

// ---------------- device scratch (no allocations allowed) ----------------
__device__ float g_seed[NPATCH * 3];            // seed coords per (b,p)
__device__ float g_patch[NPATCH * 3 * SS];      // normalized patch coords, SoA [bp][c][s]
__device__ float g_mean[NPATCH * 3];
__device__ float g_norm[NPATCH];
__device__ float g_feat[NPATCH * 128];
__device__ float g_gen[NPATCH * 24];

// =========================================================================
// Kernel 1: farthest point sampling (matches jax loop semantics exactly:
// seed[i] = far_before_update; first seed is index 0; argmax first-index tie)
// =========================================================================
__global__ void fps_kernel(const float* __restrict__ xyz) {
    int b = blockIdx.x;
    const float* X = xyz + (size_t)b * 3 * NN;
    __shared__ float s_v[1024];
    __shared__ int   s_i[1024];
    __shared__ float s_c[3];
    int tid = threadIdx.x;

    float dist[8];
#pragma unroll
    for (int k = 0; k < 8; k++) dist[k] = 1e10f;
    int far = 0;

    for (int it = 0; it < PP; it++) {
        if (tid == 0) {
            float fx = X[far], fy = X[NN + far], fz = X[2 * NN + far];
            s_c[0] = fx; s_c[1] = fy; s_c[2] = fz;
            g_seed[(b * PP + it) * 3 + 0] = fx;
            g_seed[(b * PP + it) * 3 + 1] = fy;
            g_seed[(b * PP + it) * 3 + 2] = fz;
        }
        __syncthreads();
        float cx = s_c[0], cy = s_c[1], cz = s_c[2];
        float bv = -1.0f; int bi = 0;
#pragma unroll
        for (int k = 0; k < 8; k++) {
            int i = tid + k * 1024;
            float dx = X[i] - cx, dy = X[NN + i] - cy, dz = X[2 * NN + i] - cz;
            float d = dx * dx + dy * dy + dz * dz;
            float nd = fminf(dist[k], d);
            dist[k] = nd;
            if (nd > bv || (nd == bv && i < bi)) { bv = nd; bi = i; }
        }
        s_v[tid] = bv; s_i[tid] = bi;
        __syncthreads();
        for (int s = 512; s > 0; s >>= 1) {
            if (tid < s) {
                float ov = s_v[tid + s]; int oi = s_i[tid + s];
                if (ov > s_v[tid] || (ov == s_v[tid] && oi < s_i[tid])) {
                    s_v[tid] = ov; s_i[tid] = oi;
                }
            }
            __syncthreads();
        }
        far = s_i[0];
        __syncthreads();
    }
}

// =========================================================================
// Kernel 2: per-(b,p) KNN via exact radix select (1024 smallest of 8192),
// then patch mean / max-norm / normalization.  Set-based (order-free).
// =========================================================================
__global__ void knn_kernel(const float* __restrict__ xyz) {
    int bp = blockIdx.x;
    int b = bp >> 3;
    const float* X = xyz + (size_t)b * 3 * NN;
    __shared__ unsigned s_key[NN];          // 32 KB
    __shared__ int s_sel[SS];               // 4 KB
    __shared__ int s_hist[256];
    __shared__ unsigned s_pref;
    __shared__ int s_kk;
    __shared__ int s_cnt[2];
    __shared__ float s_red[256];
    int tid = threadIdx.x;

    float sx = g_seed[bp * 3 + 0], sy = g_seed[bp * 3 + 1], sz = g_seed[bp * 3 + 2];
    float s2 = sx * sx + sy * sy + sz * sz;

    for (int i = tid; i < NN; i += 256) {
        float px = X[i], py = X[NN + i], pz = X[2 * NN + i];
        float p2 = px * px + py * py + pz * pz;
        float dot = sx * px + sy * py + sz * pz;
        float d = (s2 - 2.0f * dot) + p2;          // same expansion as reference _sqdist
        unsigned u = __float_as_uint(d);
        u = (u & 0x80000000u) ? ~u : (u | 0x80000000u);   // total order
        s_key[i] = u;
    }
    __syncthreads();

    // radix select: value of the 1024-th smallest key
    unsigned prefix = 0, maskHi = 0;
    int kk = SS;
    for (int pass = 0; pass < 4; pass++) {
        int shift = 24 - 8 * pass;
        if (tid < 256) s_hist[tid] = 0;
        __syncthreads();
        for (int i = tid; i < NN; i += 256) {
            unsigned u = s_key[i];
            if ((u & maskHi) == prefix) atomicAdd(&s_hist[(u >> shift) & 255], 1);
        }
        __syncthreads();
        if (tid == 0) {
            int cum = 0, bsel = 0;
            for (bsel = 0; bsel < 256; bsel++) {
                int c = s_hist[bsel];
                if (cum + c >= kk) break;
                cum += c;
            }
            s_pref = prefix | ((unsigned)bsel << shift);
            s_kk = kk - cum;
        }
        __syncthreads();
        prefix = s_pref; kk = s_kk;
        maskHi |= (0xFFu << shift);
        __syncthreads();
    }
    unsigned T = prefix;

    if (tid == 0) { s_cnt[0] = 0; s_cnt[1] = 0; }
    __syncthreads();
    for (int i = tid; i < NN; i += 256) {
        if (s_key[i] < T) { int pos = atomicAdd(&s_cnt[0], 1); s_sel[pos] = i; }
    }
    __syncthreads();
    int nLess = s_cnt[0];
    for (int i = tid; i < NN; i += 256) {
        if (s_key[i] == T) {
            int pos = atomicAdd(&s_cnt[1], 1);
            if (nLess + pos < SS) s_sel[nLess + pos] = i;
        }
    }
    __syncthreads();

    // gather selected coords (reuse key memory), partial sums for mean
    float* cxs = (float*)s_key;
    float* cys = cxs + SS;
    float* czs = cxs + 2 * SS;
    float ax = 0.f, ay = 0.f, az = 0.f;
    for (int j = tid; j < SS; j += 256) {
        int i = s_sel[j];
        float px = X[i], py = X[NN + i], pz = X[2 * NN + i];
        cxs[j] = px; cys[j] = py; czs[j] = pz;
        ax += px; ay += py; az += pz;
    }
    // reduce sums (x)
    s_red[tid] = ax; __syncthreads();
    for (int s = 128; s > 0; s >>= 1) { if (tid < s) s_red[tid] += s_red[tid + s]; __syncthreads(); }
    float mx = s_red[0] * (1.0f / SS); __syncthreads();
    s_red[tid] = ay; __syncthreads();
    for (int s = 128; s > 0; s >>= 1) { if (tid < s) s_red[tid] += s_red[tid + s]; __syncthreads(); }
    float my = s_red[0] * (1.0f / SS); __syncthreads();
    s_red[tid] = az; __syncthreads();
    for (int s = 128; s > 0; s >>= 1) { if (tid < s) s_red[tid] += s_red[tid + s]; __syncthreads(); }
    float mz = s_red[0] * (1.0f / SS); __syncthreads();

    // max L2 norm of centered
    float mnorm = 0.f;
    for (int j = tid; j < SS; j += 256) {
        float dx = cxs[j] - mx, dy = cys[j] - my, dz = czs[j] - mz;
        float l = sqrtf(dx * dx + dy * dy + dz * dz);
        mnorm = fmaxf(mnorm, l);
    }
    s_red[tid] = mnorm; __syncthreads();
    for (int s = 128; s > 0; s >>= 1) { if (tid < s) s_red[tid] = fmaxf(s_red[tid], s_red[tid + s]); __syncthreads(); }
    float nrm = s_red[0]; __syncthreads();

    // write normalized patch (SoA) + stats
    for (int j = tid; j < SS; j += 256) {
        g_patch[(bp * 3 + 0) * SS + j] = (cxs[j] - mx) / nrm;
        g_patch[(bp * 3 + 1) * SS + j] = (cys[j] - my) / nrm;
        g_patch[(bp * 3 + 2) * SS + j] = (czs[j] - mz) / nrm;
    }
    if (tid == 0) {
        g_mean[bp * 3 + 0] = mx; g_mean[bp * 3 + 1] = my; g_mean[bp * 3 + 2] = mz;
        g_norm[bp] = nrm;
    }
}

// =========================================================================
// Kernel 3: fused per-point MLP (3->64->64->64->128->128, relu) + maxpool.
// All weights in dynamic shared (133 KB), activations in registers.
// One block per patch (1024 points, 256 threads x 4 point-iters).
// =========================================================================
#define SW_W0 0
#define SW_B0 192
#define SW_W1 256
#define SW_B1 4352
#define SW_W2 4416
#define SW_B2 8512
#define SW_W3T 8576      // transposed [out=128][in=64]
#define SW_B3 16768
#define SW_W4 16896
#define SW_B4 33280
#define SW_TOTAL 33408

__global__ void __launch_bounds__(256, 1) mlp_kernel(
    const float* __restrict__ mw0, const float* __restrict__ mb0,
    const float* __restrict__ mw1, const float* __restrict__ mb1,
    const float* __restrict__ mw2, const float* __restrict__ mb2,
    const float* __restrict__ mw3, const float* __restrict__ mb3,
    const float* __restrict__ mw4, const float* __restrict__ mb4) {
    extern __shared__ float sw[];
    __shared__ int smax[128];
    int bp = blockIdx.x;
    int tid = threadIdx.x;

    for (int i = tid; i < 192; i += 256) sw[SW_W0 + i] = mw0[i];
    for (int i = tid; i < 64; i += 256) sw[SW_B0 + i] = mb0[i];
    for (int i = tid; i < 4096; i += 256) sw[SW_W1 + i] = mw1[i];
    for (int i = tid; i < 64; i += 256) sw[SW_B1 + i] = mb1[i];
    for (int i = tid; i < 4096; i += 256) sw[SW_W2 + i] = mw2[i];
    for (int i = tid; i < 64; i += 256) sw[SW_B2 + i] = mb2[i];
    for (int i = tid; i < 8192; i += 256) {
        int r = i >> 7, c = i & 127;            // mw3 is [64][128]
        sw[SW_W3T + c * 64 + r] = mw3[i];
    }
    for (int i = tid; i < 128; i += 256) sw[SW_B3 + i] = mb3[i];
    for (int i = tid; i < 16384; i += 256) sw[SW_W4 + i] = mw4[i];
    for (int i = tid; i < 128; i += 256) sw[SW_B4 + i] = mb4[i];
    if (tid < 128) smax[tid] = 0;
    __syncthreads();

    const float* s_w0 = sw + SW_W0; const float* s_b0 = sw + SW_B0;
    const float* s_w1 = sw + SW_W1; const float* s_b1 = sw + SW_B1;
    const float* s_w2 = sw + SW_W2; const float* s_b2 = sw + SW_B2;
    const float* s_w3t = sw + SW_W3T; const float* s_b3 = sw + SW_B3;
    const float* s_w4 = sw + SW_W4; const float* s_b4 = sw + SW_B4;

    for (int pt = 0; pt < 4; pt++) {
        int i = pt * 256 + tid;
        float x = g_patch[(bp * 3 + 0) * SS + i];
        float y = g_patch[(bp * 3 + 1) * SS + i];
        float z = g_patch[(bp * 3 + 2) * SS + i];

        float h1[64];
#pragma unroll
        for (int j = 0; j < 64; j++) {
            float a = s_b0[j];
            a = fmaf(x, s_w0[j], a);
            a = fmaf(y, s_w0[64 + j], a);
            a = fmaf(z, s_w0[128 + j], a);
            h1[j] = fmaxf(a, 0.f);
        }
        float h2[64];
#pragma unroll
        for (int j = 0; j < 64; j += 4) {
            float a0 = s_b1[j], a1 = s_b1[j + 1], a2 = s_b1[j + 2], a3 = s_b1[j + 3];
#pragma unroll
            for (int k = 0; k < 64; k++) {
                float4 w = *reinterpret_cast<const float4*>(&s_w1[k * 64 + j]);
                float h = h1[k];
                a0 = fmaf(h, w.x, a0); a1 = fmaf(h, w.y, a1);
                a2 = fmaf(h, w.z, a2); a3 = fmaf(h, w.w, a3);
            }
            h2[j] = fmaxf(a0, 0.f); h2[j + 1] = fmaxf(a1, 0.f);
            h2[j + 2] = fmaxf(a2, 0.f); h2[j + 3] = fmaxf(a3, 0.f);
        }
        float h3[64];
#pragma unroll
        for (int j = 0; j < 64; j += 4) {
            float a0 = s_b2[j], a1 = s_b2[j + 1], a2 = s_b2[j + 2], a3 = s_b2[j + 3];
#pragma unroll
            for (int k = 0; k < 64; k++) {
                float4 w = *reinterpret_cast<const float4*>(&s_w2[k * 64 + j]);
                float h = h2[k];
                a0 = fmaf(h, w.x, a0); a1 = fmaf(h, w.y, a1);
                a2 = fmaf(h, w.z, a2); a3 = fmaf(h, w.w, a3);
            }
            h3[j] = fmaxf(a0, 0.f); h3[j + 1] = fmaxf(a1, 0.f);
            h3[j + 2] = fmaxf(a2, 0.f); h3[j + 3] = fmaxf(a3, 0.f);
        }
        // fused L4 (64->128) + L5 (128->128): h4 computed 2-at-a-time on the fly
        float acc[128];
#pragma unroll
        for (int j = 0; j < 128; j++) acc[j] = s_b4[j];
        for (int i4 = 0; i4 < 128; i4 += 2) {
            float ha = s_b3[i4], hb = s_b3[i4 + 1];
#pragma unroll
            for (int k = 0; k < 64; k += 4) {
                float4 wa = *reinterpret_cast<const float4*>(&s_w3t[i4 * 64 + k]);
                float4 wb = *reinterpret_cast<const float4*>(&s_w3t[(i4 + 1) * 64 + k]);
                ha = fmaf(h3[k], wa.x, ha); ha = fmaf(h3[k + 1], wa.y, ha);
                ha = fmaf(h3[k + 2], wa.z, ha); ha = fmaf(h3[k + 3], wa.w, ha);
                hb = fmaf(h3[k], wb.x, hb); hb = fmaf(h3[k + 1], wb.y, hb);
                hb = fmaf(h3[k + 2], wb.z, hb); hb = fmaf(h3[k + 3], wb.w, hb);
            }
            ha = fmaxf(ha, 0.f); hb = fmaxf(hb, 0.f);
#pragma unroll
            for (int j = 0; j < 128; j += 4) {
                float4 wa = *reinterpret_cast<const float4*>(&s_w4[i4 * 128 + j]);
                float4 wb = *reinterpret_cast<const float4*>(&s_w4[(i4 + 1) * 128 + j]);
                acc[j]     = fmaf(ha, wa.x, fmaf(hb, wb.x, acc[j]));
                acc[j + 1] = fmaf(ha, wa.y, fmaf(hb, wb.y, acc[j + 1]));
                acc[j + 2] = fmaf(ha, wa.z, fmaf(hb, wb.z, acc[j + 2]));
                acc[j + 3] = fmaf(ha, wa.w, fmaf(hb, wb.w, acc[j + 3]));
            }
        }
        // relu + maxpool over points (warp shuffle, then shared atomicMax on bits)
#pragma unroll
        for (int j = 0; j < 128; j++) {
            float v = fmaxf(acc[j], 0.f);
#pragma unroll
            for (int o = 16; o > 0; o >>= 1)
                v = fmaxf(v, __shfl_xor_sync(0xffffffffu, v, o));
            if ((tid & 31) == 0) atomicMax(&smax[j], __float_as_int(v));
        }
    }
    __syncthreads();
    if (tid < 128) g_feat[bp * 128 + tid] = __int_as_float(smax[tid]);
}

// =========================================================================
// Kernel 4: per-patch FC decoder 128->256->256->256->24 (last layer no relu)
// =========================================================================
__global__ void dec_kernel(
    const float* __restrict__ fw0, const float* __restrict__ fb0,
    const float* __restrict__ fw1, const float* __restrict__ fb1,
    const float* __restrict__ fw2, const float* __restrict__ fb2,
    const float* __restrict__ fw3, const float* __restrict__ fb3) {
    int bp = blockIdx.x;
    int tid = threadIdx.x;
    __shared__ float a0[256], a1[256];
    if (tid < 128) a0[tid] = g_feat[bp * 128 + tid];
    __syncthreads();
    {
        float acc = fb0[tid];
#pragma unroll 8
        for (int i = 0; i < 128; i++) acc = fmaf(a0[i], fw0[i * 256 + tid], acc);
        a1[tid] = fmaxf(acc, 0.f);
    }
    __syncthreads();
    {
        float acc = fb1[tid];
#pragma unroll 8
        for (int i = 0; i < 256; i++) acc = fmaf(a1[i], fw1[i * 256 + tid], acc);
        a0[tid] = fmaxf(acc, 0.f);
    }
    __syncthreads();
    {
        float acc = fb2[tid];
#pragma unroll 8
        for (int i = 0; i < 256; i++) acc = fmaf(a0[i], fw2[i * 256 + tid], acc);
        a1[tid] = fmaxf(acc, 0.f);
    }
    __syncthreads();
    if (tid < 24) {
        float acc = fb3[tid];
#pragma unroll 8
        for (int i = 0; i < 256; i++) acc = fmaf(a1[i], fw3[i * 24 + tid], acc);
        g_gen[bp * 24 + tid] = acc;
    }
}

// =========================================================================
// Kernel 5: SoftProjection (top-7 of 1024 per query, softmax, weighted sum)
// + denormalize.  One warp per (patch, m).
// =========================================================================
__global__ void proj_kernel(const float* __restrict__ temperature,
                            float* __restrict__ out) {
    int bp = blockIdx.x;
    int tid = threadIdx.x;
    int m = tid >> 5;
    int lane = tid & 31;
    float t = temperature[0];
    float sigma = fmaxf(t * t, 1e-4f);

    const float* PX = &g_patch[(bp * 3 + 0) * SS];
    const float* PY = &g_patch[(bp * 3 + 1) * SS];
    const float* PZ = &g_patch[(bp * 3 + 2) * SS];

    float qx = g_gen[bp * 24 + m * 3 + 0];
    float qy = g_gen[bp * 24 + m * 3 + 1];
    float qz = g_gen[bp * 24 + m * 3 + 2];
    float q2 = qx * qx + qy * qy + qz * qz;

    float bd[7]; int bi[7];
#pragma unroll
    for (int k = 0; k < 7; k++) { bd[k] = 3.4e38f; bi[k] = 0; }

    for (int i = lane; i < SS; i += 32) {
        float px = PX[i], py = PY[i], pz = PZ[i];
        float p2 = px * px + py * py + pz * pz;
        float dot = qx * px + qy * py + qz * pz;
        float d = (q2 - 2.0f * dot) + p2;
        if (d < bd[6]) {
            bd[6] = d; bi[6] = i;
#pragma unroll
            for (int k = 6; k > 0; k--) {
                if (bd[k] < bd[k - 1]) {
                    float td = bd[k]; bd[k] = bd[k - 1]; bd[k - 1] = td;
                    int ti = bi[k]; bi[k] = bi[k - 1]; bi[k - 1] = ti;
                }
            }
        }
    }
    // merge 7 smallest across the warp
    float selD[7]; int selI[7];
#pragma unroll
    for (int k = 0; k < 7; k++) {
        float mv = bd[0]; int ml = lane;
#pragma unroll
        for (int o = 16; o > 0; o >>= 1) {
            float ov = __shfl_xor_sync(0xffffffffu, mv, o);
            int ol = __shfl_xor_sync(0xffffffffu, ml, o);
            if (ov < mv || (ov == mv && ol < ml)) { mv = ov; ml = ol; }
        }
        selD[k] = mv;
        selI[k] = __shfl_sync(0xffffffffu, bi[0], ml);
        if (lane == ml) {
#pragma unroll
            for (int q = 0; q < 6; q++) { bd[q] = bd[q + 1]; bi[q] = bi[q + 1]; }
            bd[6] = 3.4e38f;
        }
    }
    if (lane == 0) {
        // softmax over neg_d/sigma: exp((selD[0]-selD[k])/sigma)
        float wsum = 0.f, sx = 0.f, sy = 0.f, sz = 0.f;
#pragma unroll
        for (int k = 0; k < 7; k++) {
            float w = expf((selD[0] - selD[k]) / sigma);
            int i = selI[k];
            wsum += w;
            sx = fmaf(w, PX[i], sx);
            sy = fmaf(w, PY[i], sy);
            sz = fmaf(w, PZ[i], sz);
        }
        float inv = 1.0f / wsum;
        float nrm = g_norm[bp];
        float mex = g_mean[bp * 3 + 0], mey = g_mean[bp * 3 + 1], mez = g_mean[bp * 3 + 2];
        int o = (bp * MM + m) * 3;
        out[o + 0] = fmaf(sx * inv, nrm, mex);
        out[o + 1] = fmaf(sy * inv, nrm, mey);
        out[o + 2] = fmaf(sz * inv, nrm, mez);
    }
}

// =========================================================================
extern "C" void kernel_launch(void* const* d_in, const int* in_sizes, int n_in,
                              void* d_out, int out_size) {
    const float* xyz = (const float*)d_in[0];
    const float* mw0 = (const float*)d_in[1];  const float* mb0 = (const float*)d_in[2];
    const float* mw1 = (const float*)d_in[3];  const float* mb1 = (const float*)d_in[4];
    const float* mw2 = (const float*)d_in[5];  const float* mb2 = (const float*)d_in[6];
    const float* mw3 = (const float*)d_in[7];  const float* mb3 = (const float*)d_in[8];
    const float* mw4 = (const float*)d_in[9];  const float* mb4 = (const float*)d_in[10];
    const float* fw0 = (const float*)d_in[11]; const float* fb0 = (const float*)d_in[12];
    const float* fw1 = (const float*)d_in[13]; const float* fb1 = (const float*)d_in[14];
    const float* fw2 = (const float*)d_in[15]; const float* fb2 = (const float*)d_in[16];
    const float* fw3 = (const float*)d_in[17]; const float* fb3 = (const float*)d_in[18];
    const float* temp = (const float*)d_in[19];
    float* out = (float*)d_out;

    cudaFuncSetAttribute(mlp_kernel, cudaFuncAttributeMaxDynamicSharedMemorySize,
                         SW_TOTAL * sizeof(float));

    fps_kernel<<<BB, 1024>>>(xyz);
    knn_kernel<<<NPATCH, 256>>>(xyz);
    mlp_kernel<<<NPATCH, 256, SW_TOTAL * sizeof(float)>>>(
        mw0, mb0, mw1, mb1, mw2, mb2, mw3, mb3, mw4, mb4);
    dec_kernel<<<NPATCH, 256>>>(fw0, fb0, fw1, fb1, fw2, fb2, fw3, fb3);
    proj_kernel<<<NPATCH, 256>>>(temp, out);
}

// round 4
// speedup vs baseline: 2.2862x; 2.2862x over previous
#include <cuda_runtime.h>
#include <cuda_bf16.h>
#include <cstdint>

// ---------------- problem constants ----------------
#define BB 64
#define NN 8192
#define PP 8
#define SS 1024
#define MM 8
#define KK 7
#define NPATCH (BB*PP)   // 512

// ---------------- device scratch (no allocations allowed) ----------------
__device__ float g_seed[NPATCH * 3];
__device__ float g_patch[NPATCH * 3 * SS];      // normalized patch coords, SoA [bp][c][s]
__device__ float g_mean[NPATCH * 3];
__device__ float g_norm[NPATCH];
__device__ float g_feat[NPATCH * 128];
__device__ float g_gen[NPATCH * 24];

// =========================================================================
// helpers
// =========================================================================
__device__ __forceinline__ uint32_t smem_to_u32(const void* smem_ptr) {
    uint32_t addr;
    asm("{ .reg .u64 tmp; cvta.to.shared.u64 tmp, %1; cvt.u32.u64 %0, tmp; }"
        : "=r"(addr) : "l"(smem_ptr));
    return addr;
}

__device__ __forceinline__ void mma_bf16(float* c, const uint32_t* a, uint32_t b0, uint32_t b1) {
    asm volatile(
        "mma.sync.aligned.m16n8k16.row.col.f32.bf16.bf16.f32 "
        "{%0,%1,%2,%3}, {%4,%5,%6,%7}, {%8,%9}, {%0,%1,%2,%3};"
        : "+f"(c[0]), "+f"(c[1]), "+f"(c[2]), "+f"(c[3])
        : "r"(a[0]), "r"(a[1]), "r"(a[2]), "r"(a[3]), "r"(b0), "r"(b1));
}

__device__ __forceinline__ void ldm_x2(uint32_t& r0, uint32_t& r1, uint32_t addr) {
    asm volatile("ldmatrix.sync.aligned.m8n8.x2.shared.b16 {%0,%1}, [%2];"
                 : "=r"(r0), "=r"(r1) : "r"(addr));
}

__device__ __forceinline__ uint32_t pack_bf16x2(__nv_bfloat16 lo16, __nv_bfloat16 hi16) {
    return ((uint32_t)__bfloat16_as_ushort(hi16) << 16) | (uint32_t)__bfloat16_as_ushort(lo16);
}

// split (f0 -> low half, f1 -> high half) into hi/lo bf16x2 words
__device__ __forceinline__ void split2(float f0, float f1, uint32_t& hi, uint32_t& lo) {
    __nv_bfloat16 h0 = __float2bfloat16(f0), h1 = __float2bfloat16(f1);
    __nv_bfloat16 l0 = __float2bfloat16(f0 - __bfloat162float(h0));
    __nv_bfloat16 l1 = __float2bfloat16(f1 - __bfloat162float(h1));
    hi = pack_bf16x2(h0, h1);
    lo = pack_bf16x2(l0, l1);
}

// =========================================================================
// Kernel 1: farthest point sampling (proven correct; matches jax semantics)
// =========================================================================
__global__ void fps_kernel(const float* __restrict__ xyz) {
    int b = blockIdx.x;
    const float* X = xyz + (size_t)b * 3 * NN;
    __shared__ float s_v[32];
    __shared__ int   s_i[32];
    __shared__ float s_c[3];
    __shared__ int   s_far;
    int tid = threadIdx.x;
    int lane = tid & 31;
    int wrp = tid >> 5;

    float dist[8];
#pragma unroll
    for (int k = 0; k < 8; k++) dist[k] = 1e10f;
    int far = 0;

    for (int it = 0; it < PP; it++) {
        if (tid == 0) {
            float fx = X[far], fy = X[NN + far], fz = X[2 * NN + far];
            s_c[0] = fx; s_c[1] = fy; s_c[2] = fz;
            g_seed[(b * PP + it) * 3 + 0] = fx;
            g_seed[(b * PP + it) * 3 + 1] = fy;
            g_seed[(b * PP + it) * 3 + 2] = fz;
        }
        __syncthreads();
        float cx = s_c[0], cy = s_c[1], cz = s_c[2];
        float bv = -1.0f; int bi = 0;
#pragma unroll
        for (int k = 0; k < 8; k++) {
            int i = tid + k * 1024;
            float dx = X[i] - cx, dy = X[NN + i] - cy, dz = X[2 * NN + i] - cz;
            float d = dx * dx + dy * dy + dz * dz;
            float nd = fminf(dist[k], d);
            dist[k] = nd;
            if (nd > bv || (nd == bv && i < bi)) { bv = nd; bi = i; }
        }
        // warp argmax (first-index tie-break)
#pragma unroll
        for (int o = 16; o > 0; o >>= 1) {
            float ov = __shfl_xor_sync(0xffffffffu, bv, o);
            int oi = __shfl_xor_sync(0xffffffffu, bi, o);
            if (ov > bv || (ov == bv && oi < bi)) { bv = ov; bi = oi; }
        }
        if (lane == 0) { s_v[wrp] = bv; s_i[wrp] = bi; }
        __syncthreads();
        if (wrp == 0) {
            float mv = s_v[lane]; int mi = s_i[lane];
#pragma unroll
            for (int o = 16; o > 0; o >>= 1) {
                float ov = __shfl_xor_sync(0xffffffffu, mv, o);
                int oi = __shfl_xor_sync(0xffffffffu, mi, o);
                if (ov > mv || (ov == mv && oi < mi)) { mv = ov; mi = oi; }
            }
            if (lane == 0) s_far = mi;
        }
        __syncthreads();
        far = s_far;
        __syncthreads();
    }
}

// =========================================================================
// Kernel 2: KNN radix-select + patch normalization (proven correct)
// =========================================================================
__global__ void knn_kernel(const float* __restrict__ xyz) {
    int bp = blockIdx.x;
    int b = bp >> 3;
    const float* X = xyz + (size_t)b * 3 * NN;
    __shared__ unsigned s_key[NN];
    __shared__ int s_sel[SS];
    __shared__ int s_hist[256];
    __shared__ unsigned s_pref;
    __shared__ int s_kk;
    __shared__ int s_cnt[2];
    __shared__ float s_red[256];
    int tid = threadIdx.x;

    float sx = g_seed[bp * 3 + 0], sy = g_seed[bp * 3 + 1], sz = g_seed[bp * 3 + 2];
    float s2 = sx * sx + sy * sy + sz * sz;

    for (int i = tid; i < NN; i += 256) {
        float px = X[i], py = X[NN + i], pz = X[2 * NN + i];
        float p2 = px * px + py * py + pz * pz;
        float dot = sx * px + sy * py + sz * pz;
        float d = (s2 - 2.0f * dot) + p2;
        unsigned u = __float_as_uint(d);
        u = (u & 0x80000000u) ? ~u : (u | 0x80000000u);
        s_key[i] = u;
    }
    __syncthreads();

    unsigned prefix = 0, maskHi = 0;
    int kk = SS;
    for (int pass = 0; pass < 4; pass++) {
        int shift = 24 - 8 * pass;
        if (tid < 256) s_hist[tid] = 0;
        __syncthreads();
        for (int i = tid; i < NN; i += 256) {
            unsigned u = s_key[i];
            if ((u & maskHi) == prefix) atomicAdd(&s_hist[(u >> shift) & 255], 1);
        }
        __syncthreads();
        if (tid == 0) {
            int cum = 0, bsel = 0;
            for (bsel = 0; bsel < 256; bsel++) {
                int c = s_hist[bsel];
                if (cum + c >= kk) break;
                cum += c;
            }
            s_pref = prefix | ((unsigned)bsel << shift);
            s_kk = kk - cum;
        }
        __syncthreads();
        prefix = s_pref; kk = s_kk;
        maskHi |= (0xFFu << shift);
        __syncthreads();
    }
    unsigned T = prefix;

    if (tid == 0) { s_cnt[0] = 0; s_cnt[1] = 0; }
    __syncthreads();
    for (int i = tid; i < NN; i += 256) {
        if (s_key[i] < T) { int pos = atomicAdd(&s_cnt[0], 1); s_sel[pos] = i; }
    }
    __syncthreads();
    int nLess = s_cnt[0];
    for (int i = tid; i < NN; i += 256) {
        if (s_key[i] == T) {
            int pos = atomicAdd(&s_cnt[1], 1);
            if (nLess + pos < SS) s_sel[nLess + pos] = i;
        }
    }
    __syncthreads();

    float* cxs = (float*)s_key;
    float* cys = cxs + SS;
    float* czs = cxs + 2 * SS;
    float ax = 0.f, ay = 0.f, az = 0.f;
    for (int j = tid; j < SS; j += 256) {
        int i = s_sel[j];
        float px = X[i], py = X[NN + i], pz = X[2 * NN + i];
        cxs[j] = px; cys[j] = py; czs[j] = pz;
        ax += px; ay += py; az += pz;
    }
    s_red[tid] = ax; __syncthreads();
    for (int s = 128; s > 0; s >>= 1) { if (tid < s) s_red[tid] += s_red[tid + s]; __syncthreads(); }
    float mx = s_red[0] * (1.0f / SS); __syncthreads();
    s_red[tid] = ay; __syncthreads();
    for (int s = 128; s > 0; s >>= 1) { if (tid < s) s_red[tid] += s_red[tid + s]; __syncthreads(); }
    float my = s_red[0] * (1.0f / SS); __syncthreads();
    s_red[tid] = az; __syncthreads();
    for (int s = 128; s > 0; s >>= 1) { if (tid < s) s_red[tid] += s_red[tid + s]; __syncthreads(); }
    float mz = s_red[0] * (1.0f / SS); __syncthreads();

    float mnorm = 0.f;
    for (int j = tid; j < SS; j += 256) {
        float dx = cxs[j] - mx, dy = cys[j] - my, dz = czs[j] - mz;
        float l = sqrtf(dx * dx + dy * dy + dz * dz);
        mnorm = fmaxf(mnorm, l);
    }
    s_red[tid] = mnorm; __syncthreads();
    for (int s = 128; s > 0; s >>= 1) { if (tid < s) s_red[tid] = fmaxf(s_red[tid], s_red[tid + s]); __syncthreads(); }
    float nrm = s_red[0]; __syncthreads();

    for (int j = tid; j < SS; j += 256) {
        g_patch[(bp * 3 + 0) * SS + j] = (cxs[j] - mx) / nrm;
        g_patch[(bp * 3 + 1) * SS + j] = (cys[j] - my) / nrm;
        g_patch[(bp * 3 + 2) * SS + j] = (czs[j] - mz) / nrm;
    }
    if (tid == 0) {
        g_mean[bp * 3 + 0] = mx; g_mean[bp * 3 + 1] = my; g_mean[bp * 3 + 2] = mz;
        g_norm[bp] = nrm;
    }
}

// =========================================================================
// Kernel 3: fused MLP via mma.sync bf16, split-bf16 3-term (fp32-class).
// Block = 1 patch, 256 threads = 8 warps; warp handles 16 points/iter, 8 iters.
// Weights in SMEM as [n][k] bf16 rows (stride = K*2+16, conflict-free ldmatrix).
// Activations stay in registers: C-fragment -> (bias,relu,split) -> A-fragment.
// =========================================================================
#define O_W1H 0
#define O_W1L 3072
#define O_W2H 6144
#define O_W2L 15360
#define O_W3H 24576
#define O_W3L 33792
#define O_W4H 43008
#define O_W4L 61440
#define O_W5H 79872
#define O_W5L 114688
#define O_BIAS 149504        // 448 floats: b1@0 b2@64 b3@128 b4@192 b5@320
#define DYN_TOT 151296

template<int K, int N, int STRIDE>
__device__ __forceinline__ void stage_w(const float* __restrict__ w,
                                        char* hi, char* lo, int tid) {
    for (int i = tid; i < K * N; i += 256) {
        int k = i / N, n = i - k * N;
        float f = w[i];
        __nv_bfloat16 h = __float2bfloat16(f);
        __nv_bfloat16 l = __float2bfloat16(f - __bfloat162float(h));
        int off = n * STRIDE + k * 2;
        *(__nv_bfloat16*)(hi + off) = h;
        *(__nv_bfloat16*)(lo + off) = l;
    }
}

// one hidden layer: C = A*W (3-term), bias+relu, convert C-frags -> next A-frags
template<int KC, int NT, int STRIDE>
__device__ __forceinline__ void layer_forward(
    const uint32_t (*Ah)[4], const uint32_t (*Al)[4],
    uint32_t wH, uint32_t wL, const float* __restrict__ bias, int lane,
    uint32_t (*Oh)[4], uint32_t (*Ol)[4]) {
    uint32_t lm = (uint32_t)(lane & 7) * STRIDE + (uint32_t)((lane >> 3) & 1) * 16;
    int t4 = lane & 3;
#pragma unroll
    for (int np = 0; np < NT / 2; np++) {
        float cc[2][4];
#pragma unroll
        for (int sub = 0; sub < 2; sub++) {
            int nt = np * 2 + sub;
            float c[4] = {0.f, 0.f, 0.f, 0.f};
            uint32_t ro = lm + (uint32_t)nt * 8u * STRIDE;
#pragma unroll
            for (int kc = 0; kc < KC; kc++) {
                uint32_t b0, b1, l0, l1;
                ldm_x2(b0, b1, wH + ro + kc * 32);
                ldm_x2(l0, l1, wL + ro + kc * 32);
                mma_bf16(c, Ah[kc], b0, b1);
                mma_bf16(c, Ah[kc], l0, l1);
                mma_bf16(c, Al[kc], b0, b1);
            }
            float2 bb = *reinterpret_cast<const float2*>(bias + nt * 8 + t4 * 2);
            cc[sub][0] = fmaxf(c[0] + bb.x, 0.f);
            cc[sub][1] = fmaxf(c[1] + bb.y, 0.f);
            cc[sub][2] = fmaxf(c[2] + bb.x, 0.f);
            cc[sub][3] = fmaxf(c[3] + bb.y, 0.f);
        }
        split2(cc[0][0], cc[0][1], Oh[np][0], Ol[np][0]);
        split2(cc[0][2], cc[0][3], Oh[np][1], Ol[np][1]);
        split2(cc[1][0], cc[1][1], Oh[np][2], Ol[np][2]);
        split2(cc[1][2], cc[1][3], Oh[np][3], Ol[np][3]);
    }
}

// final layer: C = A*W, bias+relu, maxpool over the 16 rows -> shared atomicMax
template<int KC, int NT, int STRIDE>
__device__ __forceinline__ void layer_final(
    const uint32_t (*Ah)[4], const uint32_t (*Al)[4],
    uint32_t wH, uint32_t wL, const float* __restrict__ bias, int lane, int* smax) {
    uint32_t lm = (uint32_t)(lane & 7) * STRIDE + (uint32_t)((lane >> 3) & 1) * 16;
    int t4 = lane & 3;
#pragma unroll
    for (int nt = 0; nt < NT; nt++) {
        float c[4] = {0.f, 0.f, 0.f, 0.f};
        uint32_t ro = lm + (uint32_t)nt * 8u * STRIDE;
#pragma unroll
        for (int kc = 0; kc < KC; kc++) {
            uint32_t b0, b1, l0, l1;
            ldm_x2(b0, b1, wH + ro + kc * 32);
            ldm_x2(l0, l1, wL + ro + kc * 32);
            mma_bf16(c, Ah[kc], b0, b1);
            mma_bf16(c, Ah[kc], l0, l1);
            mma_bf16(c, Al[kc], b0, b1);
        }
        float2 bb = *reinterpret_cast<const float2*>(bias + nt * 8 + t4 * 2);
        float m0 = fmaxf(fmaxf(c[0] + bb.x, 0.f), fmaxf(c[2] + bb.x, 0.f));
        float m1 = fmaxf(fmaxf(c[1] + bb.y, 0.f), fmaxf(c[3] + bb.y, 0.f));
#pragma unroll
        for (int off = 4; off < 32; off <<= 1) {
            m0 = fmaxf(m0, __shfl_xor_sync(0xffffffffu, m0, off));
            m1 = fmaxf(m1, __shfl_xor_sync(0xffffffffu, m1, off));
        }
        if (lane < 4) {
            atomicMax(&smax[nt * 8 + 2 * lane], __float_as_int(m0));
            atomicMax(&smax[nt * 8 + 2 * lane + 1], __float_as_int(m1));
        }
    }
}

__global__ void __launch_bounds__(256, 1) mlp_mma_kernel(
    const float* __restrict__ mw0, const float* __restrict__ mb0,
    const float* __restrict__ mw1, const float* __restrict__ mb1,
    const float* __restrict__ mw2, const float* __restrict__ mb2,
    const float* __restrict__ mw3, const float* __restrict__ mb3,
    const float* __restrict__ mw4, const float* __restrict__ mb4) {
    extern __shared__ char sm[];
    __shared__ int smax[128];
    int bp = blockIdx.x;
    int tid = threadIdx.x;
    int lane = tid & 31;
    int w = tid >> 5;
    uint32_t sbase = smem_to_u32(sm);

    if (tid < 128) smax[tid] = 0;
    // zero L1 weight tiles (only k<3 rows carry data)
    for (int i = tid; i < 6144 / 4; i += 256) ((uint32_t*)sm)[i] = 0;
    __syncthreads();

    stage_w<3, 64, 48>(mw0, sm + O_W1H, sm + O_W1L, tid);
    stage_w<64, 64, 144>(mw1, sm + O_W2H, sm + O_W2L, tid);
    stage_w<64, 64, 144>(mw2, sm + O_W3H, sm + O_W3L, tid);
    stage_w<64, 128, 144>(mw3, sm + O_W4H, sm + O_W4L, tid);
    stage_w<128, 128, 272>(mw4, sm + O_W5H, sm + O_W5L, tid);
    float* sbias = (float*)(sm + O_BIAS);
    for (int i = tid; i < 64; i += 256) {
        sbias[i] = mb0[i]; sbias[64 + i] = mb1[i]; sbias[128 + i] = mb2[i];
    }
    for (int i = tid; i < 128; i += 256) {
        sbias[192 + i] = mb3[i]; sbias[320 + i] = mb4[i];
    }
    __syncthreads();

    const float* PX = &g_patch[(bp * 3 + 0) * SS];
    const float* PY = &g_patch[(bp * 3 + 1) * SS];
    const float* PZ = &g_patch[(bp * 3 + 2) * SS];
    int t4 = lane & 3;

    for (int it = 0; it < 8; it++) {
        int p0 = it * 128 + w * 16 + (lane >> 2);
        int p1 = p0 + 8;
        float x0 = PX[p0], y0 = PY[p0], z0 = PZ[p0];
        float x1 = PX[p1], y1 = PY[p1], z1 = PZ[p1];

        // L1 A fragment (16x16, only cols 0..2 nonzero)
        uint32_t A1h[1][4] = {{0u, 0u, 0u, 0u}};
        uint32_t A1l[1][4] = {{0u, 0u, 0u, 0u}};
        if (t4 == 0) {
            split2(x0, y0, A1h[0][0], A1l[0][0]);
            split2(x1, y1, A1h[0][1], A1l[0][1]);
        } else if (t4 == 1) {
            split2(z0, 0.f, A1h[0][0], A1l[0][0]);
            split2(z1, 0.f, A1h[0][1], A1l[0][1]);
        }

        uint32_t A2h[4][4], A2l[4][4];
        uint32_t A3h[4][4], A3l[4][4];
        uint32_t A4h[4][4], A4l[4][4];
        uint32_t A5h[8][4], A5l[8][4];

        layer_forward<1, 8, 48>(A1h, A1l, sbase + O_W1H, sbase + O_W1L, sbias + 0, lane, A2h, A2l);
        layer_forward<4, 8, 144>(A2h, A2l, sbase + O_W2H, sbase + O_W2L, sbias + 64, lane, A3h, A3l);
        layer_forward<4, 8, 144>(A3h, A3l, sbase + O_W3H, sbase + O_W3L, sbias + 128, lane, A4h, A4l);
        layer_forward<4, 16, 144>(A4h, A4l, sbase + O_W4H, sbase + O_W4L, sbias + 192, lane, A5h, A5l);
        layer_final<8, 16, 272>(A5h, A5l, sbase + O_W5H, sbase + O_W5L, sbias + 320, lane, smax);
    }
    __syncthreads();
    if (tid < 128) g_feat[bp * 128 + tid] = __int_as_float(smax[tid]);
}

// =========================================================================
// Kernel 4: per-patch FC decoder, 4 independent accumulator chains for ILP
// =========================================================================
__global__ void dec_kernel(
    const float* __restrict__ fw0, const float* __restrict__ fb0,
    const float* __restrict__ fw1, const float* __restrict__ fb1,
    const float* __restrict__ fw2, const float* __restrict__ fb2,
    const float* __restrict__ fw3, const float* __restrict__ fb3) {
    int bp = blockIdx.x;
    int tid = threadIdx.x;
    __shared__ float a0[256], a1[256];
    if (tid < 128) a0[tid] = g_feat[bp * 128 + tid];
    __syncthreads();
    {
        float p0 = 0.f, p1 = 0.f, p2 = 0.f, p3 = 0.f;
#pragma unroll 8
        for (int i = 0; i < 128; i += 4) {
            p0 = fmaf(a0[i], fw0[i * 256 + tid], p0);
            p1 = fmaf(a0[i + 1], fw0[(i + 1) * 256 + tid], p1);
            p2 = fmaf(a0[i + 2], fw0[(i + 2) * 256 + tid], p2);
            p3 = fmaf(a0[i + 3], fw0[(i + 3) * 256 + tid], p3);
        }
        a1[tid] = fmaxf(fb0[tid] + ((p0 + p1) + (p2 + p3)), 0.f);
    }
    __syncthreads();
    {
        float p0 = 0.f, p1 = 0.f, p2 = 0.f, p3 = 0.f;
#pragma unroll 8
        for (int i = 0; i < 256; i += 4) {
            p0 = fmaf(a1[i], fw1[i * 256 + tid], p0);
            p1 = fmaf(a1[i + 1], fw1[(i + 1) * 256 + tid], p1);
            p2 = fmaf(a1[i + 2], fw1[(i + 2) * 256 + tid], p2);
            p3 = fmaf(a1[i + 3], fw1[(i + 3) * 256 + tid], p3);
        }
        a0[tid] = fmaxf(fb1[tid] + ((p0 + p1) + (p2 + p3)), 0.f);
    }
    __syncthreads();
    {
        float p0 = 0.f, p1 = 0.f, p2 = 0.f, p3 = 0.f;
#pragma unroll 8
        for (int i = 0; i < 256; i += 4) {
            p0 = fmaf(a0[i], fw2[i * 256 + tid], p0);
            p1 = fmaf(a0[i + 1], fw2[(i + 1) * 256 + tid], p1);
            p2 = fmaf(a0[i + 2], fw2[(i + 2) * 256 + tid], p2);
            p3 = fmaf(a0[i + 3], fw2[(i + 3) * 256 + tid], p3);
        }
        a1[tid] = fmaxf(fb2[tid] + ((p0 + p1) + (p2 + p3)), 0.f);
    }
    __syncthreads();
    if (tid < 24) {
        float p0 = 0.f, p1 = 0.f, p2 = 0.f, p3 = 0.f;
#pragma unroll 8
        for (int i = 0; i < 256; i += 4) {
            p0 = fmaf(a1[i], fw3[i * 24 + tid], p0);
            p1 = fmaf(a1[i + 1], fw3[(i + 1) * 24 + tid], p1);
            p2 = fmaf(a1[i + 2], fw3[(i + 2) * 24 + tid], p2);
            p3 = fmaf(a1[i + 3], fw3[(i + 3) * 24 + tid], p3);
        }
        g_gen[bp * 24 + tid] = fb3[tid] + ((p0 + p1) + (p2 + p3));
    }
}

// =========================================================================
// Kernel 5: SoftProjection (proven correct)
// =========================================================================
__global__ void proj_kernel(const float* __restrict__ temperature,
                            float* __restrict__ out) {
    int bp = blockIdx.x;
    int tid = threadIdx.x;
    int m = tid >> 5;
    int lane = tid & 31;
    float t = temperature[0];
    float sigma = fmaxf(t * t, 1e-4f);

    const float* PX = &g_patch[(bp * 3 + 0) * SS];
    const float* PY = &g_patch[(bp * 3 + 1) * SS];
    const float* PZ = &g_patch[(bp * 3 + 2) * SS];

    float qx = g_gen[bp * 24 + m * 3 + 0];
    float qy = g_gen[bp * 24 + m * 3 + 1];
    float qz = g_gen[bp * 24 + m * 3 + 2];
    float q2 = qx * qx + qy * qy + qz * qz;

    float bd[7]; int bi[7];
#pragma unroll
    for (int k = 0; k < 7; k++) { bd[k] = 3.4e38f; bi[k] = 0; }

    for (int i = lane; i < SS; i += 32) {
        float px = PX[i], py = PY[i], pz = PZ[i];
        float p2 = px * px + py * py + pz * pz;
        float dot = qx * px + qy * py + qz * pz;
        float d = (q2 - 2.0f * dot) + p2;
        if (d < bd[6]) {
            bd[6] = d; bi[6] = i;
#pragma unroll
            for (int k = 6; k > 0; k--) {
                if (bd[k] < bd[k - 1]) {
                    float td = bd[k]; bd[k] = bd[k - 1]; bd[k - 1] = td;
                    int ti = bi[k]; bi[k] = bi[k - 1]; bi[k - 1] = ti;
                }
            }
        }
    }
    float selD[7]; int selI[7];
#pragma unroll
    for (int k = 0; k < 7; k++) {
        float mv = bd[0]; int ml = lane;
#pragma unroll
        for (int o = 16; o > 0; o >>= 1) {
            float ov = __shfl_xor_sync(0xffffffffu, mv, o);
            int ol = __shfl_xor_sync(0xffffffffu, ml, o);
            if (ov < mv || (ov == mv && ol < ml)) { mv = ov; ml = ol; }
        }
        selD[k] = mv;
        selI[k] = __shfl_sync(0xffffffffu, bi[0], ml);
        if (lane == ml) {
#pragma unroll
            for (int q = 0; q < 6; q++) { bd[q] = bd[q + 1]; bi[q] = bi[q + 1]; }
            bd[6] = 3.4e38f;
        }
    }
    if (lane == 0) {
        float wsum = 0.f, sx = 0.f, sy = 0.f, sz = 0.f;
#pragma unroll
        for (int k = 0; k < 7; k++) {
            float w = expf((selD[0] - selD[k]) / sigma);
            int i = selI[k];
            wsum += w;
            sx = fmaf(w, PX[i], sx);
            sy = fmaf(w, PY[i], sy);
            sz = fmaf(w, PZ[i], sz);
        }
        float inv = 1.0f / wsum;
        float nrm = g_norm[bp];
        float mex = g_mean[bp * 3 + 0], mey = g_mean[bp * 3 + 1], mez = g_mean[bp * 3 + 2];
        int o = (bp * MM + m) * 3;
        out[o + 0] = fmaf(sx * inv, nrm, mex);
        out[o + 1] = fmaf(sy * inv, nrm, mey);
        out[o + 2] = fmaf(sz * inv, nrm, mez);
    }
}

// =========================================================================
extern "C" void kernel_launch(void* const* d_in, const int* in_sizes, int n_in,
                              void* d_out, int out_size) {
    const float* xyz = (const float*)d_in[0];
    const float* mw0 = (const float*)d_in[1];  const float* mb0 = (const float*)d_in[2];
    const float* mw1 = (const float*)d_in[3];  const float* mb1 = (const float*)d_in[4];
    const float* mw2 = (const float*)d_in[5];  const float* mb2 = (const float*)d_in[6];
    const float* mw3 = (const float*)d_in[7];  const float* mb3 = (const float*)d_in[8];
    const float* mw4 = (const float*)d_in[9];  const float* mb4 = (const float*)d_in[10];
    const float* fw0 = (const float*)d_in[11]; const float* fb0 = (const float*)d_in[12];
    const float* fw1 = (const float*)d_in[13]; const float* fb1 = (const float*)d_in[14];
    const float* fw2 = (const float*)d_in[15]; const float* fb2 = (const float*)d_in[16];
    const float* fw3 = (const float*)d_in[17]; const float* fb3 = (const float*)d_in[18];
    const float* temp = (const float*)d_in[19];
    float* out = (float*)d_out;

    cudaFuncSetAttribute(mlp_mma_kernel, cudaFuncAttributeMaxDynamicSharedMemorySize,
                         DYN_TOT);

    fps_kernel<<<BB, 1024>>>(xyz);
    knn_kernel<<<NPATCH, 256>>>(xyz);
    mlp_mma_kernel<<<NPATCH, 256, DYN_TOT>>>(
        mw0, mb0, mw1, mb1, mw2, mb2, mw3, mb3, mw4, mb4);
    dec_kernel<<<NPATCH, 256>>>(fw0, fb0, fw1, fb1, fw2, fb2, fw3, fb3);
    proj_kernel<<<NPATCH, 256>>>(temp, out);
}

// round 5
// speedup vs baseline: 3.6205x; 1.5836x over previous
#include <cuda_runtime.h>
#include <cuda_bf16.h>
#include <cstdint>

// ---------------- problem constants ----------------
#define BB 64
#define NN 8192
#define PP 8
#define SS 1024
#define MM 8
#define KK 7
#define NPATCH (BB*PP)   // 512

// ---------------- device scratch (no allocations allowed) ----------------
__device__ float g_seed[NPATCH * 3];
__device__ float g_patch[NPATCH * 3 * SS];      // normalized patch coords, SoA [bp][c][s]
__device__ float g_mean[NPATCH * 3];
__device__ float g_norm[NPATCH];
__device__ float g_feat[NPATCH * 128];
__device__ float g_gen[NPATCH * 24];

// =========================================================================
// helpers
// =========================================================================
__device__ __forceinline__ uint32_t smem_to_u32(const void* smem_ptr) {
    uint32_t addr;
    asm("{ .reg .u64 tmp; cvta.to.shared.u64 tmp, %1; cvt.u32.u64 %0, tmp; }"
        : "=r"(addr) : "l"(smem_ptr));
    return addr;
}

__device__ __forceinline__ void mma_bf16(float* c, const uint32_t* a, uint32_t b0, uint32_t b1) {
    asm volatile(
        "mma.sync.aligned.m16n8k16.row.col.f32.bf16.bf16.f32 "
        "{%0,%1,%2,%3}, {%4,%5,%6,%7}, {%8,%9}, {%0,%1,%2,%3};"
        : "+f"(c[0]), "+f"(c[1]), "+f"(c[2]), "+f"(c[3])
        : "r"(a[0]), "r"(a[1]), "r"(a[2]), "r"(a[3]), "r"(b0), "r"(b1));
}

__device__ __forceinline__ void ldm_x2(uint32_t& r0, uint32_t& r1, uint32_t addr) {
    asm volatile("ldmatrix.sync.aligned.m8n8.x2.shared.b16 {%0,%1}, [%2];"
                 : "=r"(r0), "=r"(r1) : "r"(addr));
}

__device__ __forceinline__ uint32_t pack_bf16x2(__nv_bfloat16 lo16, __nv_bfloat16 hi16) {
    return ((uint32_t)__bfloat16_as_ushort(hi16) << 16) | (uint32_t)__bfloat16_as_ushort(lo16);
}

// split (f0 -> low half, f1 -> high half) into hi/lo bf16x2 words
__device__ __forceinline__ void split2(float f0, float f1, uint32_t& hi, uint32_t& lo) {
    __nv_bfloat16 h0 = __float2bfloat16(f0), h1 = __float2bfloat16(f1);
    __nv_bfloat16 l0 = __float2bfloat16(f0 - __bfloat162float(h0));
    __nv_bfloat16 l1 = __float2bfloat16(f1 - __bfloat162float(h1));
    hi = pack_bf16x2(h0, h1);
    lo = pack_bf16x2(l0, l1);
}

// =========================================================================
// Kernel 1: farthest point sampling (proven correct; matches jax semantics)
// =========================================================================
__global__ void fps_kernel(const float* __restrict__ xyz) {
    int b = blockIdx.x;
    const float* X = xyz + (size_t)b * 3 * NN;
    __shared__ float s_v[32];
    __shared__ int   s_i[32];
    __shared__ float s_c[3];
    __shared__ int   s_far;
    int tid = threadIdx.x;
    int lane = tid & 31;
    int wrp = tid >> 5;

    float dist[8];
#pragma unroll
    for (int k = 0; k < 8; k++) dist[k] = 1e10f;
    int far = 0;

    for (int it = 0; it < PP; it++) {
        if (tid == 0) {
            float fx = X[far], fy = X[NN + far], fz = X[2 * NN + far];
            s_c[0] = fx; s_c[1] = fy; s_c[2] = fz;
            g_seed[(b * PP + it) * 3 + 0] = fx;
            g_seed[(b * PP + it) * 3 + 1] = fy;
            g_seed[(b * PP + it) * 3 + 2] = fz;
        }
        __syncthreads();
        float cx = s_c[0], cy = s_c[1], cz = s_c[2];
        float bv = -1.0f; int bi = 0;
#pragma unroll
        for (int k = 0; k < 8; k++) {
            int i = tid + k * 1024;
            float dx = X[i] - cx, dy = X[NN + i] - cy, dz = X[2 * NN + i] - cz;
            float d = dx * dx + dy * dy + dz * dz;
            float nd = fminf(dist[k], d);
            dist[k] = nd;
            if (nd > bv || (nd == bv && i < bi)) { bv = nd; bi = i; }
        }
#pragma unroll
        for (int o = 16; o > 0; o >>= 1) {
            float ov = __shfl_xor_sync(0xffffffffu, bv, o);
            int oi = __shfl_xor_sync(0xffffffffu, bi, o);
            if (ov > bv || (ov == bv && oi < bi)) { bv = ov; bi = oi; }
        }
        if (lane == 0) { s_v[wrp] = bv; s_i[wrp] = bi; }
        __syncthreads();
        if (wrp == 0) {
            float mv = s_v[lane]; int mi = s_i[lane];
#pragma unroll
            for (int o = 16; o > 0; o >>= 1) {
                float ov = __shfl_xor_sync(0xffffffffu, mv, o);
                int oi = __shfl_xor_sync(0xffffffffu, mi, o);
                if (ov > mv || (ov == mv && oi < mi)) { mv = ov; mi = oi; }
            }
            if (lane == 0) s_far = mi;
        }
        __syncthreads();
        far = s_far;
        __syncthreads();
    }
}

// =========================================================================
// Kernel 2: KNN radix-select + patch normalization (proven correct)
// =========================================================================
__global__ void knn_kernel(const float* __restrict__ xyz) {
    int bp = blockIdx.x;
    int b = bp >> 3;
    const float* X = xyz + (size_t)b * 3 * NN;
    __shared__ unsigned s_key[NN];
    __shared__ int s_sel[SS];
    __shared__ int s_hist[256];
    __shared__ unsigned s_pref;
    __shared__ int s_kk;
    __shared__ int s_cnt[2];
    __shared__ float s_red[256];
    int tid = threadIdx.x;

    float sx = g_seed[bp * 3 + 0], sy = g_seed[bp * 3 + 1], sz = g_seed[bp * 3 + 2];
    float s2 = sx * sx + sy * sy + sz * sz;

    for (int i = tid; i < NN; i += 256) {
        float px = X[i], py = X[NN + i], pz = X[2 * NN + i];
        float p2 = px * px + py * py + pz * pz;
        float dot = sx * px + sy * py + sz * pz;
        float d = (s2 - 2.0f * dot) + p2;
        unsigned u = __float_as_uint(d);
        u = (u & 0x80000000u) ? ~u : (u | 0x80000000u);
        s_key[i] = u;
    }
    __syncthreads();

    unsigned prefix = 0, maskHi = 0;
    int kk = SS;
    for (int pass = 0; pass < 4; pass++) {
        int shift = 24 - 8 * pass;
        if (tid < 256) s_hist[tid] = 0;
        __syncthreads();
        for (int i = tid; i < NN; i += 256) {
            unsigned u = s_key[i];
            if ((u & maskHi) == prefix) atomicAdd(&s_hist[(u >> shift) & 255], 1);
        }
        __syncthreads();
        if (tid == 0) {
            int cum = 0, bsel = 0;
            for (bsel = 0; bsel < 256; bsel++) {
                int c = s_hist[bsel];
                if (cum + c >= kk) break;
                cum += c;
            }
            s_pref = prefix | ((unsigned)bsel << shift);
            s_kk = kk - cum;
        }
        __syncthreads();
        prefix = s_pref; kk = s_kk;
        maskHi |= (0xFFu << shift);
        __syncthreads();
    }
    unsigned T = prefix;

    if (tid == 0) { s_cnt[0] = 0; s_cnt[1] = 0; }
    __syncthreads();
    for (int i = tid; i < NN; i += 256) {
        if (s_key[i] < T) { int pos = atomicAdd(&s_cnt[0], 1); s_sel[pos] = i; }
    }
    __syncthreads();
    int nLess = s_cnt[0];
    for (int i = tid; i < NN; i += 256) {
        if (s_key[i] == T) {
            int pos = atomicAdd(&s_cnt[1], 1);
            if (nLess + pos < SS) s_sel[nLess + pos] = i;
        }
    }
    __syncthreads();

    float* cxs = (float*)s_key;
    float* cys = cxs + SS;
    float* czs = cxs + 2 * SS;
    float ax = 0.f, ay = 0.f, az = 0.f;
    for (int j = tid; j < SS; j += 256) {
        int i = s_sel[j];
        float px = X[i], py = X[NN + i], pz = X[2 * NN + i];
        cxs[j] = px; cys[j] = py; czs[j] = pz;
        ax += px; ay += py; az += pz;
    }
    s_red[tid] = ax; __syncthreads();
    for (int s = 128; s > 0; s >>= 1) { if (tid < s) s_red[tid] += s_red[tid + s]; __syncthreads(); }
    float mx = s_red[0] * (1.0f / SS); __syncthreads();
    s_red[tid] = ay; __syncthreads();
    for (int s = 128; s > 0; s >>= 1) { if (tid < s) s_red[tid] += s_red[tid + s]; __syncthreads(); }
    float my = s_red[0] * (1.0f / SS); __syncthreads();
    s_red[tid] = az; __syncthreads();
    for (int s = 128; s > 0; s >>= 1) { if (tid < s) s_red[tid] += s_red[tid + s]; __syncthreads(); }
    float mz = s_red[0] * (1.0f / SS); __syncthreads();

    float mnorm = 0.f;
    for (int j = tid; j < SS; j += 256) {
        float dx = cxs[j] - mx, dy = cys[j] - my, dz = czs[j] - mz;
        float l = sqrtf(dx * dx + dy * dy + dz * dz);
        mnorm = fmaxf(mnorm, l);
    }
    s_red[tid] = mnorm; __syncthreads();
    for (int s = 128; s > 0; s >>= 1) { if (tid < s) s_red[tid] = fmaxf(s_red[tid], s_red[tid + s]); __syncthreads(); }
    float nrm = s_red[0]; __syncthreads();

    for (int j = tid; j < SS; j += 256) {
        g_patch[(bp * 3 + 0) * SS + j] = (cxs[j] - mx) / nrm;
        g_patch[(bp * 3 + 1) * SS + j] = (cys[j] - my) / nrm;
        g_patch[(bp * 3 + 2) * SS + j] = (czs[j] - mz) / nrm;
    }
    if (tid == 0) {
        g_mean[bp * 3 + 0] = mx; g_mean[bp * 3 + 1] = my; g_mean[bp * 3 + 2] = mz;
        g_norm[bp] = nrm;
    }
}

// =========================================================================
// Kernel 3: fused MLP via mma.sync bf16 split-bf16 (3-term, fp32-class).
// Block = 1 patch, 8 warps; each warp: 2 M-tiles (32 points) per iter, 4 iters.
// B-fragments shared across the 2 tiles (halves ldmatrix); each tile uses
// 2 accumulators (AhBh | AhBl+AlBh) -> 4 independent mma chains in flight.
// =========================================================================
#define O_W1H 0
#define O_W1L 3072
#define O_W2H 6144
#define O_W2L 15360
#define O_W3H 24576
#define O_W3L 33792
#define O_W4H 43008
#define O_W4L 61440
#define O_W5H 79872
#define O_W5L 114688
#define O_BIAS 149504        // 448 floats: b1@0 b2@64 b3@128 b4@192 b5@320
#define DYN_TOT 151296

template<int K, int N, int STRIDE>
__device__ __forceinline__ void stage_w(const float* __restrict__ w,
                                        char* hi, char* lo, int tid) {
    for (int i = tid; i < K * N; i += 256) {
        int k = i / N, n = i - k * N;
        float f = w[i];
        __nv_bfloat16 h = __float2bfloat16(f);
        __nv_bfloat16 l = __float2bfloat16(f - __bfloat162float(h));
        int off = n * STRIDE + k * 2;
        *(__nv_bfloat16*)(hi + off) = h;
        *(__nv_bfloat16*)(lo + off) = l;
    }
}

// hidden layer for TWO M-tiles sharing B fragments.
template<int KC, int NT, int STRIDE>
__device__ __forceinline__ void layer_forward2(
    const uint32_t (*Ah0)[4], const uint32_t (*Al0)[4],
    const uint32_t (*Ah1)[4], const uint32_t (*Al1)[4],
    uint32_t wH, uint32_t wL, const float* __restrict__ bias, int lane,
    uint32_t (*Oh0)[4], uint32_t (*Ol0)[4],
    uint32_t (*Oh1)[4], uint32_t (*Ol1)[4]) {
    uint32_t lm = (uint32_t)(lane & 7) * STRIDE + (uint32_t)((lane >> 3) & 1) * 16;
    int t4 = lane & 3;
#pragma unroll
    for (int np = 0; np < NT / 2; np++) {
        float ccA[2][4], ccB[2][4];
#pragma unroll
        for (int sub = 0; sub < 2; sub++) {
            int nt = np * 2 + sub;
            uint32_t ro = lm + (uint32_t)nt * 8u * STRIDE;
            float c1a[4] = {0.f, 0.f, 0.f, 0.f}, c2a[4] = {0.f, 0.f, 0.f, 0.f};
            float c1b[4] = {0.f, 0.f, 0.f, 0.f}, c2b[4] = {0.f, 0.f, 0.f, 0.f};
#pragma unroll
            for (int kc = 0; kc < KC; kc++) {
                uint32_t b0, b1, l0, l1;
                ldm_x2(b0, b1, wH + ro + kc * 32);
                ldm_x2(l0, l1, wL + ro + kc * 32);
                mma_bf16(c1a, Ah0[kc], b0, b1);
                mma_bf16(c1b, Ah1[kc], b0, b1);
                mma_bf16(c2a, Ah0[kc], l0, l1);
                mma_bf16(c2b, Ah1[kc], l0, l1);
                mma_bf16(c2a, Al0[kc], b0, b1);
                mma_bf16(c2b, Al1[kc], b0, b1);
            }
            float2 bb = *reinterpret_cast<const float2*>(bias + nt * 8 + t4 * 2);
            ccA[sub][0] = fmaxf(c1a[0] + c2a[0] + bb.x, 0.f);
            ccA[sub][1] = fmaxf(c1a[1] + c2a[1] + bb.y, 0.f);
            ccA[sub][2] = fmaxf(c1a[2] + c2a[2] + bb.x, 0.f);
            ccA[sub][3] = fmaxf(c1a[3] + c2a[3] + bb.y, 0.f);
            ccB[sub][0] = fmaxf(c1b[0] + c2b[0] + bb.x, 0.f);
            ccB[sub][1] = fmaxf(c1b[1] + c2b[1] + bb.y, 0.f);
            ccB[sub][2] = fmaxf(c1b[2] + c2b[2] + bb.x, 0.f);
            ccB[sub][3] = fmaxf(c1b[3] + c2b[3] + bb.y, 0.f);
        }
        split2(ccA[0][0], ccA[0][1], Oh0[np][0], Ol0[np][0]);
        split2(ccA[0][2], ccA[0][3], Oh0[np][1], Ol0[np][1]);
        split2(ccA[1][0], ccA[1][1], Oh0[np][2], Ol0[np][2]);
        split2(ccA[1][2], ccA[1][3], Oh0[np][3], Ol0[np][3]);
        split2(ccB[0][0], ccB[0][1], Oh1[np][0], Ol1[np][0]);
        split2(ccB[0][2], ccB[0][3], Oh1[np][1], Ol1[np][1]);
        split2(ccB[1][0], ccB[1][1], Oh1[np][2], Ol1[np][2]);
        split2(ccB[1][2], ccB[1][3], Oh1[np][3], Ol1[np][3]);
    }
}

// final layer for TWO M-tiles: maxpool over 32 rows -> shared atomicMax
template<int KC, int NT, int STRIDE>
__device__ __forceinline__ void layer_final2(
    const uint32_t (*Ah0)[4], const uint32_t (*Al0)[4],
    const uint32_t (*Ah1)[4], const uint32_t (*Al1)[4],
    uint32_t wH, uint32_t wL, const float* __restrict__ bias, int lane, int* smax) {
    uint32_t lm = (uint32_t)(lane & 7) * STRIDE + (uint32_t)((lane >> 3) & 1) * 16;
    int t4 = lane & 3;
#pragma unroll
    for (int nt = 0; nt < NT; nt++) {
        uint32_t ro = lm + (uint32_t)nt * 8u * STRIDE;
        float c1a[4] = {0.f, 0.f, 0.f, 0.f}, c2a[4] = {0.f, 0.f, 0.f, 0.f};
        float c1b[4] = {0.f, 0.f, 0.f, 0.f}, c2b[4] = {0.f, 0.f, 0.f, 0.f};
#pragma unroll
        for (int kc = 0; kc < KC; kc++) {
            uint32_t b0, b1, l0, l1;
            ldm_x2(b0, b1, wH + ro + kc * 32);
            ldm_x2(l0, l1, wL + ro + kc * 32);
            mma_bf16(c1a, Ah0[kc], b0, b1);
            mma_bf16(c1b, Ah1[kc], b0, b1);
            mma_bf16(c2a, Ah0[kc], l0, l1);
            mma_bf16(c2b, Ah1[kc], l0, l1);
            mma_bf16(c2a, Al0[kc], b0, b1);
            mma_bf16(c2b, Al1[kc], b0, b1);
        }
        float2 bb = *reinterpret_cast<const float2*>(bias + nt * 8 + t4 * 2);
        float v0a = fmaxf(c1a[0] + c2a[0] + bb.x, 0.f), v2a = fmaxf(c1a[2] + c2a[2] + bb.x, 0.f);
        float v1a = fmaxf(c1a[1] + c2a[1] + bb.y, 0.f), v3a = fmaxf(c1a[3] + c2a[3] + bb.y, 0.f);
        float v0b = fmaxf(c1b[0] + c2b[0] + bb.x, 0.f), v2b = fmaxf(c1b[2] + c2b[2] + bb.x, 0.f);
        float v1b = fmaxf(c1b[1] + c2b[1] + bb.y, 0.f), v3b = fmaxf(c1b[3] + c2b[3] + bb.y, 0.f);
        float m0 = fmaxf(fmaxf(v0a, v2a), fmaxf(v0b, v2b));
        float m1 = fmaxf(fmaxf(v1a, v3a), fmaxf(v1b, v3b));
#pragma unroll
        for (int off = 4; off < 32; off <<= 1) {
            m0 = fmaxf(m0, __shfl_xor_sync(0xffffffffu, m0, off));
            m1 = fmaxf(m1, __shfl_xor_sync(0xffffffffu, m1, off));
        }
        if (lane < 4) {
            atomicMax(&smax[nt * 8 + 2 * lane], __float_as_int(m0));
            atomicMax(&smax[nt * 8 + 2 * lane + 1], __float_as_int(m1));
        }
    }
}

__global__ void __launch_bounds__(256, 1) mlp_mma_kernel(
    const float* __restrict__ mw0, const float* __restrict__ mb0,
    const float* __restrict__ mw1, const float* __restrict__ mb1,
    const float* __restrict__ mw2, const float* __restrict__ mb2,
    const float* __restrict__ mw3, const float* __restrict__ mb3,
    const float* __restrict__ mw4, const float* __restrict__ mb4) {
    extern __shared__ char sm[];
    __shared__ int smax[128];
    int bp = blockIdx.x;
    int tid = threadIdx.x;
    int lane = tid & 31;
    int w = tid >> 5;
    uint32_t sbase = smem_to_u32(sm);

    if (tid < 128) smax[tid] = 0;
    for (int i = tid; i < 6144 / 4; i += 256) ((uint32_t*)sm)[i] = 0;
    __syncthreads();

    stage_w<3, 64, 48>(mw0, sm + O_W1H, sm + O_W1L, tid);
    stage_w<64, 64, 144>(mw1, sm + O_W2H, sm + O_W2L, tid);
    stage_w<64, 64, 144>(mw2, sm + O_W3H, sm + O_W3L, tid);
    stage_w<64, 128, 144>(mw3, sm + O_W4H, sm + O_W4L, tid);
    stage_w<128, 128, 272>(mw4, sm + O_W5H, sm + O_W5L, tid);
    float* sbias = (float*)(sm + O_BIAS);
    for (int i = tid; i < 64; i += 256) {
        sbias[i] = mb0[i]; sbias[64 + i] = mb1[i]; sbias[128 + i] = mb2[i];
    }
    for (int i = tid; i < 128; i += 256) {
        sbias[192 + i] = mb3[i]; sbias[320 + i] = mb4[i];
    }
    __syncthreads();

    const float* PX = &g_patch[(bp * 3 + 0) * SS];
    const float* PY = &g_patch[(bp * 3 + 1) * SS];
    const float* PZ = &g_patch[(bp * 3 + 2) * SS];
    int t4 = lane & 3;

    for (int it = 0; it < 4; it++) {
        // warp handles 32 points: tile0 = base..base+15, tile1 = base+16..base+31
        int pbase = it * 256 + w * 32 + (lane >> 2);
        float x0 = PX[pbase], y0 = PY[pbase], z0 = PZ[pbase];
        float x1 = PX[pbase + 8], y1 = PY[pbase + 8], z1 = PZ[pbase + 8];
        float x2 = PX[pbase + 16], y2 = PY[pbase + 16], z2 = PZ[pbase + 16];
        float x3 = PX[pbase + 24], y3 = PY[pbase + 24], z3 = PZ[pbase + 24];

        uint32_t A1h0[1][4] = {{0u, 0u, 0u, 0u}}, A1l0[1][4] = {{0u, 0u, 0u, 0u}};
        uint32_t A1h1[1][4] = {{0u, 0u, 0u, 0u}}, A1l1[1][4] = {{0u, 0u, 0u, 0u}};
        if (t4 == 0) {
            split2(x0, y0, A1h0[0][0], A1l0[0][0]);
            split2(x1, y1, A1h0[0][1], A1l0[0][1]);
            split2(x2, y2, A1h1[0][0], A1l1[0][0]);
            split2(x3, y3, A1h1[0][1], A1l1[0][1]);
        } else if (t4 == 1) {
            split2(z0, 0.f, A1h0[0][0], A1l0[0][0]);
            split2(z1, 0.f, A1h0[0][1], A1l0[0][1]);
            split2(z2, 0.f, A1h1[0][0], A1l1[0][0]);
            split2(z3, 0.f, A1h1[0][1], A1l1[0][1]);
        }

        uint32_t A2h0[4][4], A2l0[4][4], A2h1[4][4], A2l1[4][4];
        uint32_t A3h0[4][4], A3l0[4][4], A3h1[4][4], A3l1[4][4];
        uint32_t A4h0[4][4], A4l0[4][4], A4h1[4][4], A4l1[4][4];
        uint32_t A5h0[8][4], A5l0[8][4], A5h1[8][4], A5l1[8][4];

        layer_forward2<1, 8, 48>(A1h0, A1l0, A1h1, A1l1,
            sbase + O_W1H, sbase + O_W1L, sbias + 0, lane,
            A2h0, A2l0, A2h1, A2l1);
        layer_forward2<4, 8, 144>(A2h0, A2l0, A2h1, A2l1,
            sbase + O_W2H, sbase + O_W2L, sbias + 64, lane,
            A3h0, A3l0, A3h1, A3l1);
        layer_forward2<4, 8, 144>(A3h0, A3l0, A3h1, A3l1,
            sbase + O_W3H, sbase + O_W3L, sbias + 128, lane,
            A4h0, A4l0, A4h1, A4l1);
        layer_forward2<4, 16, 144>(A4h0, A4l0, A4h1, A4l1,
            sbase + O_W4H, sbase + O_W4L, sbias + 192, lane,
            A5h0, A5l0, A5h1, A5l1);
        layer_final2<8, 16, 272>(A5h0, A5l0, A5h1, A5l1,
            sbase + O_W5H, sbase + O_W5L, sbias + 320, lane, smax);
    }
    __syncthreads();
    if (tid < 128) g_feat[bp * 128 + tid] = __int_as_float(smax[tid]);
}

// =========================================================================
// Kernel 4: FC decoder, one block per BATCH (8 patches share weight reads).
// grid=64, block=256; thread = output channel, loops 8 patches per weight.
// =========================================================================
__global__ void __launch_bounds__(256) dec_kernel(
    const float* __restrict__ fw0, const float* __restrict__ fb0,
    const float* __restrict__ fw1, const float* __restrict__ fb1,
    const float* __restrict__ fw2, const float* __restrict__ fb2,
    const float* __restrict__ fw3, const float* __restrict__ fb3) {
    int b = blockIdx.x;
    int tid = threadIdx.x;
    __shared__ float sA[8][256];
    __shared__ float sB[8][256];

    for (int i = tid; i < 8 * 128; i += 256) {
        int p = i >> 7, c = i & 127;
        sA[p][c] = g_feat[(b * 8 + p) * 128 + c];
    }
    __syncthreads();

    // L1: 128 -> 256
    {
        float acc[8];
#pragma unroll
        for (int p = 0; p < 8; p++) acc[p] = 0.f;
#pragma unroll 4
        for (int i = 0; i < 128; i++) {
            float wv = fw0[i * 256 + tid];
#pragma unroll
            for (int p = 0; p < 8; p++) acc[p] = fmaf(sA[p][i], wv, acc[p]);
        }
        float bv = fb0[tid];
#pragma unroll
        for (int p = 0; p < 8; p++) sB[p][tid] = fmaxf(acc[p] + bv, 0.f);
    }
    __syncthreads();
    // L2: 256 -> 256
    {
        float acc[8];
#pragma unroll
        for (int p = 0; p < 8; p++) acc[p] = 0.f;
#pragma unroll 4
        for (int i = 0; i < 256; i++) {
            float wv = fw1[i * 256 + tid];
#pragma unroll
            for (int p = 0; p < 8; p++) acc[p] = fmaf(sB[p][i], wv, acc[p]);
        }
        float bv = fb1[tid];
#pragma unroll
        for (int p = 0; p < 8; p++) sA[p][tid] = fmaxf(acc[p] + bv, 0.f);
    }
    __syncthreads();
    // L3: 256 -> 256
    {
        float acc[8];
#pragma unroll
        for (int p = 0; p < 8; p++) acc[p] = 0.f;
#pragma unroll 4
        for (int i = 0; i < 256; i++) {
            float wv = fw2[i * 256 + tid];
#pragma unroll
            for (int p = 0; p < 8; p++) acc[p] = fmaf(sA[p][i], wv, acc[p]);
        }
        float bv = fb2[tid];
#pragma unroll
        for (int p = 0; p < 8; p++) sB[p][tid] = fmaxf(acc[p] + bv, 0.f);
    }
    __syncthreads();
    // L4: 256 -> 24 (no relu); tid<192: p=tid/24, out=tid%24
    if (tid < 192) {
        int p = tid / 24, o = tid - p * 24;
        float p0 = 0.f, p1 = 0.f, p2 = 0.f, p3 = 0.f;
#pragma unroll 8
        for (int i = 0; i < 256; i += 4) {
            p0 = fmaf(sB[p][i], fw3[i * 24 + o], p0);
            p1 = fmaf(sB[p][i + 1], fw3[(i + 1) * 24 + o], p1);
            p2 = fmaf(sB[p][i + 2], fw3[(i + 2) * 24 + o], p2);
            p3 = fmaf(sB[p][i + 3], fw3[(i + 3) * 24 + o], p3);
        }
        g_gen[(b * 8 + p) * 24 + o] = fb3[o] + ((p0 + p1) + (p2 + p3));
    }
}

// =========================================================================
// Kernel 5: SoftProjection (proven correct)
// =========================================================================
__global__ void proj_kernel(const float* __restrict__ temperature,
                            float* __restrict__ out) {
    int bp = blockIdx.x;
    int tid = threadIdx.x;
    int m = tid >> 5;
    int lane = tid & 31;
    float t = temperature[0];
    float sigma = fmaxf(t * t, 1e-4f);

    const float* PX = &g_patch[(bp * 3 + 0) * SS];
    const float* PY = &g_patch[(bp * 3 + 1) * SS];
    const float* PZ = &g_patch[(bp * 3 + 2) * SS];

    float qx = g_gen[bp * 24 + m * 3 + 0];
    float qy = g_gen[bp * 24 + m * 3 + 1];
    float qz = g_gen[bp * 24 + m * 3 + 2];
    float q2 = qx * qx + qy * qy + qz * qz;

    float bd[7]; int bi[7];
#pragma unroll
    for (int k = 0; k < 7; k++) { bd[k] = 3.4e38f; bi[k] = 0; }

    for (int i = lane; i < SS; i += 32) {
        float px = PX[i], py = PY[i], pz = PZ[i];
        float p2 = px * px + py * py + pz * pz;
        float dot = qx * px + qy * py + qz * pz;
        float d = (q2 - 2.0f * dot) + p2;
        if (d < bd[6]) {
            bd[6] = d; bi[6] = i;
#pragma unroll
            for (int k = 6; k > 0; k--) {
                if (bd[k] < bd[k - 1]) {
                    float td = bd[k]; bd[k] = bd[k - 1]; bd[k - 1] = td;
                    int ti = bi[k]; bi[k] = bi[k - 1]; bi[k - 1] = ti;
                }
            }
        }
    }
    float selD[7]; int selI[7];
#pragma unroll
    for (int k = 0; k < 7; k++) {
        float mv = bd[0]; int ml = lane;
#pragma unroll
        for (int o = 16; o > 0; o >>= 1) {
            float ov = __shfl_xor_sync(0xffffffffu, mv, o);
            int ol = __shfl_xor_sync(0xffffffffu, ml, o);
            if (ov < mv || (ov == mv && ol < ml)) { mv = ov; ml = ol; }
        }
        selD[k] = mv;
        selI[k] = __shfl_sync(0xffffffffu, bi[0], ml);
        if (lane == ml) {
#pragma unroll
            for (int q = 0; q < 6; q++) { bd[q] = bd[q + 1]; bi[q] = bi[q + 1]; }
            bd[6] = 3.4e38f;
        }
    }
    if (lane == 0) {
        float wsum = 0.f, sx = 0.f, sy = 0.f, sz = 0.f;
#pragma unroll
        for (int k = 0; k < 7; k++) {
            float w = expf((selD[0] - selD[k]) / sigma);
            int i = selI[k];
            wsum += w;
            sx = fmaf(w, PX[i], sx);
            sy = fmaf(w, PY[i], sy);
            sz = fmaf(w, PZ[i], sz);
        }
        float inv = 1.0f / wsum;
        float nrm = g_norm[bp];
        float mex = g_mean[bp * 3 + 0], mey = g_mean[bp * 3 + 1], mez = g_mean[bp * 3 + 2];
        int o = (bp * MM + m) * 3;
        out[o + 0] = fmaf(sx * inv, nrm, mex);
        out[o + 1] = fmaf(sy * inv, nrm, mey);
        out[o + 2] = fmaf(sz * inv, nrm, mez);
    }
}

// =========================================================================
extern "C" void kernel_launch(void* const* d_in, const int* in_sizes, int n_in,
                              void* d_out, int out_size) {
    const float* xyz = (const float*)d_in[0];
    const float* mw0 = (const float*)d_in[1];  const float* mb0 = (const float*)d_in[2];
    const float* mw1 = (const float*)d_in[3];  const float* mb1 = (const float*)d_in[4];
    const float* mw2 = (const float*)d_in[5];  const float* mb2 = (const float*)d_in[6];
    const float* mw3 = (const float*)d_in[7];  const float* mb3 = (const float*)d_in[8];
    const float* mw4 = (const float*)d_in[9];  const float* mb4 = (const float*)d_in[10];
    const float* fw0 = (const float*)d_in[11]; const float* fb0 = (const float*)d_in[12];
    const float* fw1 = (const float*)d_in[13]; const float* fb1 = (const float*)d_in[14];
    const float* fw2 = (const float*)d_in[15]; const float* fb2 = (const float*)d_in[16];
    const float* fw3 = (const float*)d_in[17]; const float* fb3 = (const float*)d_in[18];
    const float* temp = (const float*)d_in[19];
    float* out = (float*)d_out;

    cudaFuncSetAttribute(mlp_mma_kernel, cudaFuncAttributeMaxDynamicSharedMemorySize,
                         DYN_TOT);

    fps_kernel<<<BB, 1024>>>(xyz);
    knn_kernel<<<NPATCH, 256>>>(xyz);
    mlp_mma_kernel<<<NPATCH, 256, DYN_TOT>>>(
        mw0, mb0, mw1, mb1, mw2, mb2, mw3, mb3, mw4, mb4);
    dec_kernel<<<64, 256>>>(fw0, fb0, fw1, fb1, fw2, fb2, fw3, fb3);
    proj_kernel<<<NPATCH, 256>>>(temp, out);
}

// round 6
// speedup vs baseline: 4.2520x; 1.1744x over previous
#include <cuda_runtime.h>
#include <cuda_bf16.h>
#include <cstdint>

// ---------------- problem constants ----------------
#define BB 64
#define NN 8192
#define PP 8
#define SS 1024
#define MM 8
#define KK 7
#define NPATCH (BB*PP)   // 512

// ---------------- device scratch (no allocations allowed) ----------------
__device__ float g_seed[NPATCH * 3];
__device__ float g_patch[NPATCH * 3 * SS];      // normalized patch coords, SoA [bp][c][s]
__device__ float g_mean[NPATCH * 3];
__device__ float g_norm[NPATCH];
__device__ float g_feat[NPATCH * 128];
__device__ float g_gen[NPATCH * 24];

// =========================================================================
// helpers
// =========================================================================
__device__ __forceinline__ uint32_t smem_to_u32(const void* smem_ptr) {
    uint32_t addr;
    asm("{ .reg .u64 tmp; cvta.to.shared.u64 tmp, %1; cvt.u32.u64 %0, tmp; }"
        : "=r"(addr) : "l"(smem_ptr));
    return addr;
}

__device__ __forceinline__ void mma_bf16(float* c, const uint32_t* a, uint32_t b0, uint32_t b1) {
    asm volatile(
        "mma.sync.aligned.m16n8k16.row.col.f32.bf16.bf16.f32 "
        "{%0,%1,%2,%3}, {%4,%5,%6,%7}, {%8,%9}, {%0,%1,%2,%3};"
        : "+f"(c[0]), "+f"(c[1]), "+f"(c[2]), "+f"(c[3])
        : "r"(a[0]), "r"(a[1]), "r"(a[2]), "r"(a[3]), "r"(b0), "r"(b1));
}

__device__ __forceinline__ void ldm_x2(uint32_t& r0, uint32_t& r1, uint32_t addr) {
    asm volatile("ldmatrix.sync.aligned.m8n8.x2.shared.b16 {%0,%1}, [%2];"
                 : "=r"(r0), "=r"(r1) : "r"(addr));
}

__device__ __forceinline__ uint32_t pack_bf16x2(__nv_bfloat16 lo16, __nv_bfloat16 hi16) {
    return ((uint32_t)__bfloat16_as_ushort(hi16) << 16) | (uint32_t)__bfloat16_as_ushort(lo16);
}

// split (f0 -> low half, f1 -> high half) into hi/lo bf16x2 words.
// Packed cvt.rn.bf16x2 (RN, same rounding as __float2bfloat16), ~6 instrs.
__device__ __forceinline__ void split2(float f0, float f1, uint32_t& hi, uint32_t& lo) {
    uint32_t h, l;
    asm("cvt.rn.bf16x2.f32 %0, %1, %2;" : "=r"(h) : "f"(f1), "f"(f0));
    float r1 = __uint_as_float(h & 0xFFFF0000u);
    float r0 = __uint_as_float(h << 16);
    float d1 = f1 - r1;
    float d0 = f0 - r0;
    asm("cvt.rn.bf16x2.f32 %0, %1, %2;" : "=r"(l) : "f"(d1), "f"(d0));
    hi = h; lo = l;
}

// =========================================================================
// Kernel 1: farthest point sampling (proven correct; matches jax semantics)
// =========================================================================
__global__ void fps_kernel(const float* __restrict__ xyz) {
    int b = blockIdx.x;
    const float* X = xyz + (size_t)b * 3 * NN;
    __shared__ float s_v[32];
    __shared__ int   s_i[32];
    __shared__ float s_c[3];
    __shared__ int   s_far;
    int tid = threadIdx.x;
    int lane = tid & 31;
    int wrp = tid >> 5;

    float dist[8];
#pragma unroll
    for (int k = 0; k < 8; k++) dist[k] = 1e10f;
    int far = 0;

    for (int it = 0; it < PP; it++) {
        if (tid == 0) {
            float fx = X[far], fy = X[NN + far], fz = X[2 * NN + far];
            s_c[0] = fx; s_c[1] = fy; s_c[2] = fz;
            g_seed[(b * PP + it) * 3 + 0] = fx;
            g_seed[(b * PP + it) * 3 + 1] = fy;
            g_seed[(b * PP + it) * 3 + 2] = fz;
        }
        __syncthreads();
        float cx = s_c[0], cy = s_c[1], cz = s_c[2];
        float bv = -1.0f; int bi = 0;
#pragma unroll
        for (int k = 0; k < 8; k++) {
            int i = tid + k * 1024;
            float dx = X[i] - cx, dy = X[NN + i] - cy, dz = X[2 * NN + i] - cz;
            float d = dx * dx + dy * dy + dz * dz;
            float nd = fminf(dist[k], d);
            dist[k] = nd;
            if (nd > bv || (nd == bv && i < bi)) { bv = nd; bi = i; }
        }
#pragma unroll
        for (int o = 16; o > 0; o >>= 1) {
            float ov = __shfl_xor_sync(0xffffffffu, bv, o);
            int oi = __shfl_xor_sync(0xffffffffu, bi, o);
            if (ov > bv || (ov == bv && oi < bi)) { bv = ov; bi = oi; }
        }
        if (lane == 0) { s_v[wrp] = bv; s_i[wrp] = bi; }
        __syncthreads();
        if (wrp == 0) {
            float mv = s_v[lane]; int mi = s_i[lane];
#pragma unroll
            for (int o = 16; o > 0; o >>= 1) {
                float ov = __shfl_xor_sync(0xffffffffu, mv, o);
                int oi = __shfl_xor_sync(0xffffffffu, mi, o);
                if (ov > mv || (ov == mv && oi < mi)) { mv = ov; mi = oi; }
            }
            if (lane == 0) s_far = mi;
        }
        __syncthreads();
        far = s_far;
        __syncthreads();
    }
}

// =========================================================================
// Kernel 2: KNN radix-select + patch normalization. 512 threads now.
// =========================================================================
__global__ void __launch_bounds__(512) knn_kernel(const float* __restrict__ xyz) {
    int bp = blockIdx.x;
    int b = bp >> 3;
    const float* X = xyz + (size_t)b * 3 * NN;
    __shared__ unsigned s_key[NN];
    __shared__ int s_sel[SS];
    __shared__ int s_hist[256];
    __shared__ unsigned s_pref;
    __shared__ int s_kk;
    __shared__ int s_cnt[2];
    __shared__ float s_red[512];
    int tid = threadIdx.x;

    float sx = g_seed[bp * 3 + 0], sy = g_seed[bp * 3 + 1], sz = g_seed[bp * 3 + 2];
    float s2 = sx * sx + sy * sy + sz * sz;

    for (int i = tid; i < NN; i += 512) {
        float px = X[i], py = X[NN + i], pz = X[2 * NN + i];
        float p2 = px * px + py * py + pz * pz;
        float dot = sx * px + sy * py + sz * pz;
        float d = (s2 - 2.0f * dot) + p2;
        unsigned u = __float_as_uint(d);
        u = (u & 0x80000000u) ? ~u : (u | 0x80000000u);
        s_key[i] = u;
    }
    __syncthreads();

    unsigned prefix = 0, maskHi = 0;
    int kk = SS;
    for (int pass = 0; pass < 4; pass++) {
        int shift = 24 - 8 * pass;
        if (tid < 256) s_hist[tid] = 0;
        __syncthreads();
        for (int i = tid; i < NN; i += 512) {
            unsigned u = s_key[i];
            if ((u & maskHi) == prefix) atomicAdd(&s_hist[(u >> shift) & 255], 1);
        }
        __syncthreads();
        if (tid == 0) {
            int cum = 0, bsel = 0;
            for (bsel = 0; bsel < 256; bsel++) {
                int c = s_hist[bsel];
                if (cum + c >= kk) break;
                cum += c;
            }
            s_pref = prefix | ((unsigned)bsel << shift);
            s_kk = kk - cum;
        }
        __syncthreads();
        prefix = s_pref; kk = s_kk;
        maskHi |= (0xFFu << shift);
        __syncthreads();
    }
    unsigned T = prefix;

    if (tid == 0) { s_cnt[0] = 0; s_cnt[1] = 0; }
    __syncthreads();
    for (int i = tid; i < NN; i += 512) {
        if (s_key[i] < T) { int pos = atomicAdd(&s_cnt[0], 1); s_sel[pos] = i; }
    }
    __syncthreads();
    int nLess = s_cnt[0];
    for (int i = tid; i < NN; i += 512) {
        if (s_key[i] == T) {
            int pos = atomicAdd(&s_cnt[1], 1);
            if (nLess + pos < SS) s_sel[nLess + pos] = i;
        }
    }
    __syncthreads();

    float* cxs = (float*)s_key;
    float* cys = cxs + SS;
    float* czs = cxs + 2 * SS;
    float ax = 0.f, ay = 0.f, az = 0.f;
    for (int j = tid; j < SS; j += 512) {
        int i = s_sel[j];
        float px = X[i], py = X[NN + i], pz = X[2 * NN + i];
        cxs[j] = px; cys[j] = py; czs[j] = pz;
        ax += px; ay += py; az += pz;
    }
    s_red[tid] = ax; __syncthreads();
    for (int s = 256; s > 0; s >>= 1) { if (tid < s) s_red[tid] += s_red[tid + s]; __syncthreads(); }
    float mx = s_red[0] * (1.0f / SS); __syncthreads();
    s_red[tid] = ay; __syncthreads();
    for (int s = 256; s > 0; s >>= 1) { if (tid < s) s_red[tid] += s_red[tid + s]; __syncthreads(); }
    float my = s_red[0] * (1.0f / SS); __syncthreads();
    s_red[tid] = az; __syncthreads();
    for (int s = 256; s > 0; s >>= 1) { if (tid < s) s_red[tid] += s_red[tid + s]; __syncthreads(); }
    float mz = s_red[0] * (1.0f / SS); __syncthreads();

    float mnorm = 0.f;
    for (int j = tid; j < SS; j += 512) {
        float dx = cxs[j] - mx, dy = cys[j] - my, dz = czs[j] - mz;
        float l = sqrtf(dx * dx + dy * dy + dz * dz);
        mnorm = fmaxf(mnorm, l);
    }
    s_red[tid] = mnorm; __syncthreads();
    for (int s = 256; s > 0; s >>= 1) { if (tid < s) s_red[tid] = fmaxf(s_red[tid], s_red[tid + s]); __syncthreads(); }
    float nrm = s_red[0]; __syncthreads();

    for (int j = tid; j < SS; j += 512) {
        g_patch[(bp * 3 + 0) * SS + j] = (cxs[j] - mx) / nrm;
        g_patch[(bp * 3 + 1) * SS + j] = (cys[j] - my) / nrm;
        g_patch[(bp * 3 + 2) * SS + j] = (czs[j] - mz) / nrm;
    }
    if (tid == 0) {
        g_mean[bp * 3 + 0] = mx; g_mean[bp * 3 + 1] = my; g_mean[bp * 3 + 2] = mz;
        g_norm[bp] = nrm;
    }
}

// =========================================================================
// Kernel 3: fused MLP via mma.sync bf16 split-bf16 (3-term, fp32-class).
// Block = 1 patch, 8 warps; each warp: 2 M-tiles (32 points) per iter, 4 iters.
// =========================================================================
#define O_W1H 0
#define O_W1L 3072
#define O_W2H 6144
#define O_W2L 15360
#define O_W3H 24576
#define O_W3L 33792
#define O_W4H 43008
#define O_W4L 61440
#define O_W5H 79872
#define O_W5L 114688
#define O_BIAS 149504        // 448 floats: b1@0 b2@64 b3@128 b4@192 b5@320
#define DYN_TOT 151296

template<int K, int N, int STRIDE>
__device__ __forceinline__ void stage_w(const float* __restrict__ w,
                                        char* hi, char* lo, int tid) {
    for (int i = tid; i < K * N; i += 256) {
        int k = i / N, n = i - k * N;
        float f = w[i];
        __nv_bfloat16 h = __float2bfloat16(f);
        __nv_bfloat16 l = __float2bfloat16(f - __bfloat162float(h));
        int off = n * STRIDE + k * 2;
        *(__nv_bfloat16*)(hi + off) = h;
        *(__nv_bfloat16*)(lo + off) = l;
    }
}

// hidden layer for TWO M-tiles sharing B fragments.
template<int KC, int NT, int STRIDE>
__device__ __forceinline__ void layer_forward2(
    const uint32_t (*Ah0)[4], const uint32_t (*Al0)[4],
    const uint32_t (*Ah1)[4], const uint32_t (*Al1)[4],
    uint32_t wH, uint32_t wL, const float* __restrict__ bias, int lane,
    uint32_t (*Oh0)[4], uint32_t (*Ol0)[4],
    uint32_t (*Oh1)[4], uint32_t (*Ol1)[4]) {
    uint32_t lm = (uint32_t)(lane & 7) * STRIDE + (uint32_t)((lane >> 3) & 1) * 16;
    int t4 = lane & 3;
#pragma unroll
    for (int np = 0; np < NT / 2; np++) {
        float ccA[2][4], ccB[2][4];
#pragma unroll
        for (int sub = 0; sub < 2; sub++) {
            int nt = np * 2 + sub;
            uint32_t ro = lm + (uint32_t)nt * 8u * STRIDE;
            float c1a[4] = {0.f, 0.f, 0.f, 0.f}, c2a[4] = {0.f, 0.f, 0.f, 0.f};
            float c1b[4] = {0.f, 0.f, 0.f, 0.f}, c2b[4] = {0.f, 0.f, 0.f, 0.f};
#pragma unroll
            for (int kc = 0; kc < KC; kc++) {
                uint32_t b0, b1, l0, l1;
                ldm_x2(b0, b1, wH + ro + kc * 32);
                ldm_x2(l0, l1, wL + ro + kc * 32);
                mma_bf16(c1a, Ah0[kc], b0, b1);
                mma_bf16(c1b, Ah1[kc], b0, b1);
                mma_bf16(c2a, Ah0[kc], l0, l1);
                mma_bf16(c2b, Ah1[kc], l0, l1);
                mma_bf16(c2a, Al0[kc], b0, b1);
                mma_bf16(c2b, Al1[kc], b0, b1);
            }
            float2 bb = *reinterpret_cast<const float2*>(bias + nt * 8 + t4 * 2);
            ccA[sub][0] = fmaxf(c1a[0] + c2a[0] + bb.x, 0.f);
            ccA[sub][1] = fmaxf(c1a[1] + c2a[1] + bb.y, 0.f);
            ccA[sub][2] = fmaxf(c1a[2] + c2a[2] + bb.x, 0.f);
            ccA[sub][3] = fmaxf(c1a[3] + c2a[3] + bb.y, 0.f);
            ccB[sub][0] = fmaxf(c1b[0] + c2b[0] + bb.x, 0.f);
            ccB[sub][1] = fmaxf(c1b[1] + c2b[1] + bb.y, 0.f);
            ccB[sub][2] = fmaxf(c1b[2] + c2b[2] + bb.x, 0.f);
            ccB[sub][3] = fmaxf(c1b[3] + c2b[3] + bb.y, 0.f);
        }
        split2(ccA[0][0], ccA[0][1], Oh0[np][0], Ol0[np][0]);
        split2(ccA[0][2], ccA[0][3], Oh0[np][1], Ol0[np][1]);
        split2(ccA[1][0], ccA[1][1], Oh0[np][2], Ol0[np][2]);
        split2(ccA[1][2], ccA[1][3], Oh0[np][3], Ol0[np][3]);
        split2(ccB[0][0], ccB[0][1], Oh1[np][0], Ol1[np][0]);
        split2(ccB[0][2], ccB[0][3], Oh1[np][1], Ol1[np][1]);
        split2(ccB[1][0], ccB[1][1], Oh1[np][2], Ol1[np][2]);
        split2(ccB[1][2], ccB[1][3], Oh1[np][3], Ol1[np][3]);
    }
}

// final layer for TWO M-tiles: maxpool over 32 rows -> shared atomicMax
template<int KC, int NT, int STRIDE>
__device__ __forceinline__ void layer_final2(
    const uint32_t (*Ah0)[4], const uint32_t (*Al0)[4],
    const uint32_t (*Ah1)[4], const uint32_t (*Al1)[4],
    uint32_t wH, uint32_t wL, const float* __restrict__ bias, int lane, int* smax) {
    uint32_t lm = (uint32_t)(lane & 7) * STRIDE + (uint32_t)((lane >> 3) & 1) * 16;
    int t4 = lane & 3;
#pragma unroll
    for (int nt = 0; nt < NT; nt++) {
        uint32_t ro = lm + (uint32_t)nt * 8u * STRIDE;
        float c1a[4] = {0.f, 0.f, 0.f, 0.f}, c2a[4] = {0.f, 0.f, 0.f, 0.f};
        float c1b[4] = {0.f, 0.f, 0.f, 0.f}, c2b[4] = {0.f, 0.f, 0.f, 0.f};
#pragma unroll
        for (int kc = 0; kc < KC; kc++) {
            uint32_t b0, b1, l0, l1;
            ldm_x2(b0, b1, wH + ro + kc * 32);
            ldm_x2(l0, l1, wL + ro + kc * 32);
            mma_bf16(c1a, Ah0[kc], b0, b1);
            mma_bf16(c1b, Ah1[kc], b0, b1);
            mma_bf16(c2a, Ah0[kc], l0, l1);
            mma_bf16(c2b, Ah1[kc], l0, l1);
            mma_bf16(c2a, Al0[kc], b0, b1);
            mma_bf16(c2b, Al1[kc], b0, b1);
        }
        float2 bb = *reinterpret_cast<const float2*>(bias + nt * 8 + t4 * 2);
        float v0a = fmaxf(c1a[0] + c2a[0] + bb.x, 0.f), v2a = fmaxf(c1a[2] + c2a[2] + bb.x, 0.f);
        float v1a = fmaxf(c1a[1] + c2a[1] + bb.y, 0.f), v3a = fmaxf(c1a[3] + c2a[3] + bb.y, 0.f);
        float v0b = fmaxf(c1b[0] + c2b[0] + bb.x, 0.f), v2b = fmaxf(c1b[2] + c2b[2] + bb.x, 0.f);
        float v1b = fmaxf(c1b[1] + c2b[1] + bb.y, 0.f), v3b = fmaxf(c1b[3] + c2b[3] + bb.y, 0.f);
        float m0 = fmaxf(fmaxf(v0a, v2a), fmaxf(v0b, v2b));
        float m1 = fmaxf(fmaxf(v1a, v3a), fmaxf(v1b, v3b));
#pragma unroll
        for (int off = 4; off < 32; off <<= 1) {
            m0 = fmaxf(m0, __shfl_xor_sync(0xffffffffu, m0, off));
            m1 = fmaxf(m1, __shfl_xor_sync(0xffffffffu, m1, off));
        }
        if (lane < 4) {
            atomicMax(&smax[nt * 8 + 2 * lane], __float_as_int(m0));
            atomicMax(&smax[nt * 8 + 2 * lane + 1], __float_as_int(m1));
        }
    }
}

__global__ void __launch_bounds__(256, 1) mlp_mma_kernel(
    const float* __restrict__ mw0, const float* __restrict__ mb0,
    const float* __restrict__ mw1, const float* __restrict__ mb1,
    const float* __restrict__ mw2, const float* __restrict__ mb2,
    const float* __restrict__ mw3, const float* __restrict__ mb3,
    const float* __restrict__ mw4, const float* __restrict__ mb4) {
    extern __shared__ char sm[];
    __shared__ int smax[128];
    int bp = blockIdx.x;
    int tid = threadIdx.x;
    int lane = tid & 31;
    int w = tid >> 5;
    uint32_t sbase = smem_to_u32(sm);

    if (tid < 128) smax[tid] = 0;
    for (int i = tid; i < 6144 / 4; i += 256) ((uint32_t*)sm)[i] = 0;
    __syncthreads();

    stage_w<3, 64, 48>(mw0, sm + O_W1H, sm + O_W1L, tid);
    stage_w<64, 64, 144>(mw1, sm + O_W2H, sm + O_W2L, tid);
    stage_w<64, 64, 144>(mw2, sm + O_W3H, sm + O_W3L, tid);
    stage_w<64, 128, 144>(mw3, sm + O_W4H, sm + O_W4L, tid);
    stage_w<128, 128, 272>(mw4, sm + O_W5H, sm + O_W5L, tid);
    float* sbias = (float*)(sm + O_BIAS);
    for (int i = tid; i < 64; i += 256) {
        sbias[i] = mb0[i]; sbias[64 + i] = mb1[i]; sbias[128 + i] = mb2[i];
    }
    for (int i = tid; i < 128; i += 256) {
        sbias[192 + i] = mb3[i]; sbias[320 + i] = mb4[i];
    }
    __syncthreads();

    const float* PX = &g_patch[(bp * 3 + 0) * SS];
    const float* PY = &g_patch[(bp * 3 + 1) * SS];
    const float* PZ = &g_patch[(bp * 3 + 2) * SS];
    int t4 = lane & 3;

    for (int it = 0; it < 4; it++) {
        int pbase = it * 256 + w * 32 + (lane >> 2);
        float x0 = PX[pbase], y0 = PY[pbase], z0 = PZ[pbase];
        float x1 = PX[pbase + 8], y1 = PY[pbase + 8], z1 = PZ[pbase + 8];
        float x2 = PX[pbase + 16], y2 = PY[pbase + 16], z2 = PZ[pbase + 16];
        float x3 = PX[pbase + 24], y3 = PY[pbase + 24], z3 = PZ[pbase + 24];

        uint32_t A1h0[1][4] = {{0u, 0u, 0u, 0u}}, A1l0[1][4] = {{0u, 0u, 0u, 0u}};
        uint32_t A1h1[1][4] = {{0u, 0u, 0u, 0u}}, A1l1[1][4] = {{0u, 0u, 0u, 0u}};
        if (t4 == 0) {
            split2(x0, y0, A1h0[0][0], A1l0[0][0]);
            split2(x1, y1, A1h0[0][1], A1l0[0][1]);
            split2(x2, y2, A1h1[0][0], A1l1[0][0]);
            split2(x3, y3, A1h1[0][1], A1l1[0][1]);
        } else if (t4 == 1) {
            split2(z0, 0.f, A1h0[0][0], A1l0[0][0]);
            split2(z1, 0.f, A1h0[0][1], A1l0[0][1]);
            split2(z2, 0.f, A1h1[0][0], A1l1[0][0]);
            split2(z3, 0.f, A1h1[0][1], A1l1[0][1]);
        }

        uint32_t A2h0[4][4], A2l0[4][4], A2h1[4][4], A2l1[4][4];
        uint32_t A3h0[4][4], A3l0[4][4], A3h1[4][4], A3l1[4][4];
        uint32_t A4h0[4][4], A4l0[4][4], A4h1[4][4], A4l1[4][4];
        uint32_t A5h0[8][4], A5l0[8][4], A5h1[8][4], A5l1[8][4];

        layer_forward2<1, 8, 48>(A1h0, A1l0, A1h1, A1l1,
            sbase + O_W1H, sbase + O_W1L, sbias + 0, lane,
            A2h0, A2l0, A2h1, A2l1);
        layer_forward2<4, 8, 144>(A2h0, A2l0, A2h1, A2l1,
            sbase + O_W2H, sbase + O_W2L, sbias + 64, lane,
            A3h0, A3l0, A3h1, A3l1);
        layer_forward2<4, 8, 144>(A3h0, A3l0, A3h1, A3l1,
            sbase + O_W3H, sbase + O_W3L, sbias + 128, lane,
            A4h0, A4l0, A4h1, A4l1);
        layer_forward2<4, 16, 144>(A4h0, A4l0, A4h1, A4l1,
            sbase + O_W4H, sbase + O_W4L, sbias + 192, lane,
            A5h0, A5l0, A5h1, A5l1);
        layer_final2<8, 16, 272>(A5h0, A5l0, A5h1, A5l1,
            sbase + O_W5H, sbase + O_W5L, sbias + 320, lane, smax);
    }
    __syncthreads();
    if (tid < 128) g_feat[bp * 128 + tid] = __int_as_float(smax[tid]);
}

// =========================================================================
// Kernel 4: FC decoder. grid=128 (4 patches/block), 512 threads =
// (256 channels) x (2 K-halves). Halves combine through smem each layer.
// =========================================================================
__global__ void __launch_bounds__(512) dec_kernel(
    const float* __restrict__ fw0, const float* __restrict__ fb0,
    const float* __restrict__ fw1, const float* __restrict__ fb1,
    const float* __restrict__ fw2, const float* __restrict__ fb2,
    const float* __restrict__ fw3, const float* __restrict__ fb3) {
    int pbase = blockIdx.x * 4;
    int tid = threadIdx.x;
    int c = tid & 255;
    int h = tid >> 8;            // k-half
    __shared__ float sA[4][256];
    __shared__ float sB[4][256];
    __shared__ float sP[4][256];

    for (int i = tid; i < 4 * 128; i += 512) {
        int p = i >> 7, cc = i & 127;
        sA[p][cc] = g_feat[(pbase + p) * 128 + cc];
    }
    __syncthreads();

    // L1: 128 -> 256   (half K = 64)
    {
        float acc[4] = {0.f, 0.f, 0.f, 0.f};
        const float* W = fw0 + (h * 64) * 256 + c;
#pragma unroll 8
        for (int k = 0; k < 64; k++) {
            float wv = W[k * 256];
#pragma unroll
            for (int p = 0; p < 4; p++) acc[p] = fmaf(sA[p][h * 64 + k], wv, acc[p]);
        }
        if (h == 1) {
#pragma unroll
            for (int p = 0; p < 4; p++) sP[p][c] = acc[p];
        }
        __syncthreads();
        if (h == 0) {
            float bv = fb0[c];
#pragma unroll
            for (int p = 0; p < 4; p++) sB[p][c] = fmaxf(acc[p] + sP[p][c] + bv, 0.f);
        }
        __syncthreads();
    }
    // L2: 256 -> 256   (half K = 128), reads sB, writes sA
    {
        float acc[4] = {0.f, 0.f, 0.f, 0.f};
        const float* W = fw1 + (h * 128) * 256 + c;
#pragma unroll 8
        for (int k = 0; k < 128; k++) {
            float wv = W[k * 256];
#pragma unroll
            for (int p = 0; p < 4; p++) acc[p] = fmaf(sB[p][h * 128 + k], wv, acc[p]);
        }
        if (h == 1) {
#pragma unroll
            for (int p = 0; p < 4; p++) sP[p][c] = acc[p];
        }
        __syncthreads();
        if (h == 0) {
            float bv = fb1[c];
#pragma unroll
            for (int p = 0; p < 4; p++) sA[p][c] = fmaxf(acc[p] + sP[p][c] + bv, 0.f);
        }
        __syncthreads();
    }
    // L3: 256 -> 256, reads sA, writes sB
    {
        float acc[4] = {0.f, 0.f, 0.f, 0.f};
        const float* W = fw2 + (h * 128) * 256 + c;
#pragma unroll 8
        for (int k = 0; k < 128; k++) {
            float wv = W[k * 256];
#pragma unroll
            for (int p = 0; p < 4; p++) acc[p] = fmaf(sA[p][h * 128 + k], wv, acc[p]);
        }
        if (h == 1) {
#pragma unroll
            for (int p = 0; p < 4; p++) sP[p][c] = acc[p];
        }
        __syncthreads();
        if (h == 0) {
            float bv = fb2[c];
#pragma unroll
            for (int p = 0; p < 4; p++) sB[p][c] = fmaxf(acc[p] + sP[p][c] + bv, 0.f);
        }
        __syncthreads();
    }
    // L4: 256 -> 24 (no relu). 192 active threads: p = tid/48, o, half hh.
    {
        float acc = 0.f;
        int r = tid % 48;
        int p = tid / 48;
        int o = r % 24;
        int hh = r / 24;
        if (tid < 192) {
            const float* W = fw3 + (hh * 128) * 24 + o;
#pragma unroll 8
            for (int k = 0; k < 128; k++)
                acc = fmaf(sB[p][hh * 128 + k], W[k * 24], acc);
            if (hh == 1) sP[p][o] = acc;
        }
        __syncthreads();
        if (tid < 192 && hh == 0)
            g_gen[(pbase + p) * 24 + o] = acc + sP[p][o] + fb3[o];
    }
}

// =========================================================================
// Kernel 5: SoftProjection (proven correct)
// =========================================================================
__global__ void proj_kernel(const float* __restrict__ temperature,
                            float* __restrict__ out) {
    int bp = blockIdx.x;
    int tid = threadIdx.x;
    int m = tid >> 5;
    int lane = tid & 31;
    float t = temperature[0];
    float sigma = fmaxf(t * t, 1e-4f);

    const float* PX = &g_patch[(bp * 3 + 0) * SS];
    const float* PY = &g_patch[(bp * 3 + 1) * SS];
    const float* PZ = &g_patch[(bp * 3 + 2) * SS];

    float qx = g_gen[bp * 24 + m * 3 + 0];
    float qy = g_gen[bp * 24 + m * 3 + 1];
    float qz = g_gen[bp * 24 + m * 3 + 2];
    float q2 = qx * qx + qy * qy + qz * qz;

    float bd[7]; int bi[7];
#pragma unroll
    for (int k = 0; k < 7; k++) { bd[k] = 3.4e38f; bi[k] = 0; }

    for (int i = lane; i < SS; i += 32) {
        float px = PX[i], py = PY[i], pz = PZ[i];
        float p2 = px * px + py * py + pz * pz;
        float dot = qx * px + qy * py + qz * pz;
        float d = (q2 - 2.0f * dot) + p2;
        if (d < bd[6]) {
            bd[6] = d; bi[6] = i;
#pragma unroll
            for (int k = 6; k > 0; k--) {
                if (bd[k] < bd[k - 1]) {
                    float td = bd[k]; bd[k] = bd[k - 1]; bd[k - 1] = td;
                    int ti = bi[k]; bi[k] = bi[k - 1]; bi[k - 1] = ti;
                }
            }
        }
    }
    float selD[7]; int selI[7];
#pragma unroll
    for (int k = 0; k < 7; k++) {
        float mv = bd[0]; int ml = lane;
#pragma unroll
        for (int o = 16; o > 0; o >>= 1) {
            float ov = __shfl_xor_sync(0xffffffffu, mv, o);
            int ol = __shfl_xor_sync(0xffffffffu, ml, o);
            if (ov < mv || (ov == mv && ol < ml)) { mv = ov; ml = ol; }
        }
        selD[k] = mv;
        selI[k] = __shfl_sync(0xffffffffu, bi[0], ml);
        if (lane == ml) {
#pragma unroll
            for (int q = 0; q < 6; q++) { bd[q] = bd[q + 1]; bi[q] = bi[q + 1]; }
            bd[6] = 3.4e38f;
        }
    }
    if (lane == 0) {
        float wsum = 0.f, sx = 0.f, sy = 0.f, sz = 0.f;
#pragma unroll
        for (int k = 0; k < 7; k++) {
            float w = expf((selD[0] - selD[k]) / sigma);
            int i = selI[k];
            wsum += w;
            sx = fmaf(w, PX[i], sx);
            sy = fmaf(w, PY[i], sy);
            sz = fmaf(w, PZ[i], sz);
        }
        float inv = 1.0f / wsum;
        float nrm = g_norm[bp];
        float mex = g_mean[bp * 3 + 0], mey = g_mean[bp * 3 + 1], mez = g_mean[bp * 3 + 2];
        int o = (bp * MM + m) * 3;
        out[o + 0] = fmaf(sx * inv, nrm, mex);
        out[o + 1] = fmaf(sy * inv, nrm, mey);
        out[o + 2] = fmaf(sz * inv, nrm, mez);
    }
}

// =========================================================================
extern "C" void kernel_launch(void* const* d_in, const int* in_sizes, int n_in,
                              void* d_out, int out_size) {
    const float* xyz = (const float*)d_in[0];
    const float* mw0 = (const float*)d_in[1];  const float* mb0 = (const float*)d_in[2];
    const float* mw1 = (const float*)d_in[3];  const float* mb1 = (const float*)d_in[4];
    const float* mw2 = (const float*)d_in[5];  const float* mb2 = (const float*)d_in[6];
    const float* mw3 = (const float*)d_in[7];  const float* mb3 = (const float*)d_in[8];
    const float* mw4 = (const float*)d_in[9];  const float* mb4 = (const float*)d_in[10];
    const float* fw0 = (const float*)d_in[11]; const float* fb0 = (const float*)d_in[12];
    const float* fw1 = (const float*)d_in[13]; const float* fb1 = (const float*)d_in[14];
    const float* fw2 = (const float*)d_in[15]; const float* fb2 = (const float*)d_in[16];
    const float* fw3 = (const float*)d_in[17]; const float* fb3 = (const float*)d_in[18];
    const float* temp = (const float*)d_in[19];
    float* out = (float*)d_out;

    cudaFuncSetAttribute(mlp_mma_kernel, cudaFuncAttributeMaxDynamicSharedMemorySize,
                         DYN_TOT);

    fps_kernel<<<BB, 1024>>>(xyz);
    knn_kernel<<<NPATCH, 512>>>(xyz);
    mlp_mma_kernel<<<NPATCH, 256, DYN_TOT>>>(
        mw0, mb0, mw1, mb1, mw2, mb2, mw3, mb3, mw4, mb4);
    dec_kernel<<<128, 512>>>(fw0, fb0, fw1, fb1, fw2, fb2, fw3, fb3);
    proj_kernel<<<NPATCH, 256>>>(temp, out);
}

// round 7
// speedup vs baseline: 4.2887x; 1.0086x over previous
#include <cuda_runtime.h>
#include <cuda_bf16.h>
#include <cstdint>

// ---------------- problem constants ----------------
#define BB 64
#define NN 8192
#define PP 8
#define SS 1024
#define MM 8
#define KK 7
#define NPATCH (BB*PP)   // 512

// ---------------- device scratch (no allocations allowed) ----------------
__device__ float g_seed[NPATCH * 3];
__device__ float g_patch[NPATCH * 3 * SS];      // normalized patch coords, SoA [bp][c][s]
__device__ float g_mean[NPATCH * 3];
__device__ float g_norm[NPATCH];
__device__ float g_feat[NPATCH * 128];          // maxpool accumulator (atomicMax on bits)
__device__ float g_gen[NPATCH * 24];

// =========================================================================
// helpers
// =========================================================================
__device__ __forceinline__ uint32_t smem_to_u32(const void* smem_ptr) {
    uint32_t addr;
    asm("{ .reg .u64 tmp; cvta.to.shared.u64 tmp, %1; cvt.u32.u64 %0, tmp; }"
        : "=r"(addr) : "l"(smem_ptr));
    return addr;
}

__device__ __forceinline__ void mma_bf16(float* c, const uint32_t* a, uint32_t b0, uint32_t b1) {
    asm volatile(
        "mma.sync.aligned.m16n8k16.row.col.f32.bf16.bf16.f32 "
        "{%0,%1,%2,%3}, {%4,%5,%6,%7}, {%8,%9}, {%0,%1,%2,%3};"
        : "+f"(c[0]), "+f"(c[1]), "+f"(c[2]), "+f"(c[3])
        : "r"(a[0]), "r"(a[1]), "r"(a[2]), "r"(a[3]), "r"(b0), "r"(b1));
}

__device__ __forceinline__ void ldm_x2(uint32_t& r0, uint32_t& r1, uint32_t addr) {
    asm volatile("ldmatrix.sync.aligned.m8n8.x2.shared.b16 {%0,%1}, [%2];"
                 : "=r"(r0), "=r"(r1) : "r"(addr));
}

__device__ __forceinline__ uint32_t pack_bf16x2(__nv_bfloat16 lo16, __nv_bfloat16 hi16) {
    return ((uint32_t)__bfloat16_as_ushort(hi16) << 16) | (uint32_t)__bfloat16_as_ushort(lo16);
}

// split (f0 -> low half, f1 -> high half) into hi/lo bf16x2 words.
__device__ __forceinline__ void split2(float f0, float f1, uint32_t& hi, uint32_t& lo) {
    uint32_t h, l;
    asm("cvt.rn.bf16x2.f32 %0, %1, %2;" : "=r"(h) : "f"(f1), "f"(f0));
    float r1 = __uint_as_float(h & 0xFFFF0000u);
    float r0 = __uint_as_float(h << 16);
    float d1 = f1 - r1;
    float d0 = f0 - r0;
    asm("cvt.rn.bf16x2.f32 %0, %1, %2;" : "=r"(l) : "f"(d1), "f"(d0));
    hi = h; lo = l;
}

// =========================================================================
// Kernel 1: farthest point sampling (proven correct; matches jax semantics)
// =========================================================================
__global__ void fps_kernel(const float* __restrict__ xyz) {
    int b = blockIdx.x;
    const float* X = xyz + (size_t)b * 3 * NN;
    __shared__ float s_v[32];
    __shared__ int   s_i[32];
    __shared__ float s_c[3];
    __shared__ int   s_far;
    int tid = threadIdx.x;
    int lane = tid & 31;
    int wrp = tid >> 5;

    float dist[8];
#pragma unroll
    for (int k = 0; k < 8; k++) dist[k] = 1e10f;
    int far = 0;

    for (int it = 0; it < PP; it++) {
        if (tid == 0) {
            float fx = X[far], fy = X[NN + far], fz = X[2 * NN + far];
            s_c[0] = fx; s_c[1] = fy; s_c[2] = fz;
            g_seed[(b * PP + it) * 3 + 0] = fx;
            g_seed[(b * PP + it) * 3 + 1] = fy;
            g_seed[(b * PP + it) * 3 + 2] = fz;
        }
        __syncthreads();
        float cx = s_c[0], cy = s_c[1], cz = s_c[2];
        float bv = -1.0f; int bi = 0;
#pragma unroll
        for (int k = 0; k < 8; k++) {
            int i = tid + k * 1024;
            float dx = X[i] - cx, dy = X[NN + i] - cy, dz = X[2 * NN + i] - cz;
            float d = dx * dx + dy * dy + dz * dz;
            float nd = fminf(dist[k], d);
            dist[k] = nd;
            if (nd > bv || (nd == bv && i < bi)) { bv = nd; bi = i; }
        }
#pragma unroll
        for (int o = 16; o > 0; o >>= 1) {
            float ov = __shfl_xor_sync(0xffffffffu, bv, o);
            int oi = __shfl_xor_sync(0xffffffffu, bi, o);
            if (ov > bv || (ov == bv && oi < bi)) { bv = ov; bi = oi; }
        }
        if (lane == 0) { s_v[wrp] = bv; s_i[wrp] = bi; }
        __syncthreads();
        if (wrp == 0) {
            float mv = s_v[lane]; int mi = s_i[lane];
#pragma unroll
            for (int o = 16; o > 0; o >>= 1) {
                float ov = __shfl_xor_sync(0xffffffffu, mv, o);
                int oi = __shfl_xor_sync(0xffffffffu, mi, o);
                if (ov > mv || (ov == mv && oi < mi)) { mv = ov; mi = oi; }
            }
            if (lane == 0) s_far = mi;
        }
        __syncthreads();
        far = s_far;
        __syncthreads();
    }
}

// =========================================================================
// Kernel 2: KNN radix-select + patch normalization. 512 threads.
// Warp-parallel histogram scan; ballot-aggregated selection atomics;
// dual histogram banks. Also zero-inits g_feat for the MLP's atomicMax.
// =========================================================================
__global__ void __launch_bounds__(512) knn_kernel(const float* __restrict__ xyz) {
    int bp = blockIdx.x;
    int b = bp >> 3;
    const float* X = xyz + (size_t)b * 3 * NN;
    __shared__ unsigned s_key[NN];
    __shared__ int s_sel[SS];
    __shared__ int s_hist[512];        // two banks of 256
    __shared__ unsigned s_pref;
    __shared__ int s_kk;
    __shared__ int s_cnt[2];
    __shared__ float s_red[512];
    int tid = threadIdx.x;
    int lane = tid & 31;

    // zero maxpool accumulator for this patch (consumed by mlp via atomicMax)
    if (tid < 128) g_feat[bp * 128 + tid] = 0.f;

    float sx = g_seed[bp * 3 + 0], sy = g_seed[bp * 3 + 1], sz = g_seed[bp * 3 + 2];
    float s2 = sx * sx + sy * sy + sz * sz;

    for (int i = tid; i < NN; i += 512) {
        float px = X[i], py = X[NN + i], pz = X[2 * NN + i];
        float p2 = px * px + py * py + pz * pz;
        float dot = sx * px + sy * py + sz * pz;
        float d = (s2 - 2.0f * dot) + p2;
        unsigned u = __float_as_uint(d);
        u = (u & 0x80000000u) ? ~u : (u | 0x80000000u);
        s_key[i] = u;
    }
    if (tid == 0) { s_pref = 0u; s_kk = SS; }
    __syncthreads();

    unsigned prefix = 0, maskHi = 0;
    int bank = ((tid >> 5) & 1) * 256;
    for (int pass = 0; pass < 4; pass++) {
        int shift = 24 - 8 * pass;
        s_hist[tid] = 0;
        __syncthreads();
        for (int i = tid; i < NN; i += 512) {
            unsigned u = s_key[i];
            if ((u & maskHi) == prefix) atomicAdd(&s_hist[bank + ((u >> shift) & 255)], 1);
        }
        __syncthreads();
        if (tid < 32) {
            int kk = s_kk;
            unsigned pref = s_pref;
            int sv[8]; int tot = 0;
#pragma unroll
            for (int j = 0; j < 8; j++) {
                int v = s_hist[lane * 8 + j] + s_hist[256 + lane * 8 + j];
                sv[j] = v; tot += v;
            }
            int run = tot;
#pragma unroll
            for (int o = 1; o < 32; o <<= 1) {
                int v = __shfl_up_sync(0xffffffffu, run, o);
                if (lane >= o) run += v;
            }
            int excl = run - tot;
            if (kk > excl && kk <= run) {
                int cum = excl;
#pragma unroll
                for (int j = 0; j < 8; j++) {
                    if (cum + sv[j] >= kk) {
                        s_pref = pref | ((unsigned)(lane * 8 + j) << shift);
                        s_kk = kk - cum;
                        break;
                    }
                    cum += sv[j];
                }
            }
        }
        __syncthreads();
        prefix = s_pref;
        maskHi |= (0xFFu << shift);
        __syncthreads();
    }
    unsigned T = prefix;

    if (tid == 0) { s_cnt[0] = 0; s_cnt[1] = 0; }
    __syncthreads();
    // pass 1: strictly-less keys (ballot-aggregated)
    for (int i = tid; i < NN; i += 512) {
        bool pred = s_key[i] < T;
        unsigned m = __ballot_sync(0xffffffffu, pred);
        int cnt = __popc(m);
        int base = 0;
        if (lane == 0 && cnt) base = atomicAdd(&s_cnt[0], cnt);
        base = __shfl_sync(0xffffffffu, base, 0);
        if (pred) s_sel[base + __popc(m & ((1u << lane) - 1u))] = i;
    }
    __syncthreads();
    int nLess = s_cnt[0];
    // pass 2: equal keys fill the rest
    for (int i = tid; i < NN; i += 512) {
        bool pred = s_key[i] == T;
        unsigned m = __ballot_sync(0xffffffffu, pred);
        int cnt = __popc(m);
        int base = 0;
        if (lane == 0 && cnt) base = atomicAdd(&s_cnt[1], cnt);
        base = __shfl_sync(0xffffffffu, base, 0);
        if (pred) {
            int pos = nLess + base + __popc(m & ((1u << lane) - 1u));
            if (pos < SS) s_sel[pos] = i;
        }
    }
    __syncthreads();

    float* cxs = (float*)s_key;
    float* cys = cxs + SS;
    float* czs = cxs + 2 * SS;
    float ax = 0.f, ay = 0.f, az = 0.f;
    for (int j = tid; j < SS; j += 512) {
        int i = s_sel[j];
        float px = X[i], py = X[NN + i], pz = X[2 * NN + i];
        cxs[j] = px; cys[j] = py; czs[j] = pz;
        ax += px; ay += py; az += pz;
    }
    s_red[tid] = ax; __syncthreads();
    for (int s = 256; s > 0; s >>= 1) { if (tid < s) s_red[tid] += s_red[tid + s]; __syncthreads(); }
    float mx = s_red[0] * (1.0f / SS); __syncthreads();
    s_red[tid] = ay; __syncthreads();
    for (int s = 256; s > 0; s >>= 1) { if (tid < s) s_red[tid] += s_red[tid + s]; __syncthreads(); }
    float my = s_red[0] * (1.0f / SS); __syncthreads();
    s_red[tid] = az; __syncthreads();
    for (int s = 256; s > 0; s >>= 1) { if (tid < s) s_red[tid] += s_red[tid + s]; __syncthreads(); }
    float mz = s_red[0] * (1.0f / SS); __syncthreads();

    float mnorm = 0.f;
    for (int j = tid; j < SS; j += 512) {
        float dx = cxs[j] - mx, dy = cys[j] - my, dz = czs[j] - mz;
        float l = sqrtf(dx * dx + dy * dy + dz * dz);
        mnorm = fmaxf(mnorm, l);
    }
    s_red[tid] = mnorm; __syncthreads();
    for (int s = 256; s > 0; s >>= 1) { if (tid < s) s_red[tid] = fmaxf(s_red[tid], s_red[tid + s]); __syncthreads(); }
    float nrm = s_red[0]; __syncthreads();

    for (int j = tid; j < SS; j += 512) {
        g_patch[(bp * 3 + 0) * SS + j] = (cxs[j] - mx) / nrm;
        g_patch[(bp * 3 + 1) * SS + j] = (cys[j] - my) / nrm;
        g_patch[(bp * 3 + 2) * SS + j] = (czs[j] - mz) / nrm;
    }
    if (tid == 0) {
        g_mean[bp * 3 + 0] = mx; g_mean[bp * 3 + 1] = my; g_mean[bp * 3 + 2] = mz;
        g_norm[bp] = nrm;
    }
}

// =========================================================================
// Kernel 3: fused MLP via mma.sync bf16 split-bf16 (3-term, fp32-class).
// Grid = 2 blocks per patch (512 points each) to cut wave-quantization tail.
// Block: 8 warps, each warp 2 M-tiles (32 points)/iter, 2 iters.
// Maxpool: block-local smem max, then atomicMax into g_feat (zeroed by knn).
// =========================================================================
#define O_W1H 0
#define O_W1L 3072
#define O_W2H 6144
#define O_W2L 15360
#define O_W3H 24576
#define O_W3L 33792
#define O_W4H 43008
#define O_W4L 61440
#define O_W5H 79872
#define O_W5L 114688
#define O_BIAS 149504        // 448 floats: b1@0 b2@64 b3@128 b4@192 b5@320
#define DYN_TOT 151296

template<int K, int N, int STRIDE>
__device__ __forceinline__ void stage_w(const float* __restrict__ w,
                                        char* hi, char* lo, int tid) {
    for (int i = tid; i < K * N; i += 256) {
        int k = i / N, n = i - k * N;
        float f = w[i];
        __nv_bfloat16 h = __float2bfloat16(f);
        __nv_bfloat16 l = __float2bfloat16(f - __bfloat162float(h));
        int off = n * STRIDE + k * 2;
        *(__nv_bfloat16*)(hi + off) = h;
        *(__nv_bfloat16*)(lo + off) = l;
    }
}

// hidden layer for TWO M-tiles sharing B fragments.
template<int KC, int NT, int STRIDE>
__device__ __forceinline__ void layer_forward2(
    const uint32_t (*Ah0)[4], const uint32_t (*Al0)[4],
    const uint32_t (*Ah1)[4], const uint32_t (*Al1)[4],
    uint32_t wH, uint32_t wL, const float* __restrict__ bias, int lane,
    uint32_t (*Oh0)[4], uint32_t (*Ol0)[4],
    uint32_t (*Oh1)[4], uint32_t (*Ol1)[4]) {
    uint32_t lm = (uint32_t)(lane & 7) * STRIDE + (uint32_t)((lane >> 3) & 1) * 16;
    int t4 = lane & 3;
#pragma unroll
    for (int np = 0; np < NT / 2; np++) {
        float ccA[2][4], ccB[2][4];
#pragma unroll
        for (int sub = 0; sub < 2; sub++) {
            int nt = np * 2 + sub;
            uint32_t ro = lm + (uint32_t)nt * 8u * STRIDE;
            float c1a[4] = {0.f, 0.f, 0.f, 0.f}, c2a[4] = {0.f, 0.f, 0.f, 0.f};
            float c1b[4] = {0.f, 0.f, 0.f, 0.f}, c2b[4] = {0.f, 0.f, 0.f, 0.f};
#pragma unroll
            for (int kc = 0; kc < KC; kc++) {
                uint32_t b0, b1, l0, l1;
                ldm_x2(b0, b1, wH + ro + kc * 32);
                ldm_x2(l0, l1, wL + ro + kc * 32);
                mma_bf16(c1a, Ah0[kc], b0, b1);
                mma_bf16(c1b, Ah1[kc], b0, b1);
                mma_bf16(c2a, Ah0[kc], l0, l1);
                mma_bf16(c2b, Ah1[kc], l0, l1);
                mma_bf16(c2a, Al0[kc], b0, b1);
                mma_bf16(c2b, Al1[kc], b0, b1);
            }
            float2 bb = *reinterpret_cast<const float2*>(bias + nt * 8 + t4 * 2);
            ccA[sub][0] = fmaxf(c1a[0] + c2a[0] + bb.x, 0.f);
            ccA[sub][1] = fmaxf(c1a[1] + c2a[1] + bb.y, 0.f);
            ccA[sub][2] = fmaxf(c1a[2] + c2a[2] + bb.x, 0.f);
            ccA[sub][3] = fmaxf(c1a[3] + c2a[3] + bb.y, 0.f);
            ccB[sub][0] = fmaxf(c1b[0] + c2b[0] + bb.x, 0.f);
            ccB[sub][1] = fmaxf(c1b[1] + c2b[1] + bb.y, 0.f);
            ccB[sub][2] = fmaxf(c1b[2] + c2b[2] + bb.x, 0.f);
            ccB[sub][3] = fmaxf(c1b[3] + c2b[3] + bb.y, 0.f);
        }
        split2(ccA[0][0], ccA[0][1], Oh0[np][0], Ol0[np][0]);
        split2(ccA[0][2], ccA[0][3], Oh0[np][1], Ol0[np][1]);
        split2(ccA[1][0], ccA[1][1], Oh0[np][2], Ol0[np][2]);
        split2(ccA[1][2], ccA[1][3], Oh0[np][3], Ol0[np][3]);
        split2(ccB[0][0], ccB[0][1], Oh1[np][0], Ol1[np][0]);
        split2(ccB[0][2], ccB[0][3], Oh1[np][1], Ol1[np][1]);
        split2(ccB[1][0], ccB[1][1], Oh1[np][2], Ol1[np][2]);
        split2(ccB[1][2], ccB[1][3], Oh1[np][3], Ol1[np][3]);
    }
}

// final layer for TWO M-tiles: maxpool over 32 rows -> shared atomicMax
template<int KC, int NT, int STRIDE>
__device__ __forceinline__ void layer_final2(
    const uint32_t (*Ah0)[4], const uint32_t (*Al0)[4],
    const uint32_t (*Ah1)[4], const uint32_t (*Al1)[4],
    uint32_t wH, uint32_t wL, const float* __restrict__ bias, int lane, int* smax) {
    uint32_t lm = (uint32_t)(lane & 7) * STRIDE + (uint32_t)((lane >> 3) & 1) * 16;
    int t4 = lane & 3;
#pragma unroll
    for (int nt = 0; nt < NT; nt++) {
        uint32_t ro = lm + (uint32_t)nt * 8u * STRIDE;
        float c1a[4] = {0.f, 0.f, 0.f, 0.f}, c2a[4] = {0.f, 0.f, 0.f, 0.f};
        float c1b[4] = {0.f, 0.f, 0.f, 0.f}, c2b[4] = {0.f, 0.f, 0.f, 0.f};
#pragma unroll
        for (int kc = 0; kc < KC; kc++) {
            uint32_t b0, b1, l0, l1;
            ldm_x2(b0, b1, wH + ro + kc * 32);
            ldm_x2(l0, l1, wL + ro + kc * 32);
            mma_bf16(c1a, Ah0[kc], b0, b1);
            mma_bf16(c1b, Ah1[kc], b0, b1);
            mma_bf16(c2a, Ah0[kc], l0, l1);
            mma_bf16(c2b, Ah1[kc], l0, l1);
            mma_bf16(c2a, Al0[kc], b0, b1);
            mma_bf16(c2b, Al1[kc], b0, b1);
        }
        float2 bb = *reinterpret_cast<const float2*>(bias + nt * 8 + t4 * 2);
        float v0a = fmaxf(c1a[0] + c2a[0] + bb.x, 0.f), v2a = fmaxf(c1a[2] + c2a[2] + bb.x, 0.f);
        float v1a = fmaxf(c1a[1] + c2a[1] + bb.y, 0.f), v3a = fmaxf(c1a[3] + c2a[3] + bb.y, 0.f);
        float v0b = fmaxf(c1b[0] + c2b[0] + bb.x, 0.f), v2b = fmaxf(c1b[2] + c2b[2] + bb.x, 0.f);
        float v1b = fmaxf(c1b[1] + c2b[1] + bb.y, 0.f), v3b = fmaxf(c1b[3] + c2b[3] + bb.y, 0.f);
        float m0 = fmaxf(fmaxf(v0a, v2a), fmaxf(v0b, v2b));
        float m1 = fmaxf(fmaxf(v1a, v3a), fmaxf(v1b, v3b));
#pragma unroll
        for (int off = 4; off < 32; off <<= 1) {
            m0 = fmaxf(m0, __shfl_xor_sync(0xffffffffu, m0, off));
            m1 = fmaxf(m1, __shfl_xor_sync(0xffffffffu, m1, off));
        }
        if (lane < 4) {
            atomicMax(&smax[nt * 8 + 2 * lane], __float_as_int(m0));
            atomicMax(&smax[nt * 8 + 2 * lane + 1], __float_as_int(m1));
        }
    }
}

__global__ void __launch_bounds__(256, 1) mlp_mma_kernel(
    const float* __restrict__ mw0, const float* __restrict__ mb0,
    const float* __restrict__ mw1, const float* __restrict__ mb1,
    const float* __restrict__ mw2, const float* __restrict__ mb2,
    const float* __restrict__ mw3, const float* __restrict__ mb3,
    const float* __restrict__ mw4, const float* __restrict__ mb4) {
    extern __shared__ char sm[];
    __shared__ int smax[128];
    int bp2 = blockIdx.x;
    int bp = bp2 >> 1;
    int half = bp2 & 1;
    int tid = threadIdx.x;
    int lane = tid & 31;
    int w = tid >> 5;
    uint32_t sbase = smem_to_u32(sm);

    if (tid < 128) smax[tid] = 0;
    for (int i = tid; i < 6144 / 4; i += 256) ((uint32_t*)sm)[i] = 0;
    __syncthreads();

    stage_w<3, 64, 48>(mw0, sm + O_W1H, sm + O_W1L, tid);
    stage_w<64, 64, 144>(mw1, sm + O_W2H, sm + O_W2L, tid);
    stage_w<64, 64, 144>(mw2, sm + O_W3H, sm + O_W3L, tid);
    stage_w<64, 128, 144>(mw3, sm + O_W4H, sm + O_W4L, tid);
    stage_w<128, 128, 272>(mw4, sm + O_W5H, sm + O_W5L, tid);
    float* sbias = (float*)(sm + O_BIAS);
    for (int i = tid; i < 64; i += 256) {
        sbias[i] = mb0[i]; sbias[64 + i] = mb1[i]; sbias[128 + i] = mb2[i];
    }
    for (int i = tid; i < 128; i += 256) {
        sbias[192 + i] = mb3[i]; sbias[320 + i] = mb4[i];
    }
    __syncthreads();

    const float* PX = &g_patch[(bp * 3 + 0) * SS];
    const float* PY = &g_patch[(bp * 3 + 1) * SS];
    const float* PZ = &g_patch[(bp * 3 + 2) * SS];
    int t4 = lane & 3;

    for (int it = 0; it < 2; it++) {
        int pbase = half * 512 + it * 256 + w * 32 + (lane >> 2);
        float x0 = PX[pbase], y0 = PY[pbase], z0 = PZ[pbase];
        float x1 = PX[pbase + 8], y1 = PY[pbase + 8], z1 = PZ[pbase + 8];
        float x2 = PX[pbase + 16], y2 = PY[pbase + 16], z2 = PZ[pbase + 16];
        float x3 = PX[pbase + 24], y3 = PY[pbase + 24], z3 = PZ[pbase + 24];

        uint32_t A1h0[1][4] = {{0u, 0u, 0u, 0u}}, A1l0[1][4] = {{0u, 0u, 0u, 0u}};
        uint32_t A1h1[1][4] = {{0u, 0u, 0u, 0u}}, A1l1[1][4] = {{0u, 0u, 0u, 0u}};
        if (t4 == 0) {
            split2(x0, y0, A1h0[0][0], A1l0[0][0]);
            split2(x1, y1, A1h0[0][1], A1l0[0][1]);
            split2(x2, y2, A1h1[0][0], A1l1[0][0]);
            split2(x3, y3, A1h1[0][1], A1l1[0][1]);
        } else if (t4 == 1) {
            split2(z0, 0.f, A1h0[0][0], A1l0[0][0]);
            split2(z1, 0.f, A1h0[0][1], A1l0[0][1]);
            split2(z2, 0.f, A1h1[0][0], A1l1[0][0]);
            split2(z3, 0.f, A1h1[0][1], A1l1[0][1]);
        }

        uint32_t A2h0[4][4], A2l0[4][4], A2h1[4][4], A2l1[4][4];
        uint32_t A3h0[4][4], A3l0[4][4], A3h1[4][4], A3l1[4][4];
        uint32_t A4h0[4][4], A4l0[4][4], A4h1[4][4], A4l1[4][4];
        uint32_t A5h0[8][4], A5l0[8][4], A5h1[8][4], A5l1[8][4];

        layer_forward2<1, 8, 48>(A1h0, A1l0, A1h1, A1l1,
            sbase + O_W1H, sbase + O_W1L, sbias + 0, lane,
            A2h0, A2l0, A2h1, A2l1);
        layer_forward2<4, 8, 144>(A2h0, A2l0, A2h1, A2l1,
            sbase + O_W2H, sbase + O_W2L, sbias + 64, lane,
            A3h0, A3l0, A3h1, A3l1);
        layer_forward2<4, 8, 144>(A3h0, A3l0, A3h1, A3l1,
            sbase + O_W3H, sbase + O_W3L, sbias + 128, lane,
            A4h0, A4l0, A4h1, A4l1);
        layer_forward2<4, 16, 144>(A4h0, A4l0, A4h1, A4l1,
            sbase + O_W4H, sbase + O_W4L, sbias + 192, lane,
            A5h0, A5l0, A5h1, A5l1);
        layer_final2<8, 16, 272>(A5h0, A5l0, A5h1, A5l1,
            sbase + O_W5H, sbase + O_W5L, sbias + 320, lane, smax);
    }
    __syncthreads();
    if (tid < 128) atomicMax((int*)&g_feat[bp * 128 + tid], smax[tid]);
}

// =========================================================================
// Kernel 4: FC decoder. grid=256 (2 patches/block), 512 threads =
// (256 channels) x (2 K-halves). Halves combine through smem each layer.
// =========================================================================
__global__ void __launch_bounds__(512) dec_kernel(
    const float* __restrict__ fw0, const float* __restrict__ fb0,
    const float* __restrict__ fw1, const float* __restrict__ fb1,
    const float* __restrict__ fw2, const float* __restrict__ fb2,
    const float* __restrict__ fw3, const float* __restrict__ fb3) {
    int pbase = blockIdx.x * 2;
    int tid = threadIdx.x;
    int c = tid & 255;
    int h = tid >> 8;            // k-half
    __shared__ float sA[2][256];
    __shared__ float sB[2][256];
    __shared__ float sP[2][256];

    if (tid < 256) {
        int p = tid >> 7, cc = tid & 127;
        sA[p][cc] = g_feat[(pbase + p) * 128 + cc];
    }
    __syncthreads();

    // L1: 128 -> 256   (half K = 64)
    {
        float acc[2] = {0.f, 0.f};
        const float* W = fw0 + (h * 64) * 256 + c;
#pragma unroll 8
        for (int k = 0; k < 64; k++) {
            float wv = W[k * 256];
            acc[0] = fmaf(sA[0][h * 64 + k], wv, acc[0]);
            acc[1] = fmaf(sA[1][h * 64 + k], wv, acc[1]);
        }
        if (h == 1) { sP[0][c] = acc[0]; sP[1][c] = acc[1]; }
        __syncthreads();
        if (h == 0) {
            float bv = fb0[c];
            sB[0][c] = fmaxf(acc[0] + sP[0][c] + bv, 0.f);
            sB[1][c] = fmaxf(acc[1] + sP[1][c] + bv, 0.f);
        }
        __syncthreads();
    }
    // L2: 256 -> 256   (half K = 128)
    {
        float acc[2] = {0.f, 0.f};
        const float* W = fw1 + (h * 128) * 256 + c;
#pragma unroll 8
        for (int k = 0; k < 128; k++) {
            float wv = W[k * 256];
            acc[0] = fmaf(sB[0][h * 128 + k], wv, acc[0]);
            acc[1] = fmaf(sB[1][h * 128 + k], wv, acc[1]);
        }
        if (h == 1) { sP[0][c] = acc[0]; sP[1][c] = acc[1]; }
        __syncthreads();
        if (h == 0) {
            float bv = fb1[c];
            sA[0][c] = fmaxf(acc[0] + sP[0][c] + bv, 0.f);
            sA[1][c] = fmaxf(acc[1] + sP[1][c] + bv, 0.f);
        }
        __syncthreads();
    }
    // L3: 256 -> 256
    {
        float acc[2] = {0.f, 0.f};
        const float* W = fw2 + (h * 128) * 256 + c;
#pragma unroll 8
        for (int k = 0; k < 128; k++) {
            float wv = W[k * 256];
            acc[0] = fmaf(sA[0][h * 128 + k], wv, acc[0]);
            acc[1] = fmaf(sA[1][h * 128 + k], wv, acc[1]);
        }
        if (h == 1) { sP[0][c] = acc[0]; sP[1][c] = acc[1]; }
        __syncthreads();
        if (h == 0) {
            float bv = fb2[c];
            sB[0][c] = fmaxf(acc[0] + sP[0][c] + bv, 0.f);
            sB[1][c] = fmaxf(acc[1] + sP[1][c] + bv, 0.f);
        }
        __syncthreads();
    }
    // L4: 256 -> 24 (no relu). 96 active threads: p, o, half hh.
    {
        float acc = 0.f;
        int r = tid % 48;
        int p = tid / 48;
        int o = r % 24;
        int hh = r / 24;
        if (tid < 96) {
            const float* W = fw3 + (hh * 128) * 24 + o;
#pragma unroll 8
            for (int k = 0; k < 128; k++)
                acc = fmaf(sB[p][hh * 128 + k], W[k * 24], acc);
            if (hh == 1) sP[p][o] = acc;
        }
        __syncthreads();
        if (tid < 96 && hh == 0)
            g_gen[(pbase + p) * 24 + o] = acc + sP[p][o] + fb3[o];
    }
}

// =========================================================================
// Kernel 5: SoftProjection (proven correct)
// =========================================================================
__global__ void proj_kernel(const float* __restrict__ temperature,
                            float* __restrict__ out) {
    int bp = blockIdx.x;
    int tid = threadIdx.x;
    int m = tid >> 5;
    int lane = tid & 31;
    float t = temperature[0];
    float sigma = fmaxf(t * t, 1e-4f);

    const float* PX = &g_patch[(bp * 3 + 0) * SS];
    const float* PY = &g_patch[(bp * 3 + 1) * SS];
    const float* PZ = &g_patch[(bp * 3 + 2) * SS];

    float qx = g_gen[bp * 24 + m * 3 + 0];
    float qy = g_gen[bp * 24 + m * 3 + 1];
    float qz = g_gen[bp * 24 + m * 3 + 2];
    float q2 = qx * qx + qy * qy + qz * qz;

    float bd[7]; int bi[7];
#pragma unroll
    for (int k = 0; k < 7; k++) { bd[k] = 3.4e38f; bi[k] = 0; }

    for (int i = lane; i < SS; i += 32) {
        float px = PX[i], py = PY[i], pz = PZ[i];
        float p2 = px * px + py * py + pz * pz;
        float dot = qx * px + qy * py + qz * pz;
        float d = (q2 - 2.0f * dot) + p2;
        if (d < bd[6]) {
            bd[6] = d; bi[6] = i;
#pragma unroll
            for (int k = 6; k > 0; k--) {
                if (bd[k] < bd[k - 1]) {
                    float td = bd[k]; bd[k] = bd[k - 1]; bd[k - 1] = td;
                    int ti = bi[k]; bi[k] = bi[k - 1]; bi[k - 1] = ti;
                }
            }
        }
    }
    float selD[7]; int selI[7];
#pragma unroll
    for (int k = 0; k < 7; k++) {
        float mv = bd[0]; int ml = lane;
#pragma unroll
        for (int o = 16; o > 0; o >>= 1) {
            float ov = __shfl_xor_sync(0xffffffffu, mv, o);
            int ol = __shfl_xor_sync(0xffffffffu, ml, o);
            if (ov < mv || (ov == mv && ol < ml)) { mv = ov; ml = ol; }
        }
        selD[k] = mv;
        selI[k] = __shfl_sync(0xffffffffu, bi[0], ml);
        if (lane == ml) {
#pragma unroll
            for (int q = 0; q < 6; q++) { bd[q] = bd[q + 1]; bi[q] = bi[q + 1]; }
            bd[6] = 3.4e38f;
        }
    }
    if (lane == 0) {
        float wsum = 0.f, sx = 0.f, sy = 0.f, sz = 0.f;
#pragma unroll
        for (int k = 0; k < 7; k++) {
            float w = expf((selD[0] - selD[k]) / sigma);
            int i = selI[k];
            wsum += w;
            sx = fmaf(w, PX[i], sx);
            sy = fmaf(w, PY[i], sy);
            sz = fmaf(w, PZ[i], sz);
        }
        float inv = 1.0f / wsum;
        float nrm = g_norm[bp];
        float mex = g_mean[bp * 3 + 0], mey = g_mean[bp * 3 + 1], mez = g_mean[bp * 3 + 2];
        int o = (bp * MM + m) * 3;
        out[o + 0] = fmaf(sx * inv, nrm, mex);
        out[o + 1] = fmaf(sy * inv, nrm, mey);
        out[o + 2] = fmaf(sz * inv, nrm, mez);
    }
}

// =========================================================================
extern "C" void kernel_launch(void* const* d_in, const int* in_sizes, int n_in,
                              void* d_out, int out_size) {
    const float* xyz = (const float*)d_in[0];
    const float* mw0 = (const float*)d_in[1];  const float* mb0 = (const float*)d_in[2];
    const float* mw1 = (const float*)d_in[3];  const float* mb1 = (const float*)d_in[4];
    const float* mw2 = (const float*)d_in[5];  const float* mb2 = (const float*)d_in[6];
    const float* mw3 = (const float*)d_in[7];  const float* mb3 = (const float*)d_in[8];
    const float* mw4 = (const float*)d_in[9];  const float* mb4 = (const float*)d_in[10];
    const float* fw0 = (const float*)d_in[11]; const float* fb0 = (const float*)d_in[12];
    const float* fw1 = (const float*)d_in[13]; const float* fb1 = (const float*)d_in[14];
    const float* fw2 = (const float*)d_in[15]; const float* fb2 = (const float*)d_in[16];
    const float* fw3 = (const float*)d_in[17]; const float* fb3 = (const float*)d_in[18];
    const float* temp = (const float*)d_in[19];
    float* out = (float*)d_out;

    cudaFuncSetAttribute(mlp_mma_kernel, cudaFuncAttributeMaxDynamicSharedMemorySize,
                         DYN_TOT);

    fps_kernel<<<BB, 1024>>>(xyz);
    knn_kernel<<<NPATCH, 512>>>(xyz);
    mlp_mma_kernel<<<NPATCH * 2, 256, DYN_TOT>>>(
        mw0, mb0, mw1, mb1, mw2, mb2, mw3, mb3, mw4, mb4);
    dec_kernel<<<256, 512>>>(fw0, fb0, fw1, fb1, fw2, fb2, fw3, fb3);
    proj_kernel<<<NPATCH, 256>>>(temp, out);
}

// round 9
// speedup vs baseline: 5.0187x; 1.1702x over previous
#include <cuda_runtime.h>
#include <cuda_bf16.h>
#include <cstdint>

// ---------------- problem constants ----------------
#define BB 64
#define NN 8192
#define PP 8
#define SS 1024
#define MM 8
#define KK 7
#define NPATCH (BB*PP)   // 512

// ---------------- device scratch (no allocations allowed) ----------------
__device__ float g_seed[NPATCH * 3];
__device__ float g_patch[NPATCH * 3 * SS];      // normalized patch coords, SoA [bp][c][s]
__device__ float g_mean[NPATCH * 3];
__device__ float g_norm[NPATCH];
__device__ float g_feat[NPATCH * 128];          // maxpool accumulator (atomicMax on bits)
__device__ float g_gen[NPATCH * 24];

// smem/global weight-buffer layout (bytes)
#define O_W1H 0
#define O_W1L 3072
#define O_W2H 6144
#define O_W2L 15360
#define O_W3H 24576
#define O_W3L 33792
#define O_W4H 43008
#define O_W4L 61440
#define O_W5H 79872
#define O_W5L 114688
#define O_BIAS 149504        // 448 floats: b1@0 b2@64 b3@128 b4@192 b5@320
#define DYN_TOT 151296

__device__ __align__(16) unsigned char g_wbuf[DYN_TOT];

// =========================================================================
// helpers
// =========================================================================
__device__ __forceinline__ uint32_t smem_to_u32(const void* smem_ptr) {
    uint32_t addr;
    asm("{ .reg .u64 tmp; cvta.to.shared.u64 tmp, %1; cvt.u32.u64 %0, tmp; }"
        : "=r"(addr) : "l"(smem_ptr));
    return addr;
}

__device__ __forceinline__ void mma_bf16(float* c, const uint32_t* a, uint32_t b0, uint32_t b1) {
    asm volatile(
        "mma.sync.aligned.m16n8k16.row.col.f32.bf16.bf16.f32 "
        "{%0,%1,%2,%3}, {%4,%5,%6,%7}, {%8,%9}, {%0,%1,%2,%3};"
        : "+f"(c[0]), "+f"(c[1]), "+f"(c[2]), "+f"(c[3])
        : "r"(a[0]), "r"(a[1]), "r"(a[2]), "r"(a[3]), "r"(b0), "r"(b1));
}

__device__ __forceinline__ void ldm_x2(uint32_t& r0, uint32_t& r1, uint32_t addr) {
    asm volatile("ldmatrix.sync.aligned.m8n8.x2.shared.b16 {%0,%1}, [%2];"
                 : "=r"(r0), "=r"(r1) : "r"(addr));
}

// split (f0 -> low half, f1 -> high half) into hi/lo bf16x2 words.
// Packed cvt.rn.bf16x2 (RN, same rounding as __float2bfloat16).
__device__ __forceinline__ void split2(float f0, float f1, uint32_t& hi, uint32_t& lo) {
    uint32_t h, l;
    asm("cvt.rn.bf16x2.f32 %0, %1, %2;" : "=r"(h) : "f"(f1), "f"(f0));
    float r1 = __uint_as_float(h & 0xFFFF0000u);
    float r0 = __uint_as_float(h << 16);
    float d1 = f1 - r1;
    float d0 = f0 - r0;
    asm("cvt.rn.bf16x2.f32 %0, %1, %2;" : "=r"(l) : "f"(d1), "f"(d0));
    hi = h; lo = l;
}

// =========================================================================
// Kernel 0: pre-split weights (hi/lo bf16) into g_wbuf, laid out exactly
// like the MLP's shared memory (ldmatrix-friendly [n][k] rows w/ padding).
// =========================================================================
template<int K, int N, int STRIDE>
__device__ __forceinline__ void stage_wg(const float* __restrict__ w,
                                         char* hi, char* lo, int t, int nt) {
    for (int i = t; i < K * N; i += nt) {
        int k = i / N, n = i - k * N;
        float f = w[i];
        __nv_bfloat16 h = __float2bfloat16(f);
        __nv_bfloat16 l = __float2bfloat16(f - __bfloat162float(h));
        int off = n * STRIDE + k * 2;
        *(__nv_bfloat16*)(hi + off) = h;
        *(__nv_bfloat16*)(lo + off) = l;
    }
}

__global__ void prep_kernel(
    const float* __restrict__ mw0, const float* __restrict__ mb0,
    const float* __restrict__ mw1, const float* __restrict__ mb1,
    const float* __restrict__ mw2, const float* __restrict__ mb2,
    const float* __restrict__ mw3, const float* __restrict__ mb3,
    const float* __restrict__ mw4, const float* __restrict__ mb4) {
    int t = blockIdx.x * blockDim.x + threadIdx.x;
    int nt = gridDim.x * blockDim.x;
    char* B = (char*)g_wbuf;

    // L1: write all 16 k-rows (k>=3 are zeros) so no separate zero pass needed
    for (int i = t; i < 64 * 16; i += nt) {
        int n = i >> 4, k = i & 15;
        float f = (k < 3) ? mw0[k * 64 + n] : 0.f;
        __nv_bfloat16 h = __float2bfloat16(f);
        __nv_bfloat16 l = __float2bfloat16(f - __bfloat162float(h));
        int off = n * 48 + k * 2;
        *(__nv_bfloat16*)(B + O_W1H + off) = h;
        *(__nv_bfloat16*)(B + O_W1L + off) = l;
    }
    stage_wg<64, 64, 144>(mw1, B + O_W2H, B + O_W2L, t, nt);
    stage_wg<64, 64, 144>(mw2, B + O_W3H, B + O_W3L, t, nt);
    stage_wg<64, 128, 144>(mw3, B + O_W4H, B + O_W4L, t, nt);
    stage_wg<128, 128, 272>(mw4, B + O_W5H, B + O_W5L, t, nt);
    float* bias = (float*)(B + O_BIAS);
    for (int i = t; i < 64; i += nt) {
        bias[i] = mb0[i]; bias[64 + i] = mb1[i]; bias[128 + i] = mb2[i];
    }
    for (int i = t; i < 128; i += nt) {
        bias[192 + i] = mb3[i]; bias[320 + i] = mb4[i];
    }
}

// =========================================================================
// Kernel 1: farthest point sampling (proven correct; matches jax semantics)
// =========================================================================
__global__ void fps_kernel(const float* __restrict__ xyz) {
    int b = blockIdx.x;
    const float* X = xyz + (size_t)b * 3 * NN;
    __shared__ float s_v[32];
    __shared__ int   s_i[32];
    __shared__ float s_c[3];
    __shared__ int   s_far;
    int tid = threadIdx.x;
    int lane = tid & 31;
    int wrp = tid >> 5;

    float dist[8];
#pragma unroll
    for (int k = 0; k < 8; k++) dist[k] = 1e10f;
    int far = 0;

    for (int it = 0; it < PP; it++) {
        if (tid == 0) {
            float fx = X[far], fy = X[NN + far], fz = X[2 * NN + far];
            s_c[0] = fx; s_c[1] = fy; s_c[2] = fz;
            g_seed[(b * PP + it) * 3 + 0] = fx;
            g_seed[(b * PP + it) * 3 + 1] = fy;
            g_seed[(b * PP + it) * 3 + 2] = fz;
        }
        __syncthreads();
        float cx = s_c[0], cy = s_c[1], cz = s_c[2];
        float bv = -1.0f; int bi = 0;
#pragma unroll
        for (int k = 0; k < 8; k++) {
            int i = tid + k * 1024;
            float dx = X[i] - cx, dy = X[NN + i] - cy, dz = X[2 * NN + i] - cz;
            float d = dx * dx + dy * dy + dz * dz;
            float nd = fminf(dist[k], d);
            dist[k] = nd;
            if (nd > bv || (nd == bv && i < bi)) { bv = nd; bi = i; }
        }
#pragma unroll
        for (int o = 16; o > 0; o >>= 1) {
            float ov = __shfl_xor_sync(0xffffffffu, bv, o);
            int oi = __shfl_xor_sync(0xffffffffu, bi, o);
            if (ov > bv || (ov == bv && oi < bi)) { bv = ov; bi = oi; }
        }
        if (lane == 0) { s_v[wrp] = bv; s_i[wrp] = bi; }
        __syncthreads();
        if (wrp == 0) {
            float mv = s_v[lane]; int mi = s_i[lane];
#pragma unroll
            for (int o = 16; o > 0; o >>= 1) {
                float ov = __shfl_xor_sync(0xffffffffu, mv, o);
                int oi = __shfl_xor_sync(0xffffffffu, mi, o);
                if (ov > mv || (ov == mv && oi < mi)) { mv = ov; mi = oi; }
            }
            if (lane == 0) s_far = mi;
        }
        __syncthreads();
        far = s_far;
        __syncthreads();
    }
}

// =========================================================================
// Kernel 2: KNN radix-select + patch normalization (proven, round 7)
// =========================================================================
__global__ void __launch_bounds__(512) knn_kernel(const float* __restrict__ xyz) {
    int bp = blockIdx.x;
    int b = bp >> 3;
    const float* X = xyz + (size_t)b * 3 * NN;
    __shared__ unsigned s_key[NN];
    __shared__ int s_sel[SS];
    __shared__ int s_hist[512];        // two banks of 256
    __shared__ unsigned s_pref;
    __shared__ int s_kk;
    __shared__ int s_cnt[2];
    __shared__ float s_red[512];
    int tid = threadIdx.x;
    int lane = tid & 31;

    if (tid < 128) g_feat[bp * 128 + tid] = 0.f;

    float sx = g_seed[bp * 3 + 0], sy = g_seed[bp * 3 + 1], sz = g_seed[bp * 3 + 2];
    float s2 = sx * sx + sy * sy + sz * sz;

    for (int i = tid; i < NN; i += 512) {
        float px = X[i], py = X[NN + i], pz = X[2 * NN + i];
        float p2 = px * px + py * py + pz * pz;
        float dot = sx * px + sy * py + sz * pz;
        float d = (s2 - 2.0f * dot) + p2;
        unsigned u = __float_as_uint(d);
        u = (u & 0x80000000u) ? ~u : (u | 0x80000000u);
        s_key[i] = u;
    }
    if (tid == 0) { s_pref = 0u; s_kk = SS; }
    __syncthreads();

    unsigned prefix = 0, maskHi = 0;
    int bank = ((tid >> 5) & 1) * 256;
    for (int pass = 0; pass < 4; pass++) {
        int shift = 24 - 8 * pass;
        s_hist[tid] = 0;
        __syncthreads();
        for (int i = tid; i < NN; i += 512) {
            unsigned u = s_key[i];
            if ((u & maskHi) == prefix) atomicAdd(&s_hist[bank + ((u >> shift) & 255)], 1);
        }
        __syncthreads();
        if (tid < 32) {
            int kk = s_kk;
            unsigned pref = s_pref;
            int sv[8]; int tot = 0;
#pragma unroll
            for (int j = 0; j < 8; j++) {
                int v = s_hist[lane * 8 + j] + s_hist[256 + lane * 8 + j];
                sv[j] = v; tot += v;
            }
            int run = tot;
#pragma unroll
            for (int o = 1; o < 32; o <<= 1) {
                int v = __shfl_up_sync(0xffffffffu, run, o);
                if (lane >= o) run += v;
            }
            int excl = run - tot;
            if (kk > excl && kk <= run) {
                int cum = excl;
#pragma unroll
                for (int j = 0; j < 8; j++) {
                    if (cum + sv[j] >= kk) {
                        s_pref = pref | ((unsigned)(lane * 8 + j) << shift);
                        s_kk = kk - cum;
                        break;
                    }
                    cum += sv[j];
                }
            }
        }
        __syncthreads();
        prefix = s_pref;
        maskHi |= (0xFFu << shift);
        __syncthreads();
    }
    unsigned T = prefix;

    if (tid == 0) { s_cnt[0] = 0; s_cnt[1] = 0; }
    __syncthreads();
    for (int i = tid; i < NN; i += 512) {
        bool pred = s_key[i] < T;
        unsigned m = __ballot_sync(0xffffffffu, pred);
        int cnt = __popc(m);
        int base = 0;
        if (lane == 0 && cnt) base = atomicAdd(&s_cnt[0], cnt);
        base = __shfl_sync(0xffffffffu, base, 0);
        if (pred) s_sel[base + __popc(m & ((1u << lane) - 1u))] = i;
    }
    __syncthreads();
    int nLess = s_cnt[0];
    for (int i = tid; i < NN; i += 512) {
        bool pred = s_key[i] == T;
        unsigned m = __ballot_sync(0xffffffffu, pred);
        int cnt = __popc(m);
        int base = 0;
        if (lane == 0 && cnt) base = atomicAdd(&s_cnt[1], cnt);
        base = __shfl_sync(0xffffffffu, base, 0);
        if (pred) {
            int pos = nLess + base + __popc(m & ((1u << lane) - 1u));
            if (pos < SS) s_sel[pos] = i;
        }
    }
    __syncthreads();

    float* cxs = (float*)s_key;
    float* cys = cxs + SS;
    float* czs = cxs + 2 * SS;
    float ax = 0.f, ay = 0.f, az = 0.f;
    for (int j = tid; j < SS; j += 512) {
        int i = s_sel[j];
        float px = X[i], py = X[NN + i], pz = X[2 * NN + i];
        cxs[j] = px; cys[j] = py; czs[j] = pz;
        ax += px; ay += py; az += pz;
    }
    s_red[tid] = ax; __syncthreads();
    for (int s = 256; s > 0; s >>= 1) { if (tid < s) s_red[tid] += s_red[tid + s]; __syncthreads(); }
    float mx = s_red[0] * (1.0f / SS); __syncthreads();
    s_red[tid] = ay; __syncthreads();
    for (int s = 256; s > 0; s >>= 1) { if (tid < s) s_red[tid] += s_red[tid + s]; __syncthreads(); }
    float my = s_red[0] * (1.0f / SS); __syncthreads();
    s_red[tid] = az; __syncthreads();
    for (int s = 256; s > 0; s >>= 1) { if (tid < s) s_red[tid] += s_red[tid + s]; __syncthreads(); }
    float mz = s_red[0] * (1.0f / SS); __syncthreads();

    float mnorm = 0.f;
    for (int j = tid; j < SS; j += 512) {
        float dx = cxs[j] - mx, dy = cys[j] - my, dz = czs[j] - mz;
        float l = sqrtf(dx * dx + dy * dy + dz * dz);
        mnorm = fmaxf(mnorm, l);
    }
    s_red[tid] = mnorm; __syncthreads();
    for (int s = 256; s > 0; s >>= 1) { if (tid < s) s_red[tid] = fmaxf(s_red[tid], s_red[tid + s]); __syncthreads(); }
    float nrm = s_red[0]; __syncthreads();

    for (int j = tid; j < SS; j += 512) {
        g_patch[(bp * 3 + 0) * SS + j] = (cxs[j] - mx) / nrm;
        g_patch[(bp * 3 + 1) * SS + j] = (cys[j] - my) / nrm;
        g_patch[(bp * 3 + 2) * SS + j] = (czs[j] - mz) / nrm;
    }
    if (tid == 0) {
        g_mean[bp * 3 + 0] = mx; g_mean[bp * 3 + 1] = my; g_mean[bp * 3 + 2] = mz;
        g_norm[bp] = nrm;
    }
}

// =========================================================================
// Kernel 3: fused MLP via mma.sync bf16 split-bf16 (3-term, fp32-class).
// C = Ah*Bh + Ah*Bl + Al*Bh.  Grid = 2 blocks/patch; block = 8 warps,
// each warp 2 M-tiles (32 points)/iter, 2 iters. Weights bulk-copied
// from pre-split g_wbuf (identical layout).
// =========================================================================

// hidden layer for TWO M-tiles sharing B fragments (3-term).
template<int KC, int NT, int STRIDE>
__device__ __forceinline__ void layer_forward2(
    const uint32_t (*Ah0)[4], const uint32_t (*Al0)[4],
    const uint32_t (*Ah1)[4], const uint32_t (*Al1)[4],
    uint32_t wH, uint32_t wL, const float* __restrict__ bias, int lane,
    uint32_t (*Oh0)[4], uint32_t (*Ol0)[4],
    uint32_t (*Oh1)[4], uint32_t (*Ol1)[4]) {
    uint32_t lm = (uint32_t)(lane & 7) * STRIDE + (uint32_t)((lane >> 3) & 1) * 16;
    int t4 = lane & 3;
#pragma unroll
    for (int np = 0; np < NT / 2; np++) {
        float ccA[2][4], ccB[2][4];
#pragma unroll
        for (int sub = 0; sub < 2; sub++) {
            int nt = np * 2 + sub;
            uint32_t ro = lm + (uint32_t)nt * 8u * STRIDE;
            float c1a[4] = {0.f, 0.f, 0.f, 0.f}, c2a[4] = {0.f, 0.f, 0.f, 0.f};
            float c1b[4] = {0.f, 0.f, 0.f, 0.f}, c2b[4] = {0.f, 0.f, 0.f, 0.f};
#pragma unroll
            for (int kc = 0; kc < KC; kc++) {
                uint32_t b0, b1, l0, l1;
                ldm_x2(b0, b1, wH + ro + kc * 32);
                ldm_x2(l0, l1, wL + ro + kc * 32);
                mma_bf16(c1a, Ah0[kc], b0, b1);
                mma_bf16(c1b, Ah1[kc], b0, b1);
                mma_bf16(c2a, Ah0[kc], l0, l1);
                mma_bf16(c2b, Ah1[kc], l0, l1);
                mma_bf16(c2a, Al0[kc], b0, b1);
                mma_bf16(c2b, Al1[kc], b0, b1);
            }
            float2 bb = *reinterpret_cast<const float2*>(bias + nt * 8 + t4 * 2);
            ccA[sub][0] = fmaxf(c1a[0] + c2a[0] + bb.x, 0.f);
            ccA[sub][1] = fmaxf(c1a[1] + c2a[1] + bb.y, 0.f);
            ccA[sub][2] = fmaxf(c1a[2] + c2a[2] + bb.x, 0.f);
            ccA[sub][3] = fmaxf(c1a[3] + c2a[3] + bb.y, 0.f);
            ccB[sub][0] = fmaxf(c1b[0] + c2b[0] + bb.x, 0.f);
            ccB[sub][1] = fmaxf(c1b[1] + c2b[1] + bb.y, 0.f);
            ccB[sub][2] = fmaxf(c1b[2] + c2b[2] + bb.x, 0.f);
            ccB[sub][3] = fmaxf(c1b[3] + c2b[3] + bb.y, 0.f);
        }
        split2(ccA[0][0], ccA[0][1], Oh0[np][0], Ol0[np][0]);
        split2(ccA[0][2], ccA[0][3], Oh0[np][1], Ol0[np][1]);
        split2(ccA[1][0], ccA[1][1], Oh0[np][2], Ol0[np][2]);
        split2(ccA[1][2], ccA[1][3], Oh0[np][3], Ol0[np][3]);
        split2(ccB[0][0], ccB[0][1], Oh1[np][0], Ol1[np][0]);
        split2(ccB[0][2], ccB[0][3], Oh1[np][1], Ol1[np][1]);
        split2(ccB[1][0], ccB[1][1], Oh1[np][2], Ol1[np][2]);
        split2(ccB[1][2], ccB[1][3], Oh1[np][3], Ol1[np][3]);
    }
}

// final layer for TWO M-tiles (3-term): maxpool over 32 rows -> shared atomicMax
template<int KC, int NT, int STRIDE>
__device__ __forceinline__ void layer_final2(
    const uint32_t (*Ah0)[4], const uint32_t (*Al0)[4],
    const uint32_t (*Ah1)[4], const uint32_t (*Al1)[4],
    uint32_t wH, uint32_t wL, const float* __restrict__ bias, int lane, int* smax) {
    uint32_t lm = (uint32_t)(lane & 7) * STRIDE + (uint32_t)((lane >> 3) & 1) * 16;
    int t4 = lane & 3;
#pragma unroll
    for (int nt = 0; nt < NT; nt++) {
        uint32_t ro = lm + (uint32_t)nt * 8u * STRIDE;
        float c1a[4] = {0.f, 0.f, 0.f, 0.f}, c2a[4] = {0.f, 0.f, 0.f, 0.f};
        float c1b[4] = {0.f, 0.f, 0.f, 0.f}, c2b[4] = {0.f, 0.f, 0.f, 0.f};
#pragma unroll
        for (int kc = 0; kc < KC; kc++) {
            uint32_t b0, b1, l0, l1;
            ldm_x2(b0, b1, wH + ro + kc * 32);
            ldm_x2(l0, l1, wL + ro + kc * 32);
            mma_bf16(c1a, Ah0[kc], b0, b1);
            mma_bf16(c1b, Ah1[kc], b0, b1);
            mma_bf16(c2a, Ah0[kc], l0, l1);
            mma_bf16(c2b, Ah1[kc], l0, l1);
            mma_bf16(c2a, Al0[kc], b0, b1);
            mma_bf16(c2b, Al1[kc], b0, b1);
        }
        float2 bb = *reinterpret_cast<const float2*>(bias + nt * 8 + t4 * 2);
        float v0a = fmaxf(c1a[0] + c2a[0] + bb.x, 0.f), v2a = fmaxf(c1a[2] + c2a[2] + bb.x, 0.f);
        float v1a = fmaxf(c1a[1] + c2a[1] + bb.y, 0.f), v3a = fmaxf(c1a[3] + c2a[3] + bb.y, 0.f);
        float v0b = fmaxf(c1b[0] + c2b[0] + bb.x, 0.f), v2b = fmaxf(c1b[2] + c2b[2] + bb.x, 0.f);
        float v1b = fmaxf(c1b[1] + c2b[1] + bb.y, 0.f), v3b = fmaxf(c1b[3] + c2b[3] + bb.y, 0.f);
        float m0 = fmaxf(fmaxf(v0a, v2a), fmaxf(v0b, v2b));
        float m1 = fmaxf(fmaxf(v1a, v3a), fmaxf(v1b, v3b));
#pragma unroll
        for (int off = 4; off < 32; off <<= 1) {
            m0 = fmaxf(m0, __shfl_xor_sync(0xffffffffu, m0, off));
            m1 = fmaxf(m1, __shfl_xor_sync(0xffffffffu, m1, off));
        }
        if (lane < 4) {
            atomicMax(&smax[nt * 8 + 2 * lane], __float_as_int(m0));
            atomicMax(&smax[nt * 8 + 2 * lane + 1], __float_as_int(m1));
        }
    }
}

__global__ void __launch_bounds__(256, 1) mlp_mma_kernel() {
    extern __shared__ char sm[];
    __shared__ int smax[128];
    int bp2 = blockIdx.x;
    int bp = bp2 >> 1;
    int half = bp2 & 1;
    int tid = threadIdx.x;
    int lane = tid & 31;
    int w = tid >> 5;
    uint32_t sbase = smem_to_u32(sm);

    if (tid < 128) smax[tid] = 0;
    // bulk-copy pre-split weights + biases (laid out identically)
    {
        const uint4* src = (const uint4*)g_wbuf;
        uint4* dst = (uint4*)sm;
        for (int i = tid; i < DYN_TOT / 16; i += 256) dst[i] = src[i];
    }
    __syncthreads();

    const float* sbias = (const float*)(sm + O_BIAS);
    const float* PX = &g_patch[(bp * 3 + 0) * SS];
    const float* PY = &g_patch[(bp * 3 + 1) * SS];
    const float* PZ = &g_patch[(bp * 3 + 2) * SS];
    int t4 = lane & 3;

    for (int it = 0; it < 2; it++) {
        int pbase = half * 512 + it * 256 + w * 32 + (lane >> 2);
        float x0 = PX[pbase], y0 = PY[pbase], z0 = PZ[pbase];
        float x1 = PX[pbase + 8], y1 = PY[pbase + 8], z1 = PZ[pbase + 8];
        float x2 = PX[pbase + 16], y2 = PY[pbase + 16], z2 = PZ[pbase + 16];
        float x3 = PX[pbase + 24], y3 = PY[pbase + 24], z3 = PZ[pbase + 24];

        uint32_t A1h0[1][4] = {{0u, 0u, 0u, 0u}}, A1l0[1][4] = {{0u, 0u, 0u, 0u}};
        uint32_t A1h1[1][4] = {{0u, 0u, 0u, 0u}}, A1l1[1][4] = {{0u, 0u, 0u, 0u}};
        if (t4 == 0) {
            split2(x0, y0, A1h0[0][0], A1l0[0][0]);
            split2(x1, y1, A1h0[0][1], A1l0[0][1]);
            split2(x2, y2, A1h1[0][0], A1l1[0][0]);
            split2(x3, y3, A1h1[0][1], A1l1[0][1]);
        } else if (t4 == 1) {
            split2(z0, 0.f, A1h0[0][0], A1l0[0][0]);
            split2(z1, 0.f, A1h0[0][1], A1l0[0][1]);
            split2(z2, 0.f, A1h1[0][0], A1l1[0][0]);
            split2(z3, 0.f, A1h1[0][1], A1l1[0][1]);
        }

        uint32_t A2h0[4][4], A2l0[4][4], A2h1[4][4], A2l1[4][4];
        uint32_t A3h0[4][4], A3l0[4][4], A3h1[4][4], A3l1[4][4];
        uint32_t A4h0[4][4], A4l0[4][4], A4h1[4][4], A4l1[4][4];
        uint32_t A5h0[8][4], A5l0[8][4], A5h1[8][4], A5l1[8][4];

        layer_forward2<1, 8, 48>(A1h0, A1l0, A1h1, A1l1,
            sbase + O_W1H, sbase + O_W1L, sbias + 0, lane,
            A2h0, A2l0, A2h1, A2l1);
        layer_forward2<4, 8, 144>(A2h0, A2l0, A2h1, A2l1,
            sbase + O_W2H, sbase + O_W2L, sbias + 64, lane,
            A3h0, A3l0, A3h1, A3l1);
        layer_forward2<4, 8, 144>(A3h0, A3l0, A3h1, A3l1,
            sbase + O_W3H, sbase + O_W3L, sbias + 128, lane,
            A4h0, A4l0, A4h1, A4l1);
        layer_forward2<4, 16, 144>(A4h0, A4l0, A4h1, A4l1,
            sbase + O_W4H, sbase + O_W4L, sbias + 192, lane,
            A5h0, A5l0, A5h1, A5l1);
        layer_final2<8, 16, 272>(A5h0, A5l0, A5h1, A5l1,
            sbase + O_W5H, sbase + O_W5L, sbias + 320, lane, smax);
    }
    __syncthreads();
    if (tid < 128) atomicMax((int*)&g_feat[bp * 128 + tid], smax[tid]);
}

// =========================================================================
// Kernel 4: FC decoder (proven, round 7). grid=256, 2 patches/block.
// =========================================================================
__global__ void __launch_bounds__(512) dec_kernel(
    const float* __restrict__ fw0, const float* __restrict__ fb0,
    const float* __restrict__ fw1, const float* __restrict__ fb1,
    const float* __restrict__ fw2, const float* __restrict__ fb2,
    const float* __restrict__ fw3, const float* __restrict__ fb3) {
    int pbase = blockIdx.x * 2;
    int tid = threadIdx.x;
    int c = tid & 255;
    int h = tid >> 8;            // k-half
    __shared__ float sA[2][256];
    __shared__ float sB[2][256];
    __shared__ float sP[2][256];

    if (tid < 256) {
        int p = tid >> 7, cc = tid & 127;
        sA[p][cc] = g_feat[(pbase + p) * 128 + cc];
    }
    __syncthreads();

    {
        float acc[2] = {0.f, 0.f};
        const float* W = fw0 + (h * 64) * 256 + c;
#pragma unroll 8
        for (int k = 0; k < 64; k++) {
            float wv = W[k * 256];
            acc[0] = fmaf(sA[0][h * 64 + k], wv, acc[0]);
            acc[1] = fmaf(sA[1][h * 64 + k], wv, acc[1]);
        }
        if (h == 1) { sP[0][c] = acc[0]; sP[1][c] = acc[1]; }
        __syncthreads();
        if (h == 0) {
            float bv = fb0[c];
            sB[0][c] = fmaxf(acc[0] + sP[0][c] + bv, 0.f);
            sB[1][c] = fmaxf(acc[1] + sP[1][c] + bv, 0.f);
        }
        __syncthreads();
    }
    {
        float acc[2] = {0.f, 0.f};
        const float* W = fw1 + (h * 128) * 256 + c;
#pragma unroll 8
        for (int k = 0; k < 128; k++) {
            float wv = W[k * 256];
            acc[0] = fmaf(sB[0][h * 128 + k], wv, acc[0]);
            acc[1] = fmaf(sB[1][h * 128 + k], wv, acc[1]);
        }
        if (h == 1) { sP[0][c] = acc[0]; sP[1][c] = acc[1]; }
        __syncthreads();
        if (h == 0) {
            float bv = fb1[c];
            sA[0][c] = fmaxf(acc[0] + sP[0][c] + bv, 0.f);
            sA[1][c] = fmaxf(acc[1] + sP[1][c] + bv, 0.f);
        }
        __syncthreads();
    }
    {
        float acc[2] = {0.f, 0.f};
        const float* W = fw2 + (h * 128) * 256 + c;
#pragma unroll 8
        for (int k = 0; k < 128; k++) {
            float wv = W[k * 256];
            acc[0] = fmaf(sA[0][h * 128 + k], wv, acc[0]);
            acc[1] = fmaf(sA[1][h * 128 + k], wv, acc[1]);
        }
        if (h == 1) { sP[0][c] = acc[0]; sP[1][c] = acc[1]; }
        __syncthreads();
        if (h == 0) {
            float bv = fb2[c];
            sB[0][c] = fmaxf(acc[0] + sP[0][c] + bv, 0.f);
            sB[1][c] = fmaxf(acc[1] + sP[1][c] + bv, 0.f);
        }
        __syncthreads();
    }
    {
        float acc = 0.f;
        int r = tid % 48;
        int p = tid / 48;
        int o = r % 24;
        int hh = r / 24;
        if (tid < 96) {
            const float* W = fw3 + (hh * 128) * 24 + o;
#pragma unroll 8
            for (int k = 0; k < 128; k++)
                acc = fmaf(sB[p][hh * 128 + k], W[k * 24], acc);
            if (hh == 1) sP[p][o] = acc;
        }
        __syncthreads();
        if (tid < 96 && hh == 0)
            g_gen[(pbase + p) * 24 + o] = acc + sP[p][o] + fb3[o];
    }
}

// =========================================================================
// Kernel 5: SoftProjection (proven correct)
// =========================================================================
__global__ void proj_kernel(const float* __restrict__ temperature,
                            float* __restrict__ out) {
    int bp = blockIdx.x;
    int tid = threadIdx.x;
    int m = tid >> 5;
    int lane = tid & 31;
    float t = temperature[0];
    float sigma = fmaxf(t * t, 1e-4f);

    const float* PX = &g_patch[(bp * 3 + 0) * SS];
    const float* PY = &g_patch[(bp * 3 + 1) * SS];
    const float* PZ = &g_patch[(bp * 3 + 2) * SS];

    float qx = g_gen[bp * 24 + m * 3 + 0];
    float qy = g_gen[bp * 24 + m * 3 + 1];
    float qz = g_gen[bp * 24 + m * 3 + 2];
    float q2 = qx * qx + qy * qy + qz * qz;

    float bd[7]; int bi[7];
#pragma unroll
    for (int k = 0; k < 7; k++) { bd[k] = 3.4e38f; bi[k] = 0; }

    for (int i = lane; i < SS; i += 32) {
        float px = PX[i], py = PY[i], pz = PZ[i];
        float p2 = px * px + py * py + pz * pz;
        float dot = qx * px + qy * py + qz * pz;
        float d = (q2 - 2.0f * dot) + p2;
        if (d < bd[6]) {
            bd[6] = d; bi[6] = i;
#pragma unroll
            for (int k = 6; k > 0; k--) {
                if (bd[k] < bd[k - 1]) {
                    float td = bd[k]; bd[k] = bd[k - 1]; bd[k - 1] = td;
                    int ti = bi[k]; bi[k] = bi[k - 1]; bi[k - 1] = ti;
                }
            }
        }
    }
    float selD[7]; int selI[7];
#pragma unroll
    for (int k = 0; k < 7; k++) {
        float mv = bd[0]; int ml = lane;
#pragma unroll
        for (int o = 16; o > 0; o >>= 1) {
            float ov = __shfl_xor_sync(0xffffffffu, mv, o);
            int ol = __shfl_xor_sync(0xffffffffu, ml, o);
            if (ov < mv || (ov == mv && ol < ml)) { mv = ov; ml = ol; }
        }
        selD[k] = mv;
        selI[k] = __shfl_sync(0xffffffffu, bi[0], ml);
        if (lane == ml) {
#pragma unroll
            for (int q = 0; q < 6; q++) { bd[q] = bd[q + 1]; bi[q] = bi[q + 1]; }
            bd[6] = 3.4e38f;
        }
    }
    if (lane == 0) {
        float wsum = 0.f, sx = 0.f, sy = 0.f, sz = 0.f;
#pragma unroll
        for (int k = 0; k < 7; k++) {
            float w = expf((selD[0] - selD[k]) / sigma);
            int i = selI[k];
            wsum += w;
            sx = fmaf(w, PX[i], sx);
            sy = fmaf(w, PY[i], sy);
            sz = fmaf(w, PZ[i], sz);
        }
        float inv = 1.0f / wsum;
        float nrm = g_norm[bp];
        float mex = g_mean[bp * 3 + 0], mey = g_mean[bp * 3 + 1], mez = g_mean[bp * 3 + 2];
        int o = (bp * MM + m) * 3;
        out[o + 0] = fmaf(sx * inv, nrm, mex);
        out[o + 1] = fmaf(sy * inv, nrm, mey);
        out[o + 2] = fmaf(sz * inv, nrm, mez);
    }
}

// =========================================================================
extern "C" void kernel_launch(void* const* d_in, const int* in_sizes, int n_in,
                              void* d_out, int out_size) {
    const float* xyz = (const float*)d_in[0];
    const float* mw0 = (const float*)d_in[1];  const float* mb0 = (const float*)d_in[2];
    const float* mw1 = (const float*)d_in[3];  const float* mb1 = (const float*)d_in[4];
    const float* mw2 = (const float*)d_in[5];  const float* mb2 = (const float*)d_in[6];
    const float* mw3 = (const float*)d_in[7];  const float* mb3 = (const float*)d_in[8];
    const float* mw4 = (const float*)d_in[9];  const float* mb4 = (const float*)d_in[10];
    const float* fw0 = (const float*)d_in[11]; const float* fb0 = (const float*)d_in[12];
    const float* fw1 = (const float*)d_in[13]; const float* fb1 = (const float*)d_in[14];
    const float* fw2 = (const float*)d_in[15]; const float* fb2 = (const float*)d_in[16];
    const float* fw3 = (const float*)d_in[17]; const float* fb3 = (const float*)d_in[18];
    const float* temp = (const float*)d_in[19];
    float* out = (float*)d_out;

    cudaFuncSetAttribute(mlp_mma_kernel, cudaFuncAttributeMaxDynamicSharedMemorySize,
                         DYN_TOT);

    prep_kernel<<<48, 256>>>(mw0, mb0, mw1, mb1, mw2, mb2, mw3, mb3, mw4, mb4);
    fps_kernel<<<BB, 1024>>>(xyz);
    knn_kernel<<<NPATCH, 512>>>(xyz);
    mlp_mma_kernel<<<NPATCH * 2, 256, DYN_TOT>>>();
    dec_kernel<<<256, 512>>>(fw0, fb0, fw1, fb1, fw2, fb2, fw3, fb3);
    proj_kernel<<<NPATCH, 256>>>(temp, out);
}